// round 1
// baseline (speedup 1.0000x reference)
#include <cuda_runtime.h>
#include <math.h>

#define MTOT 4096
#define HDIM 1024
#define NHEAD 16
#define HD 64
#define SEQ 2048
#define BATCH 2

#define BM 128
#define BN 64
#define BK 16

// Scratch: Q, K, V, AO (4 x 4096*1024 floats) + LOW0/LOW1 (2 x 4096*64)
__device__ float g_scratch[4u*4194304u + 2u*262144u];

// ---------------------------------------------------------------------------
// Generic SGEMM: C[M,N] = A[M,K] @ B[K,N] with fused epilogue.
// mode 0: C = acc + bias[n]
// mode 2: C = acc
// mode 1: C += sigmoid(*coupling) * sin(freq*acc) * acc * inv   (torsion)
// Requires: M%BM==0, N%BN==0, K%BK==0 (true for all shapes here).
// ---------------------------------------------------------------------------
__global__ __launch_bounds__(256) void gemm_kernel(
    const float* __restrict__ A, const float* __restrict__ B,
    const float* __restrict__ bias, const float* __restrict__ coupling,
    float* __restrict__ C, int M, int N, int K,
    int mode, float freq, float inv)
{
    __shared__ float As[BK][BM + 4];
    __shared__ float Bs[BK][BN];

    int tid = threadIdx.x;
    int ty = tid >> 4, tx = tid & 15;
    int bm = blockIdx.y * BM, bn = blockIdx.x * BN;

    float acc[8][4];
#pragma unroll
    for (int i = 0; i < 8; i++)
#pragma unroll
        for (int j = 0; j < 4; j++) acc[i][j] = 0.f;

    for (int k0 = 0; k0 < K; k0 += BK) {
        // A tile: 128x16, two float4 per thread, stored transposed
#pragma unroll
        for (int i = 0; i < 2; i++) {
            int idx = tid + i * 256;
            int row = idx >> 2, kq = (idx & 3) << 2;
            const float4 a = *(const float4*)(A + (size_t)(bm + row) * K + k0 + kq);
            As[kq + 0][row] = a.x; As[kq + 1][row] = a.y;
            As[kq + 2][row] = a.z; As[kq + 3][row] = a.w;
        }
        // B tile: 16x64, one float4 per thread
        {
            int kr = tid >> 4, nq = (tid & 15) << 2;
            *(float4*)&Bs[kr][nq] = *(const float4*)(B + (size_t)(k0 + kr) * N + bn + nq);
        }
        __syncthreads();

#pragma unroll
        for (int kk = 0; kk < BK; kk++) {
            float a[8], b[4];
#pragma unroll
            for (int i = 0; i < 8; i++) a[i] = As[kk][ty * 8 + i];
#pragma unroll
            for (int j = 0; j < 4; j++) b[j] = Bs[kk][tx * 4 + j];
#pragma unroll
            for (int i = 0; i < 8; i++)
#pragma unroll
                for (int j = 0; j < 4; j++) acc[i][j] += a[i] * b[j];
        }
        __syncthreads();
    }

    float sig = 0.f;
    if (mode == 1) {
        float c = *coupling;
        sig = 1.f / (1.f + __expf(-c));
    }

#pragma unroll
    for (int i = 0; i < 8; i++) {
        int r = bm + ty * 8 + i;
#pragma unroll
        for (int j = 0; j < 4; j++) {
            int cc = bn + tx * 4 + j;
            size_t off = (size_t)r * N + cc;
            float v = acc[i][j];
            if (mode == 0)      C[off] = v + bias[cc];
            else if (mode == 2) C[off] = v;
            else                C[off] += sig * sinf(freq * v) * v * inv;
        }
    }
}

// ---------------------------------------------------------------------------
// Flash attention, fp32. One block = 64 queries of one (batch, head).
// Non-causal, S=2048, HD=64, scale=1/8 baked into Q at load.
// ---------------------------------------------------------------------------
__global__ __launch_bounds__(256) void flash_kernel(
    const float* __restrict__ Q, const float* __restrict__ K,
    const float* __restrict__ V, float* __restrict__ O)
{
    extern __shared__ float sm[];
    float* Qs = sm;                 // 64 x 65
    float* Ks = sm + 64 * 65;
    float* Vs = sm + 2 * 64 * 65;
    float* Ps = sm + 3 * 64 * 65;

    int tid = threadIdx.x;
    int ty = tid >> 4, tx = tid & 15;
    int q0 = blockIdx.x * 64;
    int h  = blockIdx.y;
    int b  = blockIdx.z;
    size_t base = ((size_t)b * SEQ) * HDIM + (size_t)h * HD;

    // load Q tile (pre-scaled)
#pragma unroll
    for (int qq = 0; qq < 4; qq++) {
        int lin = tid + qq * 256;
        int r = lin >> 4, d4 = (lin & 15) << 2;
        float4 v = *(const float4*)(Q + base + (size_t)(q0 + r) * HDIM + d4);
        Qs[r * 65 + d4 + 0] = v.x * 0.125f;
        Qs[r * 65 + d4 + 1] = v.y * 0.125f;
        Qs[r * 65 + d4 + 2] = v.z * 0.125f;
        Qs[r * 65 + d4 + 3] = v.w * 0.125f;
    }

    float m[4], l[4], o[4][4];
#pragma unroll
    for (int i = 0; i < 4; i++) {
        m[i] = -1e30f; l[i] = 0.f;
#pragma unroll
        for (int j = 0; j < 4; j++) o[i][j] = 0.f;
    }

    for (int kt = 0; kt < SEQ; kt += 64) {
        __syncthreads();   // prior PV reads done; Qs visible on first iter
        // load K, V tiles
#pragma unroll
        for (int qq = 0; qq < 4; qq++) {
            int lin = tid + qq * 256;
            int r = lin >> 4, d4 = (lin & 15) << 2;
            size_t go = base + (size_t)(kt + r) * HDIM + d4;
            float4 kv = *(const float4*)(K + go);
            Ks[r * 65 + d4 + 0] = kv.x; Ks[r * 65 + d4 + 1] = kv.y;
            Ks[r * 65 + d4 + 2] = kv.z; Ks[r * 65 + d4 + 3] = kv.w;
            float4 vv = *(const float4*)(V + go);
            Vs[r * 65 + d4 + 0] = vv.x; Vs[r * 65 + d4 + 1] = vv.y;
            Vs[r * 65 + d4 + 2] = vv.z; Vs[r * 65 + d4 + 3] = vv.w;
        }
        __syncthreads();

        // S = Q K^T  (4x4 micro-tile per thread)
        float s[4][4];
#pragma unroll
        for (int i = 0; i < 4; i++)
#pragma unroll
            for (int j = 0; j < 4; j++) s[i][j] = 0.f;
        for (int d = 0; d < 64; d++) {
            float a[4], bb[4];
#pragma unroll
            for (int i = 0; i < 4; i++) a[i] = Qs[(ty * 4 + i) * 65 + d];
#pragma unroll
            for (int j = 0; j < 4; j++) bb[j] = Ks[(tx * 4 + j) * 65 + d];
#pragma unroll
            for (int i = 0; i < 4; i++)
#pragma unroll
                for (int j = 0; j < 4; j++) s[i][j] += a[i] * bb[j];
        }

        // online softmax (rows shared by the 16 threads of a ty-group)
#pragma unroll
        for (int i = 0; i < 4; i++) {
            float mx = fmaxf(fmaxf(s[i][0], s[i][1]), fmaxf(s[i][2], s[i][3]));
#pragma unroll
            for (int off = 1; off < 16; off <<= 1)
                mx = fmaxf(mx, __shfl_xor_sync(0xffffffffu, mx, off));
            float mn = fmaxf(m[i], mx);
            float cf = __expf(m[i] - mn);
            m[i] = mn;
            float ls = 0.f;
#pragma unroll
            for (int j = 0; j < 4; j++) {
                float p = __expf(s[i][j] - mn);
                Ps[(ty * 4 + i) * 65 + tx * 4 + j] = p;
                ls += p;
            }
#pragma unroll
            for (int off = 1; off < 16; off <<= 1)
                ls += __shfl_xor_sync(0xffffffffu, ls, off);
            l[i] = l[i] * cf + ls;
#pragma unroll
            for (int j = 0; j < 4; j++) o[i][j] *= cf;
        }
        __syncthreads();

        // O += P V
        for (int kk = 0; kk < 64; kk++) {
            float p[4], vv[4];
#pragma unroll
            for (int i = 0; i < 4; i++) p[i] = Ps[(ty * 4 + i) * 65 + kk];
#pragma unroll
            for (int j = 0; j < 4; j++) vv[j] = Vs[kk * 65 + tx * 4 + j];
#pragma unroll
            for (int i = 0; i < 4; i++)
#pragma unroll
                for (int j = 0; j < 4; j++) o[i][j] += p[i] * vv[j];
        }
    }

#pragma unroll
    for (int i = 0; i < 4; i++) {
        float li = 1.f / l[i];
        int r = q0 + ty * 4 + i;
#pragma unroll
        for (int j = 0; j < 4; j++)
            O[base + (size_t)r * HDIM + tx * 4 + j] = o[i][j] * li;
    }
}

// ---------------------------------------------------------------------------
extern "C" void kernel_launch(void* const* d_in, const int* in_sizes, int n_in,
                              void* d_out, int out_size)
{
    const float* X   = (const float*)d_in[0];
    const float* Wq  = (const float*)d_in[1];
    const float* bq  = (const float*)d_in[2];
    const float* Wk  = (const float*)d_in[3];
    const float* bk  = (const float*)d_in[4];
    const float* Wv  = (const float*)d_in[5];
    const float* bv  = (const float*)d_in[6];
    const float* Wo  = (const float*)d_in[7];
    const float* bo  = (const float*)d_in[8];
    const float* qta = (const float*)d_in[9];
    const float* qtb = (const float*)d_in[10];
    const float* kta = (const float*)d_in[11];
    const float* ktb = (const float*)d_in[12];
    const float* cpl = (const float*)d_in[13];

    float* scratch = nullptr;
    cudaGetSymbolAddress((void**)&scratch, g_scratch);
    float* Qb = scratch;
    float* Kb = scratch + 1 * 4194304;
    float* Vb = scratch + 2 * 4194304;
    float* AO = scratch + 3 * 4194304;
    float* L0 = scratch + 4 * 4194304;
    float* L1 = L0 + 262144;

    dim3 gBig(HDIM / BN, MTOT / BM);  // (16, 32)
    dim3 gLow(64 / BN,   MTOT / BM);  // (1, 32)
    const float PI2 = 6.28318530717958647692f;

    // QKV projections
    gemm_kernel<<<gBig, 256>>>(X, Wq, bq, nullptr, Qb, MTOT, HDIM, HDIM, 0, 0.f, 0.f);
    gemm_kernel<<<gBig, 256>>>(X, Wk, bk, nullptr, Kb, MTOT, HDIM, HDIM, 0, 0.f, 0.f);
    gemm_kernel<<<gBig, 256>>>(X, Wv, bv, nullptr, Vb, MTOT, HDIM, HDIM, 0, 0.f, 0.f);

    // Torsion on Q: both low-rank projections from ORIGINAL Q first,
    // then two in-place update GEMMs.
    gemm_kernel<<<gLow, 256>>>(Qb, qta,             nullptr, nullptr, L0, MTOT, 64, HDIM, 2, 0.f, 0.f);
    gemm_kernel<<<gLow, 256>>>(Qb, qta + 1024 * 64, nullptr, nullptr, L1, MTOT, 64, HDIM, 2, 0.f, 0.f);
    gemm_kernel<<<gBig, 256>>>(L0, qtb,             nullptr, cpl, Qb, MTOT, HDIM, 64, 1, PI2,       1.0f);
    gemm_kernel<<<gBig, 256>>>(L1, qtb + 64 * 1024, nullptr, cpl, Qb, MTOT, HDIM, 64, 1, 2.f * PI2, 0.5f);

    // Torsion on K
    gemm_kernel<<<gLow, 256>>>(Kb, kta,             nullptr, nullptr, L0, MTOT, 64, HDIM, 2, 0.f, 0.f);
    gemm_kernel<<<gLow, 256>>>(Kb, kta + 1024 * 64, nullptr, nullptr, L1, MTOT, 64, HDIM, 2, 0.f, 0.f);
    gemm_kernel<<<gBig, 256>>>(L0, ktb,             nullptr, cpl, Kb, MTOT, HDIM, 64, 1, PI2,       1.0f);
    gemm_kernel<<<gBig, 256>>>(L1, ktb + 64 * 1024, nullptr, cpl, Kb, MTOT, HDIM, 64, 1, 2.f * PI2, 0.5f);

    // Attention
    int smem = 4 * 64 * 65 * (int)sizeof(float);  // 66560 B
    cudaFuncSetAttribute(flash_kernel, cudaFuncAttributeMaxDynamicSharedMemorySize, smem);
    dim3 gAtt(SEQ / 64, NHEAD, BATCH);
    flash_kernel<<<gAtt, 256, smem>>>(Qb, Kb, Vb, AO);

    // Output projection -> d_out
    gemm_kernel<<<gBig, 256>>>(AO, Wo, bo, nullptr, (float*)d_out, MTOT, HDIM, HDIM, 0, 0.f, 0.f);
}

// round 5
// speedup vs baseline: 1.3801x; 1.3801x over previous
#include <cuda_runtime.h>
#include <cuda_bf16.h>
#include <math.h>
#include <stdint.h>

#define MTOT 4096
#define HDIM 1024
#define NHEAD 16
#define HD 64
#define SEQ 2048
#define BATCH 2

// Scratch: Q, K, V, AO (4 x 4096*1024 floats) + LOW0/LOW1 (2 x 4096*64)
__device__ float g_scratch[4u*4194304u + 2u*262144u];

__device__ __forceinline__ uint32_t smem_u32(const void* p) {
    uint32_t a;
    asm("{ .reg .u64 t; cvta.to.shared.u64 t, %1; cvt.u32.u64 %0, t; }"
        : "=r"(a) : "l"(p));
    return a;
}

__device__ __forceinline__ void ldsm4(uint32_t* r, uint32_t addr) {
    asm volatile("ldmatrix.sync.aligned.m8n8.x4.shared.b16 {%0,%1,%2,%3}, [%4];"
                 : "=r"(r[0]), "=r"(r[1]), "=r"(r[2]), "=r"(r[3]) : "r"(addr));
}

__device__ __forceinline__ void mma16816(float* c, const uint32_t* a, const uint32_t* b) {
    asm volatile(
        "mma.sync.aligned.m16n8k16.row.col.f32.bf16.bf16.f32 "
        "{%0,%1,%2,%3}, {%4,%5,%6,%7}, {%8,%9}, {%0,%1,%2,%3};"
        : "+f"(c[0]), "+f"(c[1]), "+f"(c[2]), "+f"(c[3])
        : "r"(a[0]), "r"(a[1]), "r"(a[2]), "r"(a[3]), "r"(b[0]), "r"(b[1]));
}

__device__ __forceinline__ void cvt2(float a, float b, uint32_t* hi, uint32_t* lo) {
    __nv_bfloat162 h = __floats2bfloat162_rn(a, b);
    float2 hf = __bfloat1622float2(h);
    __nv_bfloat162 l = __floats2bfloat162_rn(a - hf.x, b - hf.y);
    *hi = *(uint32_t*)&h;
    *lo = *(uint32_t*)&l;
}

// ===========================================================================
// Split-bf16 tensor-core GEMM via mma.sync:
//   C[4096, N] = A[4096, K] @ B[K, N], fused epilogue.
// Block tile 128x64, BK=32, 8 warps (warp tile 32x32), double-buffered smem.
// Accuracy: x = hi + lo (bf16 each); D += Ah*Bh + Ah*Bl + Al*Bh.
// mode 0: C = D + bias[n]    mode 2: C = D
// mode 1: C += sigmoid(*coupling) * sin(freq*D) * D * inv
// ===========================================================================
#define LDT 40                     // bf16 elems per smem row (32 data + 8 pad)
#define ST_AH 0                    // elem offsets within a stage
#define ST_AL 5120                 // 128*40
#define ST_BH 10240
#define ST_BL 12800                // + 64*40
#define ST_ELEMS 15360             // stage elems (30720 B)

__global__ __launch_bounds__(256) void gemm_tc(
    const float* __restrict__ A, const float* __restrict__ B,
    const float* __restrict__ bias, const float* __restrict__ coupling,
    float* __restrict__ C, int K, int N, int mode, float freq, float inv)
{
    extern __shared__ __align__(16) char smraw[];
    __nv_bfloat16* sm = (__nv_bfloat16*)smraw;
    uint32_t smb = smem_u32(smraw);

    int tid = threadIdx.x, wid = tid >> 5, lane = tid & 31;
    int bm = blockIdx.y * 128, bn = blockIdx.x * 64;
    int wm = (wid & 3) * 32, wn = (wid >> 2) * 32;

    float acc[2][4][4];
#pragma unroll
    for (int i = 0; i < 2; i++)
#pragma unroll
        for (int j = 0; j < 4; j++)
#pragma unroll
            for (int e = 0; e < 4; e++) acc[i][j][e] = 0.f;

    // per-thread global-load mapping
    int ar = tid >> 1, ac0 = (tid & 1) * 16;       // A: row, 16 cols
    int bnn = tid >> 2, bk0 = (tid & 3) * 8;       // B: n col, 8 k rows

    float Areg[16], Breg[8];
    int nchunks = K >> 5;

    // ---- load chunk 0
    {
        const float* Ap = A + (size_t)(bm + ar) * K + ac0;
#pragma unroll
        for (int g = 0; g < 4; g++) *(float4*)(Areg + g * 4) = *(const float4*)(Ap + g * 4);
        const float* Bp = B + (size_t)bk0 * N + bn + bnn;
#pragma unroll
        for (int e = 0; e < 8; e++) Breg[e] = Bp[(size_t)e * N];
    }

    for (int c = 0; c < nchunks; c++) {
        int s = c & 1;
        __nv_bfloat16* st = sm + s * ST_ELEMS;

        // ---- convert + store current chunk's regs into stage s
        {
            uint4 hi, lo;
            cvt2(Areg[0], Areg[1], &hi.x, &lo.x);
            cvt2(Areg[2], Areg[3], &hi.y, &lo.y);
            cvt2(Areg[4], Areg[5], &hi.z, &lo.z);
            cvt2(Areg[6], Areg[7], &hi.w, &lo.w);
            *(uint4*)(st + ST_AH + ar * LDT + ac0) = hi;
            *(uint4*)(st + ST_AL + ar * LDT + ac0) = lo;
            cvt2(Areg[8],  Areg[9],  &hi.x, &lo.x);
            cvt2(Areg[10], Areg[11], &hi.y, &lo.y);
            cvt2(Areg[12], Areg[13], &hi.z, &lo.z);
            cvt2(Areg[14], Areg[15], &hi.w, &lo.w);
            *(uint4*)(st + ST_AH + ar * LDT + ac0 + 8) = hi;
            *(uint4*)(st + ST_AL + ar * LDT + ac0 + 8) = lo;

            cvt2(Breg[0], Breg[1], &hi.x, &lo.x);
            cvt2(Breg[2], Breg[3], &hi.y, &lo.y);
            cvt2(Breg[4], Breg[5], &hi.z, &lo.z);
            cvt2(Breg[6], Breg[7], &hi.w, &lo.w);
            *(uint4*)(st + ST_BH + bnn * LDT + bk0) = hi;
            *(uint4*)(st + ST_BL + bnn * LDT + bk0) = lo;
        }
        __syncthreads();

        // ---- prefetch next chunk into regs (LDG latency hides under MMA)
        if (c + 1 < nchunks) {
            const float* Ap = A + (size_t)(bm + ar) * K + (c + 1) * 32 + ac0;
#pragma unroll
            for (int g = 0; g < 4; g++) *(float4*)(Areg + g * 4) = *(const float4*)(Ap + g * 4);
            const float* Bp = B + (size_t)((c + 1) * 32 + bk0) * N + bn + bnn;
#pragma unroll
            for (int e = 0; e < 8; e++) Breg[e] = Bp[(size_t)e * N];
        }

        // ---- MMA on stage s
        uint32_t stA = smb + (uint32_t)(s * ST_ELEMS) * 2;
        uint32_t stAl = stA + ST_AL * 2;
        uint32_t stBh = stA + ST_BH * 2;
        uint32_t stBl = stA + ST_BL * 2;

#pragma unroll
        for (int kk = 0; kk < 32; kk += 16) {
            uint32_t ah[2][4], al[2][4], bh[4][2], bl[4][2];
#pragma unroll
            for (int i = 0; i < 2; i++) {
                uint32_t roff = (uint32_t)((wm + i * 16 + (lane & 15)) * LDT
                                           + kk + ((lane >> 4) << 3)) * 2;
                ldsm4(ah[i], stA + roff);
                ldsm4(al[i], stAl + roff);
            }
#pragma unroll
            for (int p = 0; p < 2; p++) {
                uint32_t noff = (uint32_t)((wn + p * 16 + (lane & 7) + ((lane >> 4) << 3)) * LDT
                                           + kk + (((lane >> 3) & 1) << 3)) * 2;
                uint32_t r[4];
                ldsm4(r, stBh + noff);
                bh[p * 2][0] = r[0]; bh[p * 2][1] = r[1];
                bh[p * 2 + 1][0] = r[2]; bh[p * 2 + 1][1] = r[3];
                ldsm4(r, stBl + noff);
                bl[p * 2][0] = r[0]; bl[p * 2][1] = r[1];
                bl[p * 2 + 1][0] = r[2]; bl[p * 2 + 1][1] = r[3];
            }
#pragma unroll
            for (int i = 0; i < 2; i++)
#pragma unroll
                for (int j = 0; j < 4; j++) {
                    mma16816(acc[i][j], ah[i], bh[j]);
                    mma16816(acc[i][j], ah[i], bl[j]);
                    mma16816(acc[i][j], al[i], bh[j]);
                }
        }
        __syncthreads();
    }

    // ---- epilogue straight from register fragments
    int g = lane >> 2, q = lane & 3;
    float sg = 0.f;
    if (mode == 1) sg = 1.f / (1.f + __expf(-(*coupling)));

#pragma unroll
    for (int i = 0; i < 2; i++) {
#pragma unroll
        for (int j = 0; j < 4; j++) {
            int row = bm + wm + i * 16 + g;
            int col = bn + wn + j * 8 + q * 2;
#pragma unroll
            for (int h = 0; h < 2; h++) {          // h=0: row, h=1: row+8
                float* Cp = C + (size_t)(row + h * 8) * N + col;
                float d0 = acc[i][j][h * 2 + 0];
                float d1 = acc[i][j][h * 2 + 1];
                if (mode == 0) {
                    float2 o = { d0 + bias[col], d1 + bias[col + 1] };
                    *(float2*)Cp = o;
                } else if (mode == 2) {
                    float2 o = { d0, d1 };
                    *(float2*)Cp = o;
                } else {
                    float2 cv = *(float2*)Cp;
                    cv.x += sg * sinf(freq * d0) * d0 * inv;
                    cv.y += sg * sinf(freq * d1) * d1 * inv;
                    *(float2*)Cp = cv;
                }
            }
        }
    }
}

// ===========================================================================
// Flash attention, fp32 (unchanged from R1 — proven). One block = 64 queries.
// ===========================================================================
__global__ __launch_bounds__(256) void flash_kernel(
    const float* __restrict__ Q, const float* __restrict__ K,
    const float* __restrict__ V, float* __restrict__ O)
{
    extern __shared__ float smf[];
    float* Qs = smf;
    float* Ks = smf + 64 * 65;
    float* Vs = smf + 2 * 64 * 65;
    float* Ps = smf + 3 * 64 * 65;

    int tid = threadIdx.x;
    int ty = tid >> 4, tx = tid & 15;
    int q0 = blockIdx.x * 64;
    int h  = blockIdx.y;
    int b  = blockIdx.z;
    size_t base = ((size_t)b * SEQ) * HDIM + (size_t)h * HD;

#pragma unroll
    for (int qq = 0; qq < 4; qq++) {
        int lin = tid + qq * 256;
        int r = lin >> 4, d4 = (lin & 15) << 2;
        float4 v = *(const float4*)(Q + base + (size_t)(q0 + r) * HDIM + d4);
        Qs[r * 65 + d4 + 0] = v.x * 0.125f;
        Qs[r * 65 + d4 + 1] = v.y * 0.125f;
        Qs[r * 65 + d4 + 2] = v.z * 0.125f;
        Qs[r * 65 + d4 + 3] = v.w * 0.125f;
    }

    float m[4], l[4], o[4][4];
#pragma unroll
    for (int i = 0; i < 4; i++) {
        m[i] = -1e30f; l[i] = 0.f;
#pragma unroll
        for (int j = 0; j < 4; j++) o[i][j] = 0.f;
    }

    for (int kt = 0; kt < SEQ; kt += 64) {
        __syncthreads();
#pragma unroll
        for (int qq = 0; qq < 4; qq++) {
            int lin = tid + qq * 256;
            int r = lin >> 4, d4 = (lin & 15) << 2;
            size_t go = base + (size_t)(kt + r) * HDIM + d4;
            float4 kv = *(const float4*)(K + go);
            Ks[r * 65 + d4 + 0] = kv.x; Ks[r * 65 + d4 + 1] = kv.y;
            Ks[r * 65 + d4 + 2] = kv.z; Ks[r * 65 + d4 + 3] = kv.w;
            float4 vv = *(const float4*)(V + go);
            Vs[r * 65 + d4 + 0] = vv.x; Vs[r * 65 + d4 + 1] = vv.y;
            Vs[r * 65 + d4 + 2] = vv.z; Vs[r * 65 + d4 + 3] = vv.w;
        }
        __syncthreads();

        float s[4][4];
#pragma unroll
        for (int i = 0; i < 4; i++)
#pragma unroll
            for (int j = 0; j < 4; j++) s[i][j] = 0.f;
        for (int d = 0; d < 64; d++) {
            float a[4], bb[4];
#pragma unroll
            for (int i = 0; i < 4; i++) a[i] = Qs[(ty * 4 + i) * 65 + d];
#pragma unroll
            for (int j = 0; j < 4; j++) bb[j] = Ks[(tx * 4 + j) * 65 + d];
#pragma unroll
            for (int i = 0; i < 4; i++)
#pragma unroll
                for (int j = 0; j < 4; j++) s[i][j] += a[i] * bb[j];
        }

#pragma unroll
        for (int i = 0; i < 4; i++) {
            float mx = fmaxf(fmaxf(s[i][0], s[i][1]), fmaxf(s[i][2], s[i][3]));
#pragma unroll
            for (int off = 1; off < 16; off <<= 1)
                mx = fmaxf(mx, __shfl_xor_sync(0xffffffffu, mx, off));
            float mn = fmaxf(m[i], mx);
            float cf = __expf(m[i] - mn);
            m[i] = mn;
            float ls = 0.f;
#pragma unroll
            for (int j = 0; j < 4; j++) {
                float p = __expf(s[i][j] - mn);
                Ps[(ty * 4 + i) * 65 + tx * 4 + j] = p;
                ls += p;
            }
#pragma unroll
            for (int off = 1; off < 16; off <<= 1)
                ls += __shfl_xor_sync(0xffffffffu, ls, off);
            l[i] = l[i] * cf + ls;
#pragma unroll
            for (int j = 0; j < 4; j++) o[i][j] *= cf;
        }
        __syncthreads();

        for (int kk = 0; kk < 64; kk++) {
            float p[4], vv[4];
#pragma unroll
            for (int i = 0; i < 4; i++) p[i] = Ps[(ty * 4 + i) * 65 + kk];
#pragma unroll
            for (int j = 0; j < 4; j++) vv[j] = Vs[kk * 65 + tx * 4 + j];
#pragma unroll
            for (int i = 0; i < 4; i++)
#pragma unroll
                for (int j = 0; j < 4; j++) o[i][j] += p[i] * vv[j];
        }
    }

#pragma unroll
    for (int i = 0; i < 4; i++) {
        float li = 1.f / l[i];
        int r = q0 + ty * 4 + i;
#pragma unroll
        for (int j = 0; j < 4; j++)
            O[base + (size_t)r * HDIM + tx * 4 + j] = o[i][j] * li;
    }
}

// ===========================================================================
extern "C" void kernel_launch(void* const* d_in, const int* in_sizes, int n_in,
                              void* d_out, int out_size)
{
    const float* X   = (const float*)d_in[0];
    const float* Wq  = (const float*)d_in[1];
    const float* bq  = (const float*)d_in[2];
    const float* Wk  = (const float*)d_in[3];
    const float* bk  = (const float*)d_in[4];
    const float* Wv  = (const float*)d_in[5];
    const float* bv  = (const float*)d_in[6];
    const float* Wo  = (const float*)d_in[7];
    const float* bo  = (const float*)d_in[8];
    const float* qta = (const float*)d_in[9];
    const float* qtb = (const float*)d_in[10];
    const float* kta = (const float*)d_in[11];
    const float* ktb = (const float*)d_in[12];
    const float* cpl = (const float*)d_in[13];

    float* scratch = nullptr;
    cudaGetSymbolAddress((void**)&scratch, g_scratch);
    float* Qb = scratch;
    float* Kb = scratch + 1 * 4194304;
    float* Vb = scratch + 2 * 4194304;
    float* AO = scratch + 3 * 4194304;
    float* L0 = scratch + 4 * 4194304;
    float* L1 = L0 + 262144;

    const int GS = 2 * ST_ELEMS * 2;   // 61440 B dynamic smem
    cudaFuncSetAttribute(gemm_tc, cudaFuncAttributeMaxDynamicSharedMemorySize, GS);

    dim3 gBig(16, 32);   // N=1024
    dim3 gLow(1, 32);    // N=64
    const float PI2 = 6.28318530717958647692f;

    // QKV projections (K=1024, N=1024)
    gemm_tc<<<gBig, 256, GS>>>(X, Wq, bq, nullptr, Qb, 1024, 1024, 0, 0.f, 0.f);
    gemm_tc<<<gBig, 256, GS>>>(X, Wk, bk, nullptr, Kb, 1024, 1024, 0, 0.f, 0.f);
    gemm_tc<<<gBig, 256, GS>>>(X, Wv, bv, nullptr, Vb, 1024, 1024, 0, 0.f, 0.f);

    // Torsion Q: low-rank projections from ORIGINAL Q, then in-place updates
    gemm_tc<<<gLow, 256, GS>>>(Qb, qta,         nullptr, nullptr, L0, 1024, 64, 2, 0.f, 0.f);
    gemm_tc<<<gLow, 256, GS>>>(Qb, qta + 65536, nullptr, nullptr, L1, 1024, 64, 2, 0.f, 0.f);
    gemm_tc<<<gBig, 256, GS>>>(L0, qtb,         nullptr, cpl, Qb, 64, 1024, 1, PI2,       1.0f);
    gemm_tc<<<gBig, 256, GS>>>(L1, qtb + 65536, nullptr, cpl, Qb, 64, 1024, 1, 2.f * PI2, 0.5f);

    // Torsion K
    gemm_tc<<<gLow, 256, GS>>>(Kb, kta,         nullptr, nullptr, L0, 1024, 64, 2, 0.f, 0.f);
    gemm_tc<<<gLow, 256, GS>>>(Kb, kta + 65536, nullptr, nullptr, L1, 1024, 64, 2, 0.f, 0.f);
    gemm_tc<<<gBig, 256, GS>>>(L0, ktb,         nullptr, cpl, Kb, 64, 1024, 1, PI2,       1.0f);
    gemm_tc<<<gBig, 256, GS>>>(L1, ktb + 65536, nullptr, cpl, Kb, 64, 1024, 1, 2.f * PI2, 0.5f);

    // Attention (fp32 flash)
    int fsm = 4 * 64 * 65 * (int)sizeof(float);
    cudaFuncSetAttribute(flash_kernel, cudaFuncAttributeMaxDynamicSharedMemorySize, fsm);
    dim3 gAtt(SEQ / 64, NHEAD, BATCH);
    flash_kernel<<<gAtt, 256, fsm>>>(Qb, Kb, Vb, AO);

    // Output projection -> d_out
    gemm_tc<<<gBig, 256, GS>>>(AO, Wo, bo, nullptr, (float*)d_out, 1024, 1024, 0, 0.f, 0.f);
}

// round 6
// speedup vs baseline: 2.2662x; 1.6420x over previous
#include <cuda_runtime.h>
#include <cuda_bf16.h>
#include <math.h>
#include <stdint.h>

#define MTOT 4096
#define HDIM 1024
#define NHEAD 16
#define HD 64
#define SEQ 2048
#define BATCH 2

// Scratch: Q, K, V, AO (4 x 4096*1024 floats) + LOW0/LOW1 (2 x 4096*64)
__device__ float g_scratch[4u*4194304u + 2u*262144u];

__device__ __forceinline__ uint32_t smem_u32(const void* p) {
    uint32_t a;
    asm("{ .reg .u64 t; cvta.to.shared.u64 t, %1; cvt.u32.u64 %0, t; }"
        : "=r"(a) : "l"(p));
    return a;
}

__device__ __forceinline__ void ldsm4(uint32_t* r, uint32_t addr) {
    asm volatile("ldmatrix.sync.aligned.m8n8.x4.shared.b16 {%0,%1,%2,%3}, [%4];"
                 : "=r"(r[0]), "=r"(r[1]), "=r"(r[2]), "=r"(r[3]) : "r"(addr));
}

__device__ __forceinline__ void mma16816(float* c, const uint32_t* a, const uint32_t* b) {
    asm volatile(
        "mma.sync.aligned.m16n8k16.row.col.f32.bf16.bf16.f32 "
        "{%0,%1,%2,%3}, {%4,%5,%6,%7}, {%8,%9}, {%0,%1,%2,%3};"
        : "+f"(c[0]), "+f"(c[1]), "+f"(c[2]), "+f"(c[3])
        : "r"(a[0]), "r"(a[1]), "r"(a[2]), "r"(a[3]), "r"(b[0]), "r"(b[1]));
}

__device__ __forceinline__ void cvt2(float a, float b, uint32_t* hi, uint32_t* lo) {
    __nv_bfloat162 h = __floats2bfloat162_rn(a, b);
    float2 hf = __bfloat1622float2(h);
    __nv_bfloat162 l = __floats2bfloat162_rn(a - hf.x, b - hf.y);
    *hi = *(uint32_t*)&h;
    *lo = *(uint32_t*)&l;
}

// ===========================================================================
// Split-bf16 tensor-core GEMM via mma.sync (unchanged from R5 — proven).
// ===========================================================================
#define LDT 40
#define ST_AH 0
#define ST_AL 5120
#define ST_BH 10240
#define ST_BL 12800
#define ST_ELEMS 15360

__global__ __launch_bounds__(256) void gemm_tc(
    const float* __restrict__ A, const float* __restrict__ B,
    const float* __restrict__ bias, const float* __restrict__ coupling,
    float* __restrict__ C, int K, int N, int mode, float freq, float inv)
{
    extern __shared__ __align__(16) char smraw[];
    __nv_bfloat16* sm = (__nv_bfloat16*)smraw;
    uint32_t smb = smem_u32(smraw);

    int tid = threadIdx.x, wid = tid >> 5, lane = tid & 31;
    int bm = blockIdx.y * 128, bn = blockIdx.x * 64;
    int wm = (wid & 3) * 32, wn = (wid >> 2) * 32;

    float acc[2][4][4];
#pragma unroll
    for (int i = 0; i < 2; i++)
#pragma unroll
        for (int j = 0; j < 4; j++)
#pragma unroll
            for (int e = 0; e < 4; e++) acc[i][j][e] = 0.f;

    int ar = tid >> 1, ac0 = (tid & 1) * 16;
    int bnn = tid >> 2, bk0 = (tid & 3) * 8;

    float Areg[16], Breg[8];
    int nchunks = K >> 5;

    {
        const float* Ap = A + (size_t)(bm + ar) * K + ac0;
#pragma unroll
        for (int g = 0; g < 4; g++) *(float4*)(Areg + g * 4) = *(const float4*)(Ap + g * 4);
        const float* Bp = B + (size_t)bk0 * N + bn + bnn;
#pragma unroll
        for (int e = 0; e < 8; e++) Breg[e] = Bp[(size_t)e * N];
    }

    for (int c = 0; c < nchunks; c++) {
        int s = c & 1;
        __nv_bfloat16* st = sm + s * ST_ELEMS;

        {
            uint4 hi, lo;
            cvt2(Areg[0], Areg[1], &hi.x, &lo.x);
            cvt2(Areg[2], Areg[3], &hi.y, &lo.y);
            cvt2(Areg[4], Areg[5], &hi.z, &lo.z);
            cvt2(Areg[6], Areg[7], &hi.w, &lo.w);
            *(uint4*)(st + ST_AH + ar * LDT + ac0) = hi;
            *(uint4*)(st + ST_AL + ar * LDT + ac0) = lo;
            cvt2(Areg[8],  Areg[9],  &hi.x, &lo.x);
            cvt2(Areg[10], Areg[11], &hi.y, &lo.y);
            cvt2(Areg[12], Areg[13], &hi.z, &lo.z);
            cvt2(Areg[14], Areg[15], &hi.w, &lo.w);
            *(uint4*)(st + ST_AH + ar * LDT + ac0 + 8) = hi;
            *(uint4*)(st + ST_AL + ar * LDT + ac0 + 8) = lo;

            cvt2(Breg[0], Breg[1], &hi.x, &lo.x);
            cvt2(Breg[2], Breg[3], &hi.y, &lo.y);
            cvt2(Breg[4], Breg[5], &hi.z, &lo.z);
            cvt2(Breg[6], Breg[7], &hi.w, &lo.w);
            *(uint4*)(st + ST_BH + bnn * LDT + bk0) = hi;
            *(uint4*)(st + ST_BL + bnn * LDT + bk0) = lo;
        }
        __syncthreads();

        if (c + 1 < nchunks) {
            const float* Ap = A + (size_t)(bm + ar) * K + (c + 1) * 32 + ac0;
#pragma unroll
            for (int g = 0; g < 4; g++) *(float4*)(Areg + g * 4) = *(const float4*)(Ap + g * 4);
            const float* Bp = B + (size_t)((c + 1) * 32 + bk0) * N + bn + bnn;
#pragma unroll
            for (int e = 0; e < 8; e++) Breg[e] = Bp[(size_t)e * N];
        }

        uint32_t stA = smb + (uint32_t)(s * ST_ELEMS) * 2;
        uint32_t stAl = stA + ST_AL * 2;
        uint32_t stBh = stA + ST_BH * 2;
        uint32_t stBl = stA + ST_BL * 2;

#pragma unroll
        for (int kk = 0; kk < 32; kk += 16) {
            uint32_t ah[2][4], al[2][4], bh[4][2], bl[4][2];
#pragma unroll
            for (int i = 0; i < 2; i++) {
                uint32_t roff = (uint32_t)((wm + i * 16 + (lane & 15)) * LDT
                                           + kk + ((lane >> 4) << 3)) * 2;
                ldsm4(ah[i], stA + roff);
                ldsm4(al[i], stAl + roff);
            }
#pragma unroll
            for (int p = 0; p < 2; p++) {
                uint32_t noff = (uint32_t)((wn + p * 16 + (lane & 7) + ((lane >> 4) << 3)) * LDT
                                           + kk + (((lane >> 3) & 1) << 3)) * 2;
                uint32_t r[4];
                ldsm4(r, stBh + noff);
                bh[p * 2][0] = r[0]; bh[p * 2][1] = r[1];
                bh[p * 2 + 1][0] = r[2]; bh[p * 2 + 1][1] = r[3];
                ldsm4(r, stBl + noff);
                bl[p * 2][0] = r[0]; bl[p * 2][1] = r[1];
                bl[p * 2 + 1][0] = r[2]; bl[p * 2 + 1][1] = r[3];
            }
#pragma unroll
            for (int i = 0; i < 2; i++)
#pragma unroll
                for (int j = 0; j < 4; j++) {
                    mma16816(acc[i][j], ah[i], bh[j]);
                    mma16816(acc[i][j], ah[i], bl[j]);
                    mma16816(acc[i][j], al[i], bh[j]);
                }
        }
        __syncthreads();
    }

    int g = lane >> 2, q = lane & 3;
    float sg = 0.f;
    if (mode == 1) sg = 1.f / (1.f + __expf(-(*coupling)));

#pragma unroll
    for (int i = 0; i < 2; i++) {
#pragma unroll
        for (int j = 0; j < 4; j++) {
            int row = bm + wm + i * 16 + g;
            int col = bn + wn + j * 8 + q * 2;
#pragma unroll
            for (int h = 0; h < 2; h++) {
                float* Cp = C + (size_t)(row + h * 8) * N + col;
                float d0 = acc[i][j][h * 2 + 0];
                float d1 = acc[i][j][h * 2 + 1];
                if (mode == 0) {
                    float2 o = { d0 + bias[col], d1 + bias[col + 1] };
                    *(float2*)Cp = o;
                } else if (mode == 2) {
                    float2 o = { d0, d1 };
                    *(float2*)Cp = o;
                } else {
                    float2 cv = *(float2*)Cp;
                    cv.x += sg * sinf(freq * d0) * d0 * inv;
                    cv.y += sg * sinf(freq * d1) * d1 * inv;
                    *(float2*)Cp = cv;
                }
            }
        }
    }
}

// ===========================================================================
// Tensor-core flash attention (split-bf16, mma.sync).
// Block = 128 queries of one (b,h); 8 warps, each owns 16 query rows.
// K smem [n=key][k=hd], V smem [n=hd][k=key]; both hi/lo, LDT=72, non-trans
// ldmatrix (same patterns as gemm_tc). Double-buffered, reg prefetch.
// ===========================================================================
#define FLT 72
#define FKH 0
#define FKL 4608
#define FVH 9216
#define FVL 13824
#define FSTAGE 18432            // bf16 elems per stage (36864 B)

__global__ __launch_bounds__(256) void flash_tc(
    const float* __restrict__ Q, const float* __restrict__ K,
    const float* __restrict__ V, float* __restrict__ O)
{
    extern __shared__ __align__(16) char smraw[];
    __nv_bfloat16* sm = (__nv_bfloat16*)smraw;
    uint32_t smb = smem_u32(smraw);

    int tid = threadIdx.x, wid = tid >> 5, lane = tid & 31;
    int g = lane >> 2, q = lane & 3;
    int q0 = blockIdx.x * 128, h = blockIdx.y, b = blockIdx.z;
    size_t hb = ((size_t)b * SEQ) * HDIM + (size_t)h * HD;

    // ---- Q fragments in registers (split hi/lo, scale 1/8 folded in)
    uint32_t qh[4][4], ql[4][4];
    {
        int r0 = q0 + wid * 16 + g;
        const float* Qp = Q + hb;
#pragma unroll
        for (int t = 0; t < 4; t++) {
            float2 f0 = *(const float2*)(Qp + (size_t)r0 * HDIM + 16 * t + 2 * q);
            float2 f1 = *(const float2*)(Qp + (size_t)(r0 + 8) * HDIM + 16 * t + 2 * q);
            float2 f2 = *(const float2*)(Qp + (size_t)r0 * HDIM + 16 * t + 8 + 2 * q);
            float2 f3 = *(const float2*)(Qp + (size_t)(r0 + 8) * HDIM + 16 * t + 8 + 2 * q);
            cvt2(f0.x * 0.125f, f0.y * 0.125f, &qh[t][0], &ql[t][0]);
            cvt2(f1.x * 0.125f, f1.y * 0.125f, &qh[t][1], &ql[t][1]);
            cvt2(f2.x * 0.125f, f2.y * 0.125f, &qh[t][2], &ql[t][2]);
            cvt2(f3.x * 0.125f, f3.y * 0.125f, &qh[t][3], &ql[t][3]);
        }
    }

    // ---- softmax state + O accum
    float m[2] = { -1e30f, -1e30f }, l[2] = { 0.f, 0.f };
    float o[8][4];
#pragma unroll
    for (int j = 0; j < 8; j++)
#pragma unroll
        for (int e = 0; e < 4; e++) o[j][e] = 0.f;

    // ---- K/V prefetch mappings
    int kr = tid >> 2, kc = (tid & 3) * 16;     // K: key row, 16 hd cols
    int vn = tid >> 2, vk = (tid & 3) * 16;     // V: hd col, 16 key rows (strided)
    float4 Kreg[4];
    float  Vreg[16];

    // load tile 0
    {
        const float* Kp = K + hb + (size_t)kr * HDIM + kc;
#pragma unroll
        for (int gg = 0; gg < 4; gg++) Kreg[gg] = *(const float4*)(Kp + gg * 4);
        const float* Vp = V + hb + (size_t)vk * HDIM + vn;
#pragma unroll
        for (int e = 0; e < 16; e++) Vreg[e] = Vp[(size_t)e * HDIM];
    }

    for (int kt = 0; kt < SEQ / 64; kt++) {
        int s = kt & 1;
        __nv_bfloat16* st = sm + s * FSTAGE;

        // ---- store current tile regs (cvt hi/lo)
        {
            uint4 h0, l0, h1, l1;
            cvt2(Kreg[0].x, Kreg[0].y, &h0.x, &l0.x);
            cvt2(Kreg[0].z, Kreg[0].w, &h0.y, &l0.y);
            cvt2(Kreg[1].x, Kreg[1].y, &h0.z, &l0.z);
            cvt2(Kreg[1].z, Kreg[1].w, &h0.w, &l0.w);
            cvt2(Kreg[2].x, Kreg[2].y, &h1.x, &l1.x);
            cvt2(Kreg[2].z, Kreg[2].w, &h1.y, &l1.y);
            cvt2(Kreg[3].x, Kreg[3].y, &h1.z, &l1.z);
            cvt2(Kreg[3].z, Kreg[3].w, &h1.w, &l1.w);
            *(uint4*)(st + FKH + kr * FLT + kc)     = h0;
            *(uint4*)(st + FKH + kr * FLT + kc + 8) = h1;
            *(uint4*)(st + FKL + kr * FLT + kc)     = l0;
            *(uint4*)(st + FKL + kr * FLT + kc + 8) = l1;

            cvt2(Vreg[0],  Vreg[1],  &h0.x, &l0.x);
            cvt2(Vreg[2],  Vreg[3],  &h0.y, &l0.y);
            cvt2(Vreg[4],  Vreg[5],  &h0.z, &l0.z);
            cvt2(Vreg[6],  Vreg[7],  &h0.w, &l0.w);
            cvt2(Vreg[8],  Vreg[9],  &h1.x, &l1.x);
            cvt2(Vreg[10], Vreg[11], &h1.y, &l1.y);
            cvt2(Vreg[12], Vreg[13], &h1.z, &l1.z);
            cvt2(Vreg[14], Vreg[15], &h1.w, &l1.w);
            *(uint4*)(st + FVH + vn * FLT + vk)     = h0;
            *(uint4*)(st + FVH + vn * FLT + vk + 8) = h1;
            *(uint4*)(st + FVL + vn * FLT + vk)     = l0;
            *(uint4*)(st + FVL + vn * FLT + vk + 8) = l1;
        }
        __syncthreads();

        // ---- prefetch next tile
        if (kt + 1 < SEQ / 64) {
            const float* Kp = K + hb + (size_t)((kt + 1) * 64 + kr) * HDIM + kc;
#pragma unroll
            for (int gg = 0; gg < 4; gg++) Kreg[gg] = *(const float4*)(Kp + gg * 4);
            const float* Vp = V + hb + (size_t)((kt + 1) * 64 + vk) * HDIM + vn;
#pragma unroll
            for (int e = 0; e < 16; e++) Vreg[e] = Vp[(size_t)e * HDIM];
        }

        uint32_t kbase = smb + (uint32_t)(s * FSTAGE) * 2;

        // ---- S = Q K^T (3-term split), S tile 16 x 64 per warp
        float sf[8][4];
#pragma unroll
        for (int j = 0; j < 8; j++)
#pragma unroll
            for (int e = 0; e < 4; e++) sf[j][e] = 0.f;

#pragma unroll
        for (int t = 0; t < 4; t++) {
            uint32_t kh[4][4], kl[4][4];
#pragma unroll
            for (int p = 0; p < 4; p++) {
                uint32_t off = (uint32_t)((p * 16 + (lane & 7) + ((lane >> 4) << 3)) * FLT
                                          + t * 16 + (((lane >> 3) & 1) << 3)) * 2;
                ldsm4(kh[p], kbase + FKH * 2 + off);
                ldsm4(kl[p], kbase + FKL * 2 + off);
            }
#pragma unroll
            for (int p = 0; p < 4; p++) {
                mma16816(sf[2 * p],     qh[t], kh[p]);
                mma16816(sf[2 * p],     qh[t], kl[p]);
                mma16816(sf[2 * p],     ql[t], kh[p]);
                mma16816(sf[2 * p + 1], qh[t], kh[p] + 2);
                mma16816(sf[2 * p + 1], qh[t], kl[p] + 2);
                mma16816(sf[2 * p + 1], ql[t], kh[p] + 2);
            }
        }

        // ---- online softmax on fragments (rows g, g+8)
#pragma unroll
        for (int r = 0; r < 2; r++) {
            float mx = -1e30f;
#pragma unroll
            for (int j = 0; j < 8; j++)
                mx = fmaxf(mx, fmaxf(sf[j][2 * r], sf[j][2 * r + 1]));
            mx = fmaxf(mx, __shfl_xor_sync(0xffffffffu, mx, 1));
            mx = fmaxf(mx, __shfl_xor_sync(0xffffffffu, mx, 2));
            float mn = fmaxf(m[r], mx);
            float cf = __expf(m[r] - mn);
            m[r] = mn;
            float ls = 0.f;
#pragma unroll
            for (int j = 0; j < 8; j++) {
                float p0 = __expf(sf[j][2 * r]     - mn);
                float p1 = __expf(sf[j][2 * r + 1] - mn);
                sf[j][2 * r] = p0; sf[j][2 * r + 1] = p1;
                ls += p0 + p1;
            }
            ls += __shfl_xor_sync(0xffffffffu, ls, 1);
            ls += __shfl_xor_sync(0xffffffffu, ls, 2);
            l[r] = l[r] * cf + ls;
#pragma unroll
            for (int j = 0; j < 8; j++) {
                o[j][2 * r] *= cf; o[j][2 * r + 1] *= cf;
            }
        }

        // ---- O += P V (3-term split); P c-frag -> a-frag layout identity
#pragma unroll
        for (int t = 0; t < 4; t++) {
            uint32_t pa_h[4], pa_l[4];
            cvt2(sf[2 * t][0],     sf[2 * t][1],     &pa_h[0], &pa_l[0]);
            cvt2(sf[2 * t][2],     sf[2 * t][3],     &pa_h[1], &pa_l[1]);
            cvt2(sf[2 * t + 1][0], sf[2 * t + 1][1], &pa_h[2], &pa_l[2]);
            cvt2(sf[2 * t + 1][2], sf[2 * t + 1][3], &pa_h[3], &pa_l[3]);
#pragma unroll
            for (int p = 0; p < 4; p++) {
                uint32_t off = (uint32_t)((p * 16 + (lane & 7) + ((lane >> 4) << 3)) * FLT
                                          + t * 16 + (((lane >> 3) & 1) << 3)) * 2;
                uint32_t vh[4], vl[4];
                ldsm4(vh, kbase + FVH * 2 + off);
                ldsm4(vl, kbase + FVL * 2 + off);
                mma16816(o[2 * p],     pa_h, vh);
                mma16816(o[2 * p],     pa_h, vl);
                mma16816(o[2 * p],     pa_l, vh);
                mma16816(o[2 * p + 1], pa_h, vh + 2);
                mma16816(o[2 * p + 1], pa_h, vl + 2);
                mma16816(o[2 * p + 1], pa_l, vh + 2);
            }
        }
    }

    // ---- epilogue
    {
        int r0 = q0 + wid * 16 + g;
#pragma unroll
        for (int r = 0; r < 2; r++) {
            float invl = 1.f / l[r];
            int row = r0 + r * 8;
#pragma unroll
            for (int j = 0; j < 8; j++) {
                float2 o2 = { o[j][2 * r] * invl, o[j][2 * r + 1] * invl };
                *(float2*)(O + hb + (size_t)row * HDIM + j * 8 + 2 * q) = o2;
            }
        }
    }
}

// ===========================================================================
extern "C" void kernel_launch(void* const* d_in, const int* in_sizes, int n_in,
                              void* d_out, int out_size)
{
    const float* X   = (const float*)d_in[0];
    const float* Wq  = (const float*)d_in[1];
    const float* bq  = (const float*)d_in[2];
    const float* Wk  = (const float*)d_in[3];
    const float* bk  = (const float*)d_in[4];
    const float* Wv  = (const float*)d_in[5];
    const float* bv  = (const float*)d_in[6];
    const float* Wo  = (const float*)d_in[7];
    const float* bo  = (const float*)d_in[8];
    const float* qta = (const float*)d_in[9];
    const float* qtb = (const float*)d_in[10];
    const float* kta = (const float*)d_in[11];
    const float* ktb = (const float*)d_in[12];
    const float* cpl = (const float*)d_in[13];

    float* scratch = nullptr;
    cudaGetSymbolAddress((void**)&scratch, g_scratch);
    float* Qb = scratch;
    float* Kb = scratch + 1 * 4194304;
    float* Vb = scratch + 2 * 4194304;
    float* AO = scratch + 3 * 4194304;
    float* L0 = scratch + 4 * 4194304;
    float* L1 = L0 + 262144;

    const int GS = 2 * ST_ELEMS * 2;   // 61440 B
    cudaFuncSetAttribute(gemm_tc, cudaFuncAttributeMaxDynamicSharedMemorySize, GS);

    dim3 gBig(16, 32);
    dim3 gLow(1, 32);
    const float PI2 = 6.28318530717958647692f;

    // QKV projections
    gemm_tc<<<gBig, 256, GS>>>(X, Wq, bq, nullptr, Qb, 1024, 1024, 0, 0.f, 0.f);
    gemm_tc<<<gBig, 256, GS>>>(X, Wk, bk, nullptr, Kb, 1024, 1024, 0, 0.f, 0.f);
    gemm_tc<<<gBig, 256, GS>>>(X, Wv, bv, nullptr, Vb, 1024, 1024, 0, 0.f, 0.f);

    // Torsion Q
    gemm_tc<<<gLow, 256, GS>>>(Qb, qta,         nullptr, nullptr, L0, 1024, 64, 2, 0.f, 0.f);
    gemm_tc<<<gLow, 256, GS>>>(Qb, qta + 65536, nullptr, nullptr, L1, 1024, 64, 2, 0.f, 0.f);
    gemm_tc<<<gBig, 256, GS>>>(L0, qtb,         nullptr, cpl, Qb, 64, 1024, 1, PI2,       1.0f);
    gemm_tc<<<gBig, 256, GS>>>(L1, qtb + 65536, nullptr, cpl, Qb, 64, 1024, 1, 2.f * PI2, 0.5f);

    // Torsion K
    gemm_tc<<<gLow, 256, GS>>>(Kb, kta,         nullptr, nullptr, L0, 1024, 64, 2, 0.f, 0.f);
    gemm_tc<<<gLow, 256, GS>>>(Kb, kta + 65536, nullptr, nullptr, L1, 1024, 64, 2, 0.f, 0.f);
    gemm_tc<<<gBig, 256, GS>>>(L0, ktb,         nullptr, cpl, Kb, 64, 1024, 1, PI2,       1.0f);
    gemm_tc<<<gBig, 256, GS>>>(L1, ktb + 65536, nullptr, cpl, Kb, 64, 1024, 1, 2.f * PI2, 0.5f);

    // Tensor-core flash attention
    const int FS = 2 * FSTAGE * 2;     // 73728 B
    cudaFuncSetAttribute(flash_tc, cudaFuncAttributeMaxDynamicSharedMemorySize, FS);
    dim3 gAtt(SEQ / 128, NHEAD, BATCH);
    flash_tc<<<gAtt, 256, FS>>>(Qb, Kb, Vb, AO);

    // Output projection -> d_out
    gemm_tc<<<gBig, 256, GS>>>(AO, Wo, bo, nullptr, (float*)d_out, 1024, 1024, 0, 0.f, 0.f);
}

// round 7
// speedup vs baseline: 2.4254x; 1.0703x over previous
#include <cuda_runtime.h>
#include <cuda_bf16.h>
#include <math.h>
#include <stdint.h>

#define MTOT 4096
#define HDIM 1024
#define NHEAD 16
#define HD 64
#define SEQ 2048
#define BATCH 2

typedef __nv_bfloat16 bf16;

// ---------------- scratch ----------------
// fp32: Qf, Kf (needed for torsion read-modify-write)
__device__ float g_f32[2u * 4194304u];
// bf16 planes
#define O_XH   0u
#define O_XL   4194304u
#define O_WT   8388608u      // WqTh,WqTl,WkTh,WkTl,WvTh,WvTl,WoTh,WoTl (8 x 1048576)
#define O_TA   16777216u     // qta0h,qta0l,qta1h,qta1l,kta0h,kta0l,kta1h,kta1l (8 x 65536)
#define O_TB   17301504u     // qtb0h,qtb0l,qtb1h,qtb1l,ktb0h,ktb0l,ktb1h,ktb1l (8 x 65536)
#define O_QBH  17825792u
#define O_QBL  22020096u
#define O_KBH  26214400u
#define O_KBL  30408704u
#define O_VBH  34603008u
#define O_VBL  38797312u
#define O_AOH  42991616u
#define O_AOL  47185920u
#define O_LB   51380224u     // L0h,L0l,L1h,L1l (4 x 262144)
__device__ bf16 g_bf[52428800u];

// ---------------- helpers ----------------
__device__ __forceinline__ uint32_t smem_u32(const void* p) {
    uint32_t a;
    asm("{ .reg .u64 t; cvta.to.shared.u64 t, %1; cvt.u32.u64 %0, t; }"
        : "=r"(a) : "l"(p));
    return a;
}
__device__ __forceinline__ void ldsm4(uint32_t* r, uint32_t addr) {
    asm volatile("ldmatrix.sync.aligned.m8n8.x4.shared.b16 {%0,%1,%2,%3}, [%4];"
                 : "=r"(r[0]), "=r"(r[1]), "=r"(r[2]), "=r"(r[3]) : "r"(addr));
}
__device__ __forceinline__ void mma16816(float* c, const uint32_t* a, const uint32_t* b) {
    asm volatile(
        "mma.sync.aligned.m16n8k16.row.col.f32.bf16.bf16.f32 "
        "{%0,%1,%2,%3}, {%4,%5,%6,%7}, {%8,%9}, {%0,%1,%2,%3};"
        : "+f"(c[0]), "+f"(c[1]), "+f"(c[2]), "+f"(c[3])
        : "r"(a[0]), "r"(a[1]), "r"(a[2]), "r"(a[3]), "r"(b[0]), "r"(b[1]));
}
__device__ __forceinline__ void cvt2(float a, float b, uint32_t* hi, uint32_t* lo) {
    __nv_bfloat162 h = __floats2bfloat162_rn(a, b);
    float2 hf = __bfloat1622float2(h);
    __nv_bfloat162 l = __floats2bfloat162_rn(a - hf.x, b - hf.y);
    *hi = *(uint32_t*)&h;
    *lo = *(uint32_t*)&l;
}

// ---------------- pre-conversion kernels ----------------
// elementwise split fp32 -> bf16 hi/lo planes (n4 = elems/4)
__global__ __launch_bounds__(256) void split_f32(
    const float* __restrict__ in, bf16* __restrict__ oh, bf16* __restrict__ ol, int n4)
{
    int i = blockIdx.x * 256 + threadIdx.x;
    if (i < n4) {
        float4 f = ((const float4*)in)[i];
        uint2 h, l;
        cvt2(f.x, f.y, &h.x, &l.x);
        cvt2(f.z, f.w, &h.y, &l.y);
        ((uint2*)oh)[i] = h;
        ((uint2*)ol)[i] = l;
    }
}

// transpose + split: in [M][N] fp32 -> out [N][M] bf16 hi/lo. M,N multiples of 32.
__global__ __launch_bounds__(256) void transpose_split(
    const float* __restrict__ in, bf16* __restrict__ oh, bf16* __restrict__ ol,
    int M, int N)
{
    __shared__ float t[32][33];
    int bx = blockIdx.x * 32;      // N
    int by = blockIdx.y * 32;      // M
    int tx = threadIdx.x & 31, ty = threadIdx.x >> 5;
#pragma unroll
    for (int i = 0; i < 32; i += 8)
        t[ty + i][tx] = in[(size_t)(by + ty + i) * N + bx + tx];
    __syncthreads();
#pragma unroll
    for (int i = 0; i < 32; i += 8) {
        float v = t[tx][ty + i];
        bf16 h = __float2bfloat16_rn(v);
        bf16 l = __float2bfloat16_rn(v - __bfloat162float(h));
        size_t o = (size_t)(bx + ty + i) * M + by + tx;
        oh[o] = h;
        ol[o] = l;
    }
}

// ===========================================================================
// Split-bf16 GEMM, pre-converted operands (cvt-free mainloop).
//   C[4096, N] = A[4096, K] @ Bt[N, K]^T
// A planes [M][K], B planes [N][K] (K-major). Tile 128x64, BK=32, 8 warps.
// modes: 0: Cf = D + bias
//        6: Cf = D + bias, planes = cvt(D + bias)
//        5: planes = cvt(D + bias)
//        2: planes = cvt(D)
//        1: Cf += sig*sin(freq*D)*D*inv
//        4: planes = cvt(Cf + sig*sin(freq*D)*D*inv)   (Cf read-only)
// blockIdx.z advances B planes by zsB elems and P planes by zsP elems.
// ===========================================================================
#define LDT 40
#define ST_AH 0
#define ST_AL 5120
#define ST_BH 10240
#define ST_BL 12800
#define ST_ELEMS 15360

__global__ __launch_bounds__(256) void gemm_bf(
    const bf16* __restrict__ Ah, const bf16* __restrict__ Al,
    const bf16* __restrict__ Bh, const bf16* __restrict__ Bl,
    const float* __restrict__ bias, const float* __restrict__ coupling,
    float* __restrict__ Cf, bf16* __restrict__ Ph, bf16* __restrict__ Pl,
    int K, int N, int mode, float freq, float inv, int zsB, int zsP)
{
    extern __shared__ __align__(16) char smraw[];
    bf16* sm = (bf16*)smraw;
    uint32_t smb = smem_u32(smraw);

    int z = blockIdx.z;
    Bh += (size_t)z * zsB; Bl += (size_t)z * zsB;
    Ph += (size_t)z * zsP; Pl += (size_t)z * zsP;

    int tid = threadIdx.x, wid = tid >> 5, lane = tid & 31;
    int bm = blockIdx.y * 128, bn = blockIdx.x * 64;
    int wm = (wid & 3) * 32, wn = (wid >> 2) * 32;

    float acc[2][4][4];
#pragma unroll
    for (int i = 0; i < 2; i++)
#pragma unroll
        for (int j = 0; j < 4; j++)
#pragma unroll
            for (int e = 0; e < 4; e++) acc[i][j][e] = 0.f;

    int ar = tid >> 1, ac0 = (tid & 1) * 16;
    int bnn = tid >> 2, bk0 = (tid & 3) * 8;

    uint4 Avh[2], Avl[2], Bvh, Bvl;
    int nchunks = K >> 5;

    {
        const bf16* Aph = Ah + (size_t)(bm + ar) * K + ac0;
        const bf16* Apl = Al + (size_t)(bm + ar) * K + ac0;
        Avh[0] = *(const uint4*)Aph; Avh[1] = *(const uint4*)(Aph + 8);
        Avl[0] = *(const uint4*)Apl; Avl[1] = *(const uint4*)(Apl + 8);
        Bvh = *(const uint4*)(Bh + (size_t)(bn + bnn) * K + bk0);
        Bvl = *(const uint4*)(Bl + (size_t)(bn + bnn) * K + bk0);
    }

    for (int c = 0; c < nchunks; c++) {
        int s = c & 1;
        bf16* st = sm + s * ST_ELEMS;

        *(uint4*)(st + ST_AH + ar * LDT + ac0)     = Avh[0];
        *(uint4*)(st + ST_AH + ar * LDT + ac0 + 8) = Avh[1];
        *(uint4*)(st + ST_AL + ar * LDT + ac0)     = Avl[0];
        *(uint4*)(st + ST_AL + ar * LDT + ac0 + 8) = Avl[1];
        *(uint4*)(st + ST_BH + bnn * LDT + bk0)    = Bvh;
        *(uint4*)(st + ST_BL + bnn * LDT + bk0)    = Bvl;
        __syncthreads();

        if (c + 1 < nchunks) {
            const bf16* Aph = Ah + (size_t)(bm + ar) * K + (c + 1) * 32 + ac0;
            const bf16* Apl = Al + (size_t)(bm + ar) * K + (c + 1) * 32 + ac0;
            Avh[0] = *(const uint4*)Aph; Avh[1] = *(const uint4*)(Aph + 8);
            Avl[0] = *(const uint4*)Apl; Avl[1] = *(const uint4*)(Apl + 8);
            Bvh = *(const uint4*)(Bh + (size_t)(bn + bnn) * K + (c + 1) * 32 + bk0);
            Bvl = *(const uint4*)(Bl + (size_t)(bn + bnn) * K + (c + 1) * 32 + bk0);
        }

        uint32_t stA  = smb + (uint32_t)(s * ST_ELEMS) * 2;
        uint32_t stAl = stA + ST_AL * 2;
        uint32_t stBh = stA + ST_BH * 2;
        uint32_t stBl = stA + ST_BL * 2;

#pragma unroll
        for (int kk = 0; kk < 32; kk += 16) {
            uint32_t ah[2][4], al[2][4], bh[4][2], bl[4][2];
#pragma unroll
            for (int i = 0; i < 2; i++) {
                uint32_t roff = (uint32_t)((wm + i * 16 + (lane & 15)) * LDT
                                           + kk + ((lane >> 4) << 3)) * 2;
                ldsm4(ah[i], stA + roff);
                ldsm4(al[i], stAl + roff);
            }
#pragma unroll
            for (int p = 0; p < 2; p++) {
                uint32_t noff = (uint32_t)((wn + p * 16 + (lane & 7) + ((lane >> 4) << 3)) * LDT
                                           + kk + (((lane >> 3) & 1) << 3)) * 2;
                uint32_t r[4];
                ldsm4(r, stBh + noff);
                bh[p * 2][0] = r[0]; bh[p * 2][1] = r[1];
                bh[p * 2 + 1][0] = r[2]; bh[p * 2 + 1][1] = r[3];
                ldsm4(r, stBl + noff);
                bl[p * 2][0] = r[0]; bl[p * 2][1] = r[1];
                bl[p * 2 + 1][0] = r[2]; bl[p * 2 + 1][1] = r[3];
            }
#pragma unroll
            for (int i = 0; i < 2; i++)
#pragma unroll
                for (int j = 0; j < 4; j++) {
                    mma16816(acc[i][j], ah[i], bh[j]);
                    mma16816(acc[i][j], ah[i], bl[j]);
                    mma16816(acc[i][j], al[i], bh[j]);
                }
        }
        __syncthreads();
    }

    int g = lane >> 2, q = lane & 3;
    float sg = 0.f;
    if (mode == 1 || mode == 4) sg = 1.f / (1.f + __expf(-(*coupling)));

#pragma unroll
    for (int i = 0; i < 2; i++) {
#pragma unroll
        for (int j = 0; j < 4; j++) {
            int row = bm + wm + i * 16 + g;
            int col = bn + wn + j * 8 + q * 2;
#pragma unroll
            for (int h = 0; h < 2; h++) {
                size_t off = (size_t)(row + h * 8) * N + col;
                float d0 = acc[i][j][h * 2 + 0];
                float d1 = acc[i][j][h * 2 + 1];
                if (mode == 0) {
                    float2 o = { d0 + bias[col], d1 + bias[col + 1] };
                    *(float2*)(Cf + off) = o;
                } else if (mode == 6) {
                    float b0 = d0 + bias[col], b1 = d1 + bias[col + 1];
                    float2 o = { b0, b1 };
                    *(float2*)(Cf + off) = o;
                    uint32_t ph, pl;
                    cvt2(b0, b1, &ph, &pl);
                    *(uint32_t*)(Ph + off) = ph;
                    *(uint32_t*)(Pl + off) = pl;
                } else if (mode == 5) {
                    float b0 = d0 + bias[col], b1 = d1 + bias[col + 1];
                    uint32_t ph, pl;
                    cvt2(b0, b1, &ph, &pl);
                    *(uint32_t*)(Ph + off) = ph;
                    *(uint32_t*)(Pl + off) = pl;
                } else if (mode == 2) {
                    uint32_t ph, pl;
                    cvt2(d0, d1, &ph, &pl);
                    *(uint32_t*)(Ph + off) = ph;
                    *(uint32_t*)(Pl + off) = pl;
                } else if (mode == 1) {
                    float2 cv = *(float2*)(Cf + off);
                    cv.x += sg * sinf(freq * d0) * d0 * inv;
                    cv.y += sg * sinf(freq * d1) * d1 * inv;
                    *(float2*)(Cf + off) = cv;
                } else {   // mode 4
                    float2 cv = *(float2*)(Cf + off);
                    float t0 = cv.x + sg * sinf(freq * d0) * d0 * inv;
                    float t1 = cv.y + sg * sinf(freq * d1) * d1 * inv;
                    uint32_t ph, pl;
                    cvt2(t0, t1, &ph, &pl);
                    *(uint32_t*)(Ph + off) = ph;
                    *(uint32_t*)(Pl + off) = pl;
                }
            }
        }
    }
}

// ===========================================================================
// Tensor-core flash attention, pre-split bf16 operands.
// Block = 128 queries of one (b,h); 8 warps. Emits AO as bf16 hi/lo planes.
// ===========================================================================
#define FLT 72
#define FKH 0
#define FKL 4608
#define FVH 9216
#define FVL 13824
#define FSTAGE 18432

__device__ __forceinline__ uint32_t ldscale(const bf16* p) {
    __nv_bfloat162 v = *(const __nv_bfloat162*)p;
    __nv_bfloat162 s = __float2bfloat162_rn(0.125f);
    v = __hmul2(v, s);
    return *(uint32_t*)&v;
}

__global__ __launch_bounds__(256) void flash_bf(
    const bf16* __restrict__ Qh, const bf16* __restrict__ Ql,
    const bf16* __restrict__ Kh, const bf16* __restrict__ Kl,
    const bf16* __restrict__ Vh, const bf16* __restrict__ Vl,
    bf16* __restrict__ Oh, bf16* __restrict__ Ol)
{
    extern __shared__ __align__(16) char smraw[];
    bf16* sm = (bf16*)smraw;
    uint32_t smb = smem_u32(smraw);

    int tid = threadIdx.x, wid = tid >> 5, lane = tid & 31;
    int g = lane >> 2, q = lane & 3;
    int q0 = blockIdx.x * 128, h = blockIdx.y, b = blockIdx.z;
    size_t hb = ((size_t)b * SEQ) * HDIM + (size_t)h * HD;

    // ---- Q fragments (pre-split planes, exact x0.125 scale)
    uint32_t qh[4][4], ql[4][4];
    {
        int r0 = q0 + wid * 16 + g;
        const bf16* Qph = Qh + hb;
        const bf16* Qpl = Ql + hb;
#pragma unroll
        for (int t = 0; t < 4; t++) {
            qh[t][0] = ldscale(Qph + (size_t)r0 * HDIM + 16 * t + 2 * q);
            qh[t][1] = ldscale(Qph + (size_t)(r0 + 8) * HDIM + 16 * t + 2 * q);
            qh[t][2] = ldscale(Qph + (size_t)r0 * HDIM + 16 * t + 8 + 2 * q);
            qh[t][3] = ldscale(Qph + (size_t)(r0 + 8) * HDIM + 16 * t + 8 + 2 * q);
            ql[t][0] = ldscale(Qpl + (size_t)r0 * HDIM + 16 * t + 2 * q);
            ql[t][1] = ldscale(Qpl + (size_t)(r0 + 8) * HDIM + 16 * t + 2 * q);
            ql[t][2] = ldscale(Qpl + (size_t)r0 * HDIM + 16 * t + 8 + 2 * q);
            ql[t][3] = ldscale(Qpl + (size_t)(r0 + 8) * HDIM + 16 * t + 8 + 2 * q);
        }
    }

    float m[2] = { -1e30f, -1e30f }, l[2] = { 0.f, 0.f };
    float o[8][4];
#pragma unroll
    for (int j = 0; j < 8; j++)
#pragma unroll
        for (int e = 0; e < 4; e++) o[j][e] = 0.f;

    int kr = tid >> 2, kc = (tid & 3) * 16;
    int vn = tid >> 2, vk = (tid & 3) * 16;

    uint4 Khr[2], Klr[2];
    bf16 Vhr[16], Vlr[16];

    {
        const bf16* Kph = Kh + hb + (size_t)kr * HDIM + kc;
        const bf16* Kpl = Kl + hb + (size_t)kr * HDIM + kc;
        Khr[0] = *(const uint4*)Kph; Khr[1] = *(const uint4*)(Kph + 8);
        Klr[0] = *(const uint4*)Kpl; Klr[1] = *(const uint4*)(Kpl + 8);
        const bf16* Vph = Vh + hb + (size_t)vk * HDIM + vn;
        const bf16* Vpl = Vl + hb + (size_t)vk * HDIM + vn;
#pragma unroll
        for (int e = 0; e < 16; e++) {
            Vhr[e] = Vph[(size_t)e * HDIM];
            Vlr[e] = Vpl[(size_t)e * HDIM];
        }
    }

    for (int kt = 0; kt < SEQ / 64; kt++) {
        int s = kt & 1;
        bf16* st = sm + s * FSTAGE;

        *(uint4*)(st + FKH + kr * FLT + kc)     = Khr[0];
        *(uint4*)(st + FKH + kr * FLT + kc + 8) = Khr[1];
        *(uint4*)(st + FKL + kr * FLT + kc)     = Klr[0];
        *(uint4*)(st + FKL + kr * FLT + kc + 8) = Klr[1];
#pragma unroll
        for (int e = 0; e < 16; e++) {
            st[FVH + vn * FLT + vk + e] = Vhr[e];
            st[FVL + vn * FLT + vk + e] = Vlr[e];
        }
        __syncthreads();

        if (kt + 1 < SEQ / 64) {
            const bf16* Kph = Kh + hb + (size_t)((kt + 1) * 64 + kr) * HDIM + kc;
            const bf16* Kpl = Kl + hb + (size_t)((kt + 1) * 64 + kr) * HDIM + kc;
            Khr[0] = *(const uint4*)Kph; Khr[1] = *(const uint4*)(Kph + 8);
            Klr[0] = *(const uint4*)Kpl; Klr[1] = *(const uint4*)(Kpl + 8);
            const bf16* Vph = Vh + hb + (size_t)((kt + 1) * 64 + vk) * HDIM + vn;
            const bf16* Vpl = Vl + hb + (size_t)((kt + 1) * 64 + vk) * HDIM + vn;
#pragma unroll
            for (int e = 0; e < 16; e++) {
                Vhr[e] = Vph[(size_t)e * HDIM];
                Vlr[e] = Vpl[(size_t)e * HDIM];
            }
        }

        uint32_t kbase = smb + (uint32_t)(s * FSTAGE) * 2;

        float sf[8][4];
#pragma unroll
        for (int j = 0; j < 8; j++)
#pragma unroll
            for (int e = 0; e < 4; e++) sf[j][e] = 0.f;

#pragma unroll
        for (int t = 0; t < 4; t++) {
            uint32_t kh[4][4], kl[4][4];
#pragma unroll
            for (int p = 0; p < 4; p++) {
                uint32_t off = (uint32_t)((p * 16 + (lane & 7) + ((lane >> 4) << 3)) * FLT
                                          + t * 16 + (((lane >> 3) & 1) << 3)) * 2;
                ldsm4(kh[p], kbase + FKH * 2 + off);
                ldsm4(kl[p], kbase + FKL * 2 + off);
            }
#pragma unroll
            for (int p = 0; p < 4; p++) {
                mma16816(sf[2 * p],     qh[t], kh[p]);
                mma16816(sf[2 * p],     qh[t], kl[p]);
                mma16816(sf[2 * p],     ql[t], kh[p]);
                mma16816(sf[2 * p + 1], qh[t], kh[p] + 2);
                mma16816(sf[2 * p + 1], qh[t], kl[p] + 2);
                mma16816(sf[2 * p + 1], ql[t], kh[p] + 2);
            }
        }

#pragma unroll
        for (int r = 0; r < 2; r++) {
            float mx = -1e30f;
#pragma unroll
            for (int j = 0; j < 8; j++)
                mx = fmaxf(mx, fmaxf(sf[j][2 * r], sf[j][2 * r + 1]));
            mx = fmaxf(mx, __shfl_xor_sync(0xffffffffu, mx, 1));
            mx = fmaxf(mx, __shfl_xor_sync(0xffffffffu, mx, 2));
            float mn = fmaxf(m[r], mx);
            float cf = __expf(m[r] - mn);
            m[r] = mn;
            float ls = 0.f;
#pragma unroll
            for (int j = 0; j < 8; j++) {
                float p0 = __expf(sf[j][2 * r]     - mn);
                float p1 = __expf(sf[j][2 * r + 1] - mn);
                sf[j][2 * r] = p0; sf[j][2 * r + 1] = p1;
                ls += p0 + p1;
            }
            ls += __shfl_xor_sync(0xffffffffu, ls, 1);
            ls += __shfl_xor_sync(0xffffffffu, ls, 2);
            l[r] = l[r] * cf + ls;
#pragma unroll
            for (int j = 0; j < 8; j++) {
                o[j][2 * r] *= cf; o[j][2 * r + 1] *= cf;
            }
        }

#pragma unroll
        for (int t = 0; t < 4; t++) {
            uint32_t pa_h[4], pa_l[4];
            cvt2(sf[2 * t][0],     sf[2 * t][1],     &pa_h[0], &pa_l[0]);
            cvt2(sf[2 * t][2],     sf[2 * t][3],     &pa_h[1], &pa_l[1]);
            cvt2(sf[2 * t + 1][0], sf[2 * t + 1][1], &pa_h[2], &pa_l[2]);
            cvt2(sf[2 * t + 1][2], sf[2 * t + 1][3], &pa_h[3], &pa_l[3]);
#pragma unroll
            for (int p = 0; p < 4; p++) {
                uint32_t off = (uint32_t)((p * 16 + (lane & 7) + ((lane >> 4) << 3)) * FLT
                                          + t * 16 + (((lane >> 3) & 1) << 3)) * 2;
                uint32_t vh[4], vl[4];
                ldsm4(vh, kbase + FVH * 2 + off);
                ldsm4(vl, kbase + FVL * 2 + off);
                mma16816(o[2 * p],     pa_h, vh);
                mma16816(o[2 * p],     pa_h, vl);
                mma16816(o[2 * p],     pa_l, vh);
                mma16816(o[2 * p + 1], pa_h, vh + 2);
                mma16816(o[2 * p + 1], pa_h, vl + 2);
                mma16816(o[2 * p + 1], pa_l, vh + 2);
            }
        }
    }

    // ---- epilogue: emit AO as bf16 hi/lo planes
    {
        int r0 = q0 + wid * 16 + g;
#pragma unroll
        for (int r = 0; r < 2; r++) {
            float invl = 1.f / l[r];
            int row = r0 + r * 8;
#pragma unroll
            for (int j = 0; j < 8; j++) {
                float v0 = o[j][2 * r] * invl;
                float v1 = o[j][2 * r + 1] * invl;
                uint32_t ph, pl;
                cvt2(v0, v1, &ph, &pl);
                size_t off = hb + (size_t)row * HDIM + j * 8 + 2 * q;
                *(uint32_t*)(Oh + off) = ph;
                *(uint32_t*)(Ol + off) = pl;
            }
        }
    }
}

// ===========================================================================
extern "C" void kernel_launch(void* const* d_in, const int* in_sizes, int n_in,
                              void* d_out, int out_size)
{
    const float* X   = (const float*)d_in[0];
    const float* Wq  = (const float*)d_in[1];
    const float* bq  = (const float*)d_in[2];
    const float* Wk  = (const float*)d_in[3];
    const float* bk  = (const float*)d_in[4];
    const float* Wv  = (const float*)d_in[5];
    const float* bv  = (const float*)d_in[6];
    const float* Wo  = (const float*)d_in[7];
    const float* bo  = (const float*)d_in[8];
    const float* qta = (const float*)d_in[9];
    const float* qtb = (const float*)d_in[10];
    const float* kta = (const float*)d_in[11];
    const float* ktb = (const float*)d_in[12];
    const float* cpl = (const float*)d_in[13];

    float* f32 = nullptr;
    bf16* bf = nullptr;
    cudaGetSymbolAddress((void**)&f32, g_f32);
    cudaGetSymbolAddress((void**)&bf, g_bf);
    float* Qf = f32;
    float* Kf = f32 + 4194304;

    const int GS = 2 * ST_ELEMS * 2;   // 61440 B
    const int FS = 2 * FSTAGE * 2;     // 73728 B
    cudaFuncSetAttribute(gemm_bf, cudaFuncAttributeMaxDynamicSharedMemorySize, GS);
    cudaFuncSetAttribute(flash_bf, cudaFuncAttributeMaxDynamicSharedMemorySize, FS);

    const float PI2 = 6.28318530717958647692f;

    // ---- pre-convert: X split; weights transpose+split
    split_f32<<<4096, 256>>>(X, bf + O_XH, bf + O_XL, 1048576);
    dim3 gW(32, 32);
    transpose_split<<<gW, 256>>>(Wq, bf + O_WT + 0u,       bf + O_WT + 1048576u, 1024, 1024);
    transpose_split<<<gW, 256>>>(Wk, bf + O_WT + 2097152u, bf + O_WT + 3145728u, 1024, 1024);
    transpose_split<<<gW, 256>>>(Wv, bf + O_WT + 4194304u, bf + O_WT + 5242880u, 1024, 1024);
    transpose_split<<<gW, 256>>>(Wo, bf + O_WT + 6291456u, bf + O_WT + 7340032u, 1024, 1024);
    dim3 gTA(2, 32);    // ta: [1024][64] -> [64][1024]
    transpose_split<<<gTA, 256>>>(qta,          bf + O_TA + 0u,      bf + O_TA + 65536u,  1024, 64);
    transpose_split<<<gTA, 256>>>(qta + 65536,  bf + O_TA + 131072u, bf + O_TA + 196608u, 1024, 64);
    transpose_split<<<gTA, 256>>>(kta,          bf + O_TA + 262144u, bf + O_TA + 327680u, 1024, 64);
    transpose_split<<<gTA, 256>>>(kta + 65536,  bf + O_TA + 393216u, bf + O_TA + 458752u, 1024, 64);
    dim3 gTB(32, 2);    // tb: [64][1024] -> [1024][64]
    transpose_split<<<gTB, 256>>>(qtb,          bf + O_TB + 0u,      bf + O_TB + 65536u,  64, 1024);
    transpose_split<<<gTB, 256>>>(qtb + 65536,  bf + O_TB + 131072u, bf + O_TB + 196608u, 64, 1024);
    transpose_split<<<gTB, 256>>>(ktb,          bf + O_TB + 262144u, bf + O_TB + 327680u, 64, 1024);
    transpose_split<<<gTB, 256>>>(ktb + 65536,  bf + O_TB + 393216u, bf + O_TB + 458752u, 64, 1024);

    dim3 gBig(16, 32);
    dim3 gLow(1, 32, 2);

    // ---- QKV projections
    gemm_bf<<<gBig, 256, GS>>>(bf + O_XH, bf + O_XL,
                               bf + O_WT + 0u, bf + O_WT + 1048576u,
                               bq, nullptr, Qf, bf + O_QBH, bf + O_QBL,
                               1024, 1024, 6, 0.f, 0.f, 0, 0);
    gemm_bf<<<gBig, 256, GS>>>(bf + O_XH, bf + O_XL,
                               bf + O_WT + 2097152u, bf + O_WT + 3145728u,
                               bk, nullptr, Kf, bf + O_KBH, bf + O_KBL,
                               1024, 1024, 6, 0.f, 0.f, 0, 0);
    gemm_bf<<<gBig, 256, GS>>>(bf + O_XH, bf + O_XL,
                               bf + O_WT + 4194304u, bf + O_WT + 5242880u,
                               bv, nullptr, nullptr, bf + O_VBH, bf + O_VBL,
                               1024, 1024, 5, 0.f, 0.f, 0, 0);

    // ---- Torsion Q: both low-rank projections in one launch (z=0,1)
    gemm_bf<<<gLow, 256, GS>>>(bf + O_QBH, bf + O_QBL,
                               bf + O_TA + 0u, bf + O_TA + 65536u,
                               nullptr, nullptr, nullptr,
                               bf + O_LB, bf + O_LB + 262144u,
                               1024, 64, 2, 0.f, 0.f, 131072, 524288);
    gemm_bf<<<gBig, 256, GS>>>(bf + O_LB, bf + O_LB + 262144u,
                               bf + O_TB + 0u, bf + O_TB + 65536u,
                               nullptr, cpl, Qf, nullptr, nullptr,
                               64, 1024, 1, PI2, 1.0f, 0, 0);
    gemm_bf<<<gBig, 256, GS>>>(bf + O_LB + 524288u, bf + O_LB + 786432u,
                               bf + O_TB + 131072u, bf + O_TB + 196608u,
                               nullptr, cpl, Qf, bf + O_QBH, bf + O_QBL,
                               64, 1024, 4, 2.f * PI2, 0.5f, 0, 0);

    // ---- Torsion K
    gemm_bf<<<gLow, 256, GS>>>(bf + O_KBH, bf + O_KBL,
                               bf + O_TA + 262144u, bf + O_TA + 327680u,
                               nullptr, nullptr, nullptr,
                               bf + O_LB, bf + O_LB + 262144u,
                               1024, 64, 2, 0.f, 0.f, 131072, 524288);
    gemm_bf<<<gBig, 256, GS>>>(bf + O_LB, bf + O_LB + 262144u,
                               bf + O_TB + 262144u, bf + O_TB + 327680u,
                               nullptr, cpl, Kf, nullptr, nullptr,
                               64, 1024, 1, PI2, 1.0f, 0, 0);
    gemm_bf<<<gBig, 256, GS>>>(bf + O_LB + 524288u, bf + O_LB + 786432u,
                               bf + O_TB + 393216u, bf + O_TB + 458752u,
                               nullptr, cpl, Kf, bf + O_KBH, bf + O_KBL,
                               64, 1024, 4, 2.f * PI2, 0.5f, 0, 0);

    // ---- Flash attention (bf16 planes in, AO planes out)
    dim3 gAtt(SEQ / 128, NHEAD, BATCH);
    flash_bf<<<gAtt, 256, FS>>>(bf + O_QBH, bf + O_QBL,
                                bf + O_KBH, bf + O_KBL,
                                bf + O_VBH, bf + O_VBL,
                                bf + O_AOH, bf + O_AOL);

    // ---- Output projection -> d_out
    gemm_bf<<<gBig, 256, GS>>>(bf + O_AOH, bf + O_AOL,
                               bf + O_WT + 6291456u, bf + O_WT + 7340032u,
                               bo, nullptr, (float*)d_out, nullptr, nullptr,
                               1024, 1024, 0, 0.f, 0.f, 0, 0);
}

// round 9
// speedup vs baseline: 2.5000x; 1.0307x over previous
#include <cuda_runtime.h>
#include <cuda_bf16.h>
#include <math.h>
#include <stdint.h>

#define MTOT 4096
#define HDIM 1024
#define NHEAD 16
#define HD 64
#define SEQ 2048
#define BATCH 2

typedef __nv_bfloat16 bf16;

// ---------------- scratch ----------------
__device__ float g_f32[2u * 4194304u];
#define O_XH   0u
#define O_XL   4194304u
#define O_WT   8388608u
#define O_TA   16777216u
#define O_TB   17301504u
#define O_QBH  17825792u
#define O_QBL  22020096u
#define O_KBH  26214400u
#define O_KBL  30408704u
#define O_VBH  34603008u
#define O_VBL  38797312u
#define O_AOH  42991616u
#define O_AOL  47185920u
#define O_LB   51380224u
__device__ bf16 g_bf[52428800u];

// ---------------- helpers ----------------
__device__ __forceinline__ uint32_t smem_u32(const void* p) {
    uint32_t a;
    asm("{ .reg .u64 t; cvta.to.shared.u64 t, %1; cvt.u32.u64 %0, t; }"
        : "=r"(a) : "l"(p));
    return a;
}
__device__ __forceinline__ void ldsm4(uint32_t* r, uint32_t addr) {
    asm volatile("ldmatrix.sync.aligned.m8n8.x4.shared.b16 {%0,%1,%2,%3}, [%4];"
                 : "=r"(r[0]), "=r"(r[1]), "=r"(r[2]), "=r"(r[3]) : "r"(addr));
}
__device__ __forceinline__ void mma16816(float* c, const uint32_t* a, const uint32_t* b) {
    asm volatile(
        "mma.sync.aligned.m16n8k16.row.col.f32.bf16.bf16.f32 "
        "{%0,%1,%2,%3}, {%4,%5,%6,%7}, {%8,%9}, {%0,%1,%2,%3};"
        : "+f"(c[0]), "+f"(c[1]), "+f"(c[2]), "+f"(c[3])
        : "r"(a[0]), "r"(a[1]), "r"(a[2]), "r"(a[3]), "r"(b[0]), "r"(b[1]));
}
__device__ __forceinline__ void cvt2(float a, float b, uint32_t* hi, uint32_t* lo) {
    __nv_bfloat162 h = __floats2bfloat162_rn(a, b);
    float2 hf = __bfloat1622float2(h);
    __nv_bfloat162 l = __floats2bfloat162_rn(a - hf.x, b - hf.y);
    *hi = *(uint32_t*)&h;
    *lo = *(uint32_t*)&l;
}

// ---------------- pre-conversion kernels ----------------
__global__ __launch_bounds__(256) void split_f32(
    const float* __restrict__ in, bf16* __restrict__ oh, bf16* __restrict__ ol, int n4)
{
    int i = blockIdx.x * 256 + threadIdx.x;
    if (i < n4) {
        float4 f = ((const float4*)in)[i];
        uint2 h, l;
        cvt2(f.x, f.y, &h.x, &l.x);
        cvt2(f.z, f.w, &h.y, &l.y);
        ((uint2*)oh)[i] = h;
        ((uint2*)ol)[i] = l;
    }
}

__global__ __launch_bounds__(256) void transpose_split(
    const float* __restrict__ in, bf16* __restrict__ oh, bf16* __restrict__ ol,
    int M, int N)
{
    __shared__ float t[32][33];
    int bx = blockIdx.x * 32;
    int by = blockIdx.y * 32;
    int tx = threadIdx.x & 31, ty = threadIdx.x >> 5;
#pragma unroll
    for (int i = 0; i < 32; i += 8)
        t[ty + i][tx] = in[(size_t)(by + ty + i) * N + bx + tx];
    __syncthreads();
#pragma unroll
    for (int i = 0; i < 32; i += 8) {
        float v = t[tx][ty + i];
        bf16 h = __float2bfloat16_rn(v);
        bf16 l = __float2bfloat16_rn(v - __bfloat162float(h));
        size_t o = (size_t)(bx + ty + i) * M + by + tx;
        oh[o] = h;
        ol[o] = l;
    }
}

// ---------------- shared epilogue ----------------
__device__ __forceinline__ void epilogue_frag(
    float d0, float d1, size_t off, int col,
    const float* __restrict__ bias, float sg,
    float* __restrict__ Cf, bf16* __restrict__ Ph, bf16* __restrict__ Pl,
    int mode, float freq, float inv)
{
    if (mode == 0) {
        float2 o = { d0 + bias[col], d1 + bias[col + 1] };
        *(float2*)(Cf + off) = o;
    } else if (mode == 6) {
        float b0 = d0 + bias[col], b1 = d1 + bias[col + 1];
        float2 o = { b0, b1 };
        *(float2*)(Cf + off) = o;
        uint32_t ph, pl;
        cvt2(b0, b1, &ph, &pl);
        *(uint32_t*)(Ph + off) = ph;
        *(uint32_t*)(Pl + off) = pl;
    } else if (mode == 5) {
        float b0 = d0 + bias[col], b1 = d1 + bias[col + 1];
        uint32_t ph, pl;
        cvt2(b0, b1, &ph, &pl);
        *(uint32_t*)(Ph + off) = ph;
        *(uint32_t*)(Pl + off) = pl;
    } else if (mode == 2) {
        uint32_t ph, pl;
        cvt2(d0, d1, &ph, &pl);
        *(uint32_t*)(Ph + off) = ph;
        *(uint32_t*)(Pl + off) = pl;
    } else if (mode == 1) {
        float2 cv = *(float2*)(Cf + off);
        cv.x += sg * sinf(freq * d0) * d0 * inv;
        cv.y += sg * sinf(freq * d1) * d1 * inv;
        *(float2*)(Cf + off) = cv;
    } else {   // mode 4
        float2 cv = *(float2*)(Cf + off);
        float t0 = cv.x + sg * sinf(freq * d0) * d0 * inv;
        float t1 = cv.y + sg * sinf(freq * d1) * d1 * inv;
        uint32_t ph, pl;
        cvt2(t0, t1, &ph, &pl);
        *(uint32_t*)(Ph + off) = ph;
        *(uint32_t*)(Pl + off) = pl;
    }
}

// ===========================================================================
// gemm_bf: 128x64 tile, 256 thr (kept for N=64 torsion low-rank GEMMs).
// ===========================================================================
#define LDT 40
#define ST_AH 0
#define ST_AL 5120
#define ST_BH 10240
#define ST_BL 12800
#define ST_ELEMS 15360

__global__ __launch_bounds__(256) void gemm_bf(
    const bf16* __restrict__ Ah, const bf16* __restrict__ Al,
    const bf16* __restrict__ Bh, const bf16* __restrict__ Bl,
    const float* __restrict__ bias, const float* __restrict__ coupling,
    float* __restrict__ Cf, bf16* __restrict__ Ph, bf16* __restrict__ Pl,
    int K, int N, int mode, float freq, float inv, int zsB, int zsP)
{
    extern __shared__ __align__(16) char smraw[];
    bf16* sm = (bf16*)smraw;
    uint32_t smb = smem_u32(smraw);

    int z = blockIdx.z;
    Bh += (size_t)z * zsB; Bl += (size_t)z * zsB;
    Ph += (size_t)z * zsP; Pl += (size_t)z * zsP;

    int tid = threadIdx.x, wid = tid >> 5, lane = tid & 31;
    int bm = blockIdx.y * 128, bn = blockIdx.x * 64;
    int wm = (wid & 3) * 32, wn = (wid >> 2) * 32;

    float acc[2][4][4];
#pragma unroll
    for (int i = 0; i < 2; i++)
#pragma unroll
        for (int j = 0; j < 4; j++)
#pragma unroll
            for (int e = 0; e < 4; e++) acc[i][j][e] = 0.f;

    int ar = tid >> 1, ac0 = (tid & 1) * 16;
    int bnn = tid >> 2, bk0 = (tid & 3) * 8;

    uint4 Avh[2], Avl[2], Bvh, Bvl;
    int nchunks = K >> 5;

    {
        const bf16* Aph = Ah + (size_t)(bm + ar) * K + ac0;
        const bf16* Apl = Al + (size_t)(bm + ar) * K + ac0;
        Avh[0] = *(const uint4*)Aph; Avh[1] = *(const uint4*)(Aph + 8);
        Avl[0] = *(const uint4*)Apl; Avl[1] = *(const uint4*)(Apl + 8);
        Bvh = *(const uint4*)(Bh + (size_t)(bn + bnn) * K + bk0);
        Bvl = *(const uint4*)(Bl + (size_t)(bn + bnn) * K + bk0);
    }

    for (int c = 0; c < nchunks; c++) {
        int s = c & 1;
        bf16* st = sm + s * ST_ELEMS;

        *(uint4*)(st + ST_AH + ar * LDT + ac0)     = Avh[0];
        *(uint4*)(st + ST_AH + ar * LDT + ac0 + 8) = Avh[1];
        *(uint4*)(st + ST_AL + ar * LDT + ac0)     = Avl[0];
        *(uint4*)(st + ST_AL + ar * LDT + ac0 + 8) = Avl[1];
        *(uint4*)(st + ST_BH + bnn * LDT + bk0)    = Bvh;
        *(uint4*)(st + ST_BL + bnn * LDT + bk0)    = Bvl;
        __syncthreads();

        if (c + 1 < nchunks) {
            const bf16* Aph = Ah + (size_t)(bm + ar) * K + (c + 1) * 32 + ac0;
            const bf16* Apl = Al + (size_t)(bm + ar) * K + (c + 1) * 32 + ac0;
            Avh[0] = *(const uint4*)Aph; Avh[1] = *(const uint4*)(Aph + 8);
            Avl[0] = *(const uint4*)Apl; Avl[1] = *(const uint4*)(Apl + 8);
            Bvh = *(const uint4*)(Bh + (size_t)(bn + bnn) * K + (c + 1) * 32 + bk0);
            Bvl = *(const uint4*)(Bl + (size_t)(bn + bnn) * K + (c + 1) * 32 + bk0);
        }

        uint32_t stA  = smb + (uint32_t)(s * ST_ELEMS) * 2;
        uint32_t stAl = stA + ST_AL * 2;
        uint32_t stBh = stA + ST_BH * 2;
        uint32_t stBl = stA + ST_BL * 2;

#pragma unroll
        for (int kk = 0; kk < 32; kk += 16) {
            uint32_t ah[2][4], al[2][4], bh[4][2], bl[4][2];
#pragma unroll
            for (int i = 0; i < 2; i++) {
                uint32_t roff = (uint32_t)((wm + i * 16 + (lane & 15)) * LDT
                                           + kk + ((lane >> 4) << 3)) * 2;
                ldsm4(ah[i], stA + roff);
                ldsm4(al[i], stAl + roff);
            }
#pragma unroll
            for (int p = 0; p < 2; p++) {
                uint32_t noff = (uint32_t)((wn + p * 16 + (lane & 7) + ((lane >> 4) << 3)) * LDT
                                           + kk + (((lane >> 3) & 1) << 3)) * 2;
                uint32_t r[4];
                ldsm4(r, stBh + noff);
                bh[p * 2][0] = r[0]; bh[p * 2][1] = r[1];
                bh[p * 2 + 1][0] = r[2]; bh[p * 2 + 1][1] = r[3];
                ldsm4(r, stBl + noff);
                bl[p * 2][0] = r[0]; bl[p * 2][1] = r[1];
                bl[p * 2 + 1][0] = r[2]; bl[p * 2 + 1][1] = r[3];
            }
#pragma unroll
            for (int i = 0; i < 2; i++)
#pragma unroll
                for (int j = 0; j < 4; j++) {
                    mma16816(acc[i][j], ah[i], bh[j]);
                    mma16816(acc[i][j], ah[i], bl[j]);
                    mma16816(acc[i][j], al[i], bh[j]);
                }
        }
        __syncthreads();
    }

    int g = lane >> 2, q = lane & 3;
    float sg = 0.f;
    if (mode == 1 || mode == 4) sg = 1.f / (1.f + __expf(-(*coupling)));

#pragma unroll
    for (int i = 0; i < 2; i++)
#pragma unroll
        for (int j = 0; j < 4; j++) {
            int row = bm + wm + i * 16 + g;
            int col = bn + wn + j * 8 + q * 2;
#pragma unroll
            for (int h = 0; h < 2; h++) {
                size_t off = (size_t)(row + h * 8) * N + col;
                epilogue_frag(acc[i][j][h * 2], acc[i][j][h * 2 + 1], off, col,
                              bias, sg, Cf, Ph, Pl, mode, freq, inv);
            }
        }
}

// ===========================================================================
// gemm_bf2: 128x128 tile, 512 thr (16 warps, 4x4; warp tile 32x32).
// Per k16: 8 LDSM feed 24 MMAs (3:1) — double the MMA/LDSM ratio of gemm_bf.
// Same smem address patterns (LDT=40, roff/noff) as gemm_bf.
// ===========================================================================
#define ST2_AH 0
#define ST2_AL 5120
#define ST2_BH 10240
#define ST2_BL 15360
#define ST2_ELEMS 20480

__global__ __launch_bounds__(512, 1) void gemm_bf2(
    const bf16* __restrict__ Ah, const bf16* __restrict__ Al,
    const bf16* __restrict__ Bh, const bf16* __restrict__ Bl,
    const float* __restrict__ bias, const float* __restrict__ coupling,
    float* __restrict__ Cf, bf16* __restrict__ Ph, bf16* __restrict__ Pl,
    int K, int N, int mode, float freq, float inv)
{
    extern __shared__ __align__(16) char smraw[];
    bf16* sm = (bf16*)smraw;
    uint32_t smb = smem_u32(smraw);

    int tid = threadIdx.x, wid = tid >> 5, lane = tid & 31;
    int bm = blockIdx.y * 128, bn = blockIdx.x * 128;
    int wm = (wid & 3) * 32, wn = (wid >> 2) * 32;

    float acc[2][4][4];
#pragma unroll
    for (int i = 0; i < 2; i++)
#pragma unroll
        for (int j = 0; j < 4; j++)
#pragma unroll
            for (int e = 0; e < 4; e++) acc[i][j][e] = 0.f;

    int ar = tid >> 2, ac0 = (tid & 3) * 8;       // A: 128 rows x 32 k
    int bnn = tid >> 2, bk0 = (tid & 3) * 8;      // B: 128 n-rows x 32 k

    uint4 Avh, Avl, Bvh, Bvl;
    int nchunks = K >> 5;

    {
        Avh = *(const uint4*)(Ah + (size_t)(bm + ar) * K + ac0);
        Avl = *(const uint4*)(Al + (size_t)(bm + ar) * K + ac0);
        Bvh = *(const uint4*)(Bh + (size_t)(bn + bnn) * K + bk0);
        Bvl = *(const uint4*)(Bl + (size_t)(bn + bnn) * K + bk0);
    }

    for (int c = 0; c < nchunks; c++) {
        int s = c & 1;
        bf16* st = sm + s * ST2_ELEMS;

        *(uint4*)(st + ST2_AH + ar * LDT + ac0)  = Avh;
        *(uint4*)(st + ST2_AL + ar * LDT + ac0)  = Avl;
        *(uint4*)(st + ST2_BH + bnn * LDT + bk0) = Bvh;
        *(uint4*)(st + ST2_BL + bnn * LDT + bk0) = Bvl;
        __syncthreads();

        if (c + 1 < nchunks) {
            Avh = *(const uint4*)(Ah + (size_t)(bm + ar) * K + (c + 1) * 32 + ac0);
            Avl = *(const uint4*)(Al + (size_t)(bm + ar) * K + (c + 1) * 32 + ac0);
            Bvh = *(const uint4*)(Bh + (size_t)(bn + bnn) * K + (c + 1) * 32 + bk0);
            Bvl = *(const uint4*)(Bl + (size_t)(bn + bnn) * K + (c + 1) * 32 + bk0);
        }

        uint32_t stA  = smb + (uint32_t)(s * ST2_ELEMS) * 2;
        uint32_t stAl = stA + ST2_AL * 2;
        uint32_t stBh = stA + ST2_BH * 2;
        uint32_t stBl = stA + ST2_BL * 2;

#pragma unroll
        for (int kk = 0; kk < 32; kk += 16) {
            uint32_t ah[2][4], al[2][4], bh[4][2], bl[4][2];
#pragma unroll
            for (int i = 0; i < 2; i++) {
                uint32_t roff = (uint32_t)((wm + i * 16 + (lane & 15)) * LDT
                                           + kk + ((lane >> 4) << 3)) * 2;
                ldsm4(ah[i], stA + roff);
                ldsm4(al[i], stAl + roff);
            }
#pragma unroll
            for (int p = 0; p < 2; p++) {
                uint32_t noff = (uint32_t)((wn + p * 16 + (lane & 7) + ((lane >> 4) << 3)) * LDT
                                           + kk + (((lane >> 3) & 1) << 3)) * 2;
                uint32_t r[4];
                ldsm4(r, stBh + noff);
                bh[p * 2][0] = r[0]; bh[p * 2][1] = r[1];
                bh[p * 2 + 1][0] = r[2]; bh[p * 2 + 1][1] = r[3];
                ldsm4(r, stBl + noff);
                bl[p * 2][0] = r[0]; bl[p * 2][1] = r[1];
                bl[p * 2 + 1][0] = r[2]; bl[p * 2 + 1][1] = r[3];
            }
#pragma unroll
            for (int i = 0; i < 2; i++)
#pragma unroll
                for (int j = 0; j < 4; j++) {
                    mma16816(acc[i][j], ah[i], bh[j]);
                    mma16816(acc[i][j], ah[i], bl[j]);
                    mma16816(acc[i][j], al[i], bh[j]);
                }
        }
        __syncthreads();
    }

    int g = lane >> 2, q = lane & 3;
    float sg = 0.f;
    if (mode == 1 || mode == 4) sg = 1.f / (1.f + __expf(-(*coupling)));

#pragma unroll
    for (int i = 0; i < 2; i++)
#pragma unroll
        for (int j = 0; j < 4; j++) {
            int row = bm + wm + i * 16 + g;
            int col = bn + wn + j * 8 + q * 2;
#pragma unroll
            for (int h = 0; h < 2; h++) {
                size_t off = (size_t)(row + h * 8) * N + col;
                epilogue_frag(acc[i][j][h * 2], acc[i][j][h * 2 + 1], off, col,
                              bias, sg, Cf, Ph, Pl, mode, freq, inv);
            }
        }
}

// ===========================================================================
// Tensor-core flash attention (unchanged from R7 — proven).
// ===========================================================================
#define FLT 72
#define FKH 0
#define FKL 4608
#define FVH 9216
#define FVL 13824
#define FSTAGE 18432

__device__ __forceinline__ uint32_t ldscale(const bf16* p) {
    __nv_bfloat162 v = *(const __nv_bfloat162*)p;
    __nv_bfloat162 s = __float2bfloat162_rn(0.125f);
    v = __hmul2(v, s);
    return *(uint32_t*)&v;
}

__global__ __launch_bounds__(256) void flash_bf(
    const bf16* __restrict__ Qh, const bf16* __restrict__ Ql,
    const bf16* __restrict__ Kh, const bf16* __restrict__ Kl,
    const bf16* __restrict__ Vh, const bf16* __restrict__ Vl,
    bf16* __restrict__ Oh, bf16* __restrict__ Ol)
{
    extern __shared__ __align__(16) char smraw[];
    bf16* sm = (bf16*)smraw;
    uint32_t smb = smem_u32(smraw);

    int tid = threadIdx.x, wid = tid >> 5, lane = tid & 31;
    int g = lane >> 2, q = lane & 3;
    int q0 = blockIdx.x * 128, h = blockIdx.y, b = blockIdx.z;
    size_t hb = ((size_t)b * SEQ) * HDIM + (size_t)h * HD;

    uint32_t qh[4][4], ql[4][4];
    {
        int r0 = q0 + wid * 16 + g;
        const bf16* Qph = Qh + hb;
        const bf16* Qpl = Ql + hb;
#pragma unroll
        for (int t = 0; t < 4; t++) {
            qh[t][0] = ldscale(Qph + (size_t)r0 * HDIM + 16 * t + 2 * q);
            qh[t][1] = ldscale(Qph + (size_t)(r0 + 8) * HDIM + 16 * t + 2 * q);
            qh[t][2] = ldscale(Qph + (size_t)r0 * HDIM + 16 * t + 8 + 2 * q);
            qh[t][3] = ldscale(Qph + (size_t)(r0 + 8) * HDIM + 16 * t + 8 + 2 * q);
            ql[t][0] = ldscale(Qpl + (size_t)r0 * HDIM + 16 * t + 2 * q);
            ql[t][1] = ldscale(Qpl + (size_t)(r0 + 8) * HDIM + 16 * t + 2 * q);
            ql[t][2] = ldscale(Qpl + (size_t)r0 * HDIM + 16 * t + 8 + 2 * q);
            ql[t][3] = ldscale(Qpl + (size_t)(r0 + 8) * HDIM + 16 * t + 8 + 2 * q);
        }
    }

    float m[2] = { -1e30f, -1e30f }, l[2] = { 0.f, 0.f };
    float o[8][4];
#pragma unroll
    for (int j = 0; j < 8; j++)
#pragma unroll
        for (int e = 0; e < 4; e++) o[j][e] = 0.f;

    int kr = tid >> 2, kc = (tid & 3) * 16;
    int vn = tid >> 2, vk = (tid & 3) * 16;

    uint4 Khr[2], Klr[2];
    bf16 Vhr[16], Vlr[16];

    {
        const bf16* Kph = Kh + hb + (size_t)kr * HDIM + kc;
        const bf16* Kpl = Kl + hb + (size_t)kr * HDIM + kc;
        Khr[0] = *(const uint4*)Kph; Khr[1] = *(const uint4*)(Kph + 8);
        Klr[0] = *(const uint4*)Kpl; Klr[1] = *(const uint4*)(Kpl + 8);
        const bf16* Vph = Vh + hb + (size_t)vk * HDIM + vn;
        const bf16* Vpl = Vl + hb + (size_t)vk * HDIM + vn;
#pragma unroll
        for (int e = 0; e < 16; e++) {
            Vhr[e] = Vph[(size_t)e * HDIM];
            Vlr[e] = Vpl[(size_t)e * HDIM];
        }
    }

    for (int kt = 0; kt < SEQ / 64; kt++) {
        int s = kt & 1;
        bf16* st = sm + s * FSTAGE;

        *(uint4*)(st + FKH + kr * FLT + kc)     = Khr[0];
        *(uint4*)(st + FKH + kr * FLT + kc + 8) = Khr[1];
        *(uint4*)(st + FKL + kr * FLT + kc)     = Klr[0];
        *(uint4*)(st + FKL + kr * FLT + kc + 8) = Klr[1];
#pragma unroll
        for (int e = 0; e < 16; e++) {
            st[FVH + vn * FLT + vk + e] = Vhr[e];
            st[FVL + vn * FLT + vk + e] = Vlr[e];
        }
        __syncthreads();

        if (kt + 1 < SEQ / 64) {
            const bf16* Kph = Kh + hb + (size_t)((kt + 1) * 64 + kr) * HDIM + kc;
            const bf16* Kpl = Kl + hb + (size_t)((kt + 1) * 64 + kr) * HDIM + kc;
            Khr[0] = *(const uint4*)Kph; Khr[1] = *(const uint4*)(Kph + 8);
            Klr[0] = *(const uint4*)Kpl; Klr[1] = *(const uint4*)(Kpl + 8);
            const bf16* Vph = Vh + hb + (size_t)((kt + 1) * 64 + vk) * HDIM + vn;
            const bf16* Vpl = Vl + hb + (size_t)((kt + 1) * 64 + vk) * HDIM + vn;
#pragma unroll
            for (int e = 0; e < 16; e++) {
                Vhr[e] = Vph[(size_t)e * HDIM];
                Vlr[e] = Vpl[(size_t)e * HDIM];
            }
        }

        uint32_t kbase = smb + (uint32_t)(s * FSTAGE) * 2;

        float sf[8][4];
#pragma unroll
        for (int j = 0; j < 8; j++)
#pragma unroll
            for (int e = 0; e < 4; e++) sf[j][e] = 0.f;

#pragma unroll
        for (int t = 0; t < 4; t++) {
            uint32_t kh[4][4], kl[4][4];
#pragma unroll
            for (int p = 0; p < 4; p++) {
                uint32_t off = (uint32_t)((p * 16 + (lane & 7) + ((lane >> 4) << 3)) * FLT
                                          + t * 16 + (((lane >> 3) & 1) << 3)) * 2;
                ldsm4(kh[p], kbase + FKH * 2 + off);
                ldsm4(kl[p], kbase + FKL * 2 + off);
            }
#pragma unroll
            for (int p = 0; p < 4; p++) {
                mma16816(sf[2 * p],     qh[t], kh[p]);
                mma16816(sf[2 * p],     qh[t], kl[p]);
                mma16816(sf[2 * p],     ql[t], kh[p]);
                mma16816(sf[2 * p + 1], qh[t], kh[p] + 2);
                mma16816(sf[2 * p + 1], qh[t], kl[p] + 2);
                mma16816(sf[2 * p + 1], ql[t], kh[p] + 2);
            }
        }

#pragma unroll
        for (int r = 0; r < 2; r++) {
            float mx = -1e30f;
#pragma unroll
            for (int j = 0; j < 8; j++)
                mx = fmaxf(mx, fmaxf(sf[j][2 * r], sf[j][2 * r + 1]));
            mx = fmaxf(mx, __shfl_xor_sync(0xffffffffu, mx, 1));
            mx = fmaxf(mx, __shfl_xor_sync(0xffffffffu, mx, 2));
            float mn = fmaxf(m[r], mx);
            float cf = __expf(m[r] - mn);
            m[r] = mn;
            float ls = 0.f;
#pragma unroll
            for (int j = 0; j < 8; j++) {
                float p0 = __expf(sf[j][2 * r]     - mn);
                float p1 = __expf(sf[j][2 * r + 1] - mn);
                sf[j][2 * r] = p0; sf[j][2 * r + 1] = p1;
                ls += p0 + p1;
            }
            ls += __shfl_xor_sync(0xffffffffu, ls, 1);
            ls += __shfl_xor_sync(0xffffffffu, ls, 2);
            l[r] = l[r] * cf + ls;
#pragma unroll
            for (int j = 0; j < 8; j++) {
                o[j][2 * r] *= cf; o[j][2 * r + 1] *= cf;
            }
        }

#pragma unroll
        for (int t = 0; t < 4; t++) {
            uint32_t pa_h[4], pa_l[4];
            cvt2(sf[2 * t][0],     sf[2 * t][1],     &pa_h[0], &pa_l[0]);
            cvt2(sf[2 * t][2],     sf[2 * t][3],     &pa_h[1], &pa_l[1]);
            cvt2(sf[2 * t + 1][0], sf[2 * t + 1][1], &pa_h[2], &pa_l[2]);
            cvt2(sf[2 * t + 1][2], sf[2 * t + 1][3], &pa_h[3], &pa_l[3]);
#pragma unroll
            for (int p = 0; p < 4; p++) {
                uint32_t off = (uint32_t)((p * 16 + (lane & 7) + ((lane >> 4) << 3)) * FLT
                                          + t * 16 + (((lane >> 3) & 1) << 3)) * 2;
                uint32_t vh[4], vl[4];
                ldsm4(vh, kbase + FVH * 2 + off);
                ldsm4(vl, kbase + FVL * 2 + off);
                mma16816(o[2 * p],     pa_h, vh);
                mma16816(o[2 * p],     pa_h, vl);
                mma16816(o[2 * p],     pa_l, vh);
                mma16816(o[2 * p + 1], pa_h, vh + 2);
                mma16816(o[2 * p + 1], pa_h, vl + 2);
                mma16816(o[2 * p + 1], pa_l, vh + 2);
            }
        }
    }

    {
        int r0 = q0 + wid * 16 + g;
#pragma unroll
        for (int r = 0; r < 2; r++) {
            float invl = 1.f / l[r];
            int row = r0 + r * 8;
#pragma unroll
            for (int j = 0; j < 8; j++) {
                float v0 = o[j][2 * r] * invl;
                float v1 = o[j][2 * r + 1] * invl;
                uint32_t ph, pl;
                cvt2(v0, v1, &ph, &pl);
                size_t off = hb + (size_t)row * HDIM + j * 8 + 2 * q;
                *(uint32_t*)(Oh + off) = ph;
                *(uint32_t*)(Ol + off) = pl;
            }
        }
    }
}

// ===========================================================================
extern "C" void kernel_launch(void* const* d_in, const int* in_sizes, int n_in,
                              void* d_out, int out_size)
{
    const float* X   = (const float*)d_in[0];
    const float* Wq  = (const float*)d_in[1];
    const float* bq  = (const float*)d_in[2];
    const float* Wk  = (const float*)d_in[3];
    const float* bk  = (const float*)d_in[4];
    const float* Wv  = (const float*)d_in[5];
    const float* bv  = (const float*)d_in[6];
    const float* Wo  = (const float*)d_in[7];
    const float* bo  = (const float*)d_in[8];
    const float* qta = (const float*)d_in[9];
    const float* qtb = (const float*)d_in[10];
    const float* kta = (const float*)d_in[11];
    const float* ktb = (const float*)d_in[12];
    const float* cpl = (const float*)d_in[13];

    float* f32 = nullptr;
    bf16* bf = nullptr;
    cudaGetSymbolAddress((void**)&f32, g_f32);
    cudaGetSymbolAddress((void**)&bf, g_bf);
    float* Qf = f32;
    float* Kf = f32 + 4194304;

    const int GS  = 2 * ST_ELEMS * 2;    // 61440 B
    const int GS2 = 2 * ST2_ELEMS * 2;   // 81920 B
    const int FS  = 2 * FSTAGE * 2;      // 73728 B
    cudaFuncSetAttribute(gemm_bf,  cudaFuncAttributeMaxDynamicSharedMemorySize, GS);
    cudaFuncSetAttribute(gemm_bf2, cudaFuncAttributeMaxDynamicSharedMemorySize, GS2);
    cudaFuncSetAttribute(flash_bf, cudaFuncAttributeMaxDynamicSharedMemorySize, FS);

    const float PI2 = 6.28318530717958647692f;

    // ---- pre-convert
    split_f32<<<4096, 256>>>(X, bf + O_XH, bf + O_XL, 1048576);
    dim3 gW(32, 32);
    transpose_split<<<gW, 256>>>(Wq, bf + O_WT + 0u,       bf + O_WT + 1048576u, 1024, 1024);
    transpose_split<<<gW, 256>>>(Wk, bf + O_WT + 2097152u, bf + O_WT + 3145728u, 1024, 1024);
    transpose_split<<<gW, 256>>>(Wv, bf + O_WT + 4194304u, bf + O_WT + 5242880u, 1024, 1024);
    transpose_split<<<gW, 256>>>(Wo, bf + O_WT + 6291456u, bf + O_WT + 7340032u, 1024, 1024);
    dim3 gTA(2, 32);
    transpose_split<<<gTA, 256>>>(qta,          bf + O_TA + 0u,      bf + O_TA + 65536u,  1024, 64);
    transpose_split<<<gTA, 256>>>(qta + 65536,  bf + O_TA + 131072u, bf + O_TA + 196608u, 1024, 64);
    transpose_split<<<gTA, 256>>>(kta,          bf + O_TA + 262144u, bf + O_TA + 327680u, 1024, 64);
    transpose_split<<<gTA, 256>>>(kta + 65536,  bf + O_TA + 393216u, bf + O_TA + 458752u, 1024, 64);
    dim3 gTB(32, 2);
    transpose_split<<<gTB, 256>>>(qtb,          bf + O_TB + 0u,      bf + O_TB + 65536u,  64, 1024);
    transpose_split<<<gTB, 256>>>(qtb + 65536,  bf + O_TB + 131072u, bf + O_TB + 196608u, 64, 1024);
    transpose_split<<<gTB, 256>>>(ktb,          bf + O_TB + 262144u, bf + O_TB + 327680u, 64, 1024);
    transpose_split<<<gTB, 256>>>(ktb + 65536,  bf + O_TB + 393216u, bf + O_TB + 458752u, 64, 1024);

    dim3 gBig2(8, 32);       // 128x128 tiles over 4096x1024
    dim3 gLow(1, 32, 2);

    // ---- QKV projections (wide tiles)
    gemm_bf2<<<gBig2, 512, GS2>>>(bf + O_XH, bf + O_XL,
                                  bf + O_WT + 0u, bf + O_WT + 1048576u,
                                  bq, nullptr, Qf, bf + O_QBH, bf + O_QBL,
                                  1024, 1024, 6, 0.f, 0.f);
    gemm_bf2<<<gBig2, 512, GS2>>>(bf + O_XH, bf + O_XL,
                                  bf + O_WT + 2097152u, bf + O_WT + 3145728u,
                                  bk, nullptr, Kf, bf + O_KBH, bf + O_KBL,
                                  1024, 1024, 6, 0.f, 0.f);
    gemm_bf2<<<gBig2, 512, GS2>>>(bf + O_XH, bf + O_XL,
                                  bf + O_WT + 4194304u, bf + O_WT + 5242880u,
                                  bv, nullptr, nullptr, bf + O_VBH, bf + O_VBL,
                                  1024, 1024, 5, 0.f, 0.f);

    // ---- Torsion Q
    gemm_bf<<<gLow, 256, GS>>>(bf + O_QBH, bf + O_QBL,
                               bf + O_TA + 0u, bf + O_TA + 65536u,
                               nullptr, nullptr, nullptr,
                               bf + O_LB, bf + O_LB + 262144u,
                               1024, 64, 2, 0.f, 0.f, 131072, 524288);
    gemm_bf2<<<gBig2, 512, GS2>>>(bf + O_LB, bf + O_LB + 262144u,
                                  bf + O_TB + 0u, bf + O_TB + 65536u,
                                  nullptr, cpl, Qf, nullptr, nullptr,
                                  64, 1024, 1, PI2, 1.0f);
    gemm_bf2<<<gBig2, 512, GS2>>>(bf + O_LB + 524288u, bf + O_LB + 786432u,
                                  bf + O_TB + 131072u, bf + O_TB + 196608u,
                                  nullptr, cpl, Qf, bf + O_QBH, bf + O_QBL,
                                  64, 1024, 4, 2.f * PI2, 0.5f);

    // ---- Torsion K
    gemm_bf<<<gLow, 256, GS>>>(bf + O_KBH, bf + O_KBL,
                               bf + O_TA + 262144u, bf + O_TA + 327680u,
                               nullptr, nullptr, nullptr,
                               bf + O_LB, bf + O_LB + 262144u,
                               1024, 64, 2, 0.f, 0.f, 131072, 524288);
    gemm_bf2<<<gBig2, 512, GS2>>>(bf + O_LB, bf + O_LB + 262144u,
                                  bf + O_TB + 262144u, bf + O_TB + 327680u,
                                  nullptr, cpl, Kf, nullptr, nullptr,
                                  64, 1024, 1, PI2, 1.0f);
    gemm_bf2<<<gBig2, 512, GS2>>>(bf + O_LB + 524288u, bf + O_LB + 786432u,
                                  bf + O_TB + 393216u, bf + O_TB + 458752u,
                                  nullptr, cpl, Kf, bf + O_KBH, bf + O_KBL,
                                  64, 1024, 4, 2.f * PI2, 0.5f);

    // ---- Flash attention
    dim3 gAtt(SEQ / 128, NHEAD, BATCH);
    flash_bf<<<gAtt, 256, FS>>>(bf + O_QBH, bf + O_QBL,
                                bf + O_KBH, bf + O_KBL,
                                bf + O_VBH, bf + O_VBL,
                                bf + O_AOH, bf + O_AOL);

    // ---- Output projection -> d_out
    gemm_bf2<<<gBig2, 512, GS2>>>(bf + O_AOH, bf + O_AOL,
                                  bf + O_WT + 6291456u, bf + O_WT + 7340032u,
                                  bo, nullptr, (float*)d_out, nullptr, nullptr,
                                  1024, 1024, 0, 0.f, 0.f);
}

// round 10
// speedup vs baseline: 2.7565x; 1.1026x over previous
#include <cuda_runtime.h>
#include <cuda_bf16.h>
#include <math.h>
#include <stdint.h>

#define MTOT 4096
#define HDIM 1024
#define NHEAD 16
#define HD 64
#define SEQ 2048
#define BATCH 2

typedef __nv_bfloat16 bf16;

// ---------------- scratch ----------------
__device__ float g_f32[2u * 4194304u];          // Qf, Kf
#define O_XH   0u
#define O_XL   4194304u
#define O_WT   8388608u      // (WqTh,WqTl),(WkTh,WkTl),(WvTh,WvTl),(WoTh,WoTl): h@z*2097152, l=h+1048576
#define O_TA   16777216u     // 4 slots: h@z*131072, l=h+65536  (qta0,qta1,kta0,kta1)
#define O_TB   17301504u     // 4 slots: h@z*131072, l=h+65536  (qtb0,qtb1,ktb0,ktb1)
#define O_QBH  17825792u     // Q/K/V planes: h@O_QBH+z*8388608, l=h+4194304
#define O_VBH  34603008u
#define O_AOH  42991616u
#define O_AOL  47185920u
#define O_LB   51380224u     // 4 slots: h@z*524288, l=h+262144
#define O_VTH  53477376u     // V transposed [bh][d][s]
#define O_VTL  57671680u
__device__ bf16 g_bf[61865984u];

// ---------------- helpers ----------------
__device__ __forceinline__ uint32_t smem_u32(const void* p) {
    uint32_t a;
    asm("{ .reg .u64 t; cvta.to.shared.u64 t, %1; cvt.u32.u64 %0, t; }"
        : "=r"(a) : "l"(p));
    return a;
}
__device__ __forceinline__ void ldsm4(uint32_t* r, uint32_t addr) {
    asm volatile("ldmatrix.sync.aligned.m8n8.x4.shared.b16 {%0,%1,%2,%3}, [%4];"
                 : "=r"(r[0]), "=r"(r[1]), "=r"(r[2]), "=r"(r[3]) : "r"(addr));
}
__device__ __forceinline__ void mma16816(float* c, const uint32_t* a, const uint32_t* b) {
    asm volatile(
        "mma.sync.aligned.m16n8k16.row.col.f32.bf16.bf16.f32 "
        "{%0,%1,%2,%3}, {%4,%5,%6,%7}, {%8,%9}, {%0,%1,%2,%3};"
        : "+f"(c[0]), "+f"(c[1]), "+f"(c[2]), "+f"(c[3])
        : "r"(a[0]), "r"(a[1]), "r"(a[2]), "r"(a[3]), "r"(b[0]), "r"(b[1]));
}
__device__ __forceinline__ void cvt2(float a, float b, uint32_t* hi, uint32_t* lo) {
    __nv_bfloat162 h = __floats2bfloat162_rn(a, b);
    float2 hf = __bfloat1622float2(h);
    __nv_bfloat162 l = __floats2bfloat162_rn(a - hf.x, b - hf.y);
    *hi = *(uint32_t*)&h;
    *lo = *(uint32_t*)&l;
}
__device__ __forceinline__ void cp16(uint32_t s, const void* g) {
    asm volatile("cp.async.cg.shared.global [%0], [%1], 16;" :: "r"(s), "l"(g));
}

// ---------------- pre-conversion kernels ----------------
__global__ __launch_bounds__(256) void split_f32(
    const float* __restrict__ in, bf16* __restrict__ oh, bf16* __restrict__ ol, int n4)
{
    int i = blockIdx.x * 256 + threadIdx.x;
    if (i < n4) {
        float4 f = ((const float4*)in)[i];
        uint2 h, l;
        cvt2(f.x, f.y, &h.x, &l.x);
        cvt2(f.z, f.w, &h.y, &l.y);
        ((uint2*)oh)[i] = h;
        ((uint2*)ol)[i] = l;
    }
}

// fused 4-input transpose+split: in[z] is [M][N] fp32 -> out slot z is [N][M] hi/lo
__global__ __launch_bounds__(256) void transpose_split4(
    const float* __restrict__ i0, const float* __restrict__ i1,
    const float* __restrict__ i2, const float* __restrict__ i3,
    bf16* __restrict__ oh, bf16* __restrict__ ol,
    int M, int N, int zsO)
{
    __shared__ float t[32][33];
    int z = blockIdx.z;
    const float* in = (z == 0) ? i0 : (z == 1) ? i1 : (z == 2) ? i2 : i3;
    oh += (size_t)z * zsO; ol += (size_t)z * zsO;
    int bx = blockIdx.x * 32;
    int by = blockIdx.y * 32;
    int tx = threadIdx.x & 31, ty = threadIdx.x >> 5;
#pragma unroll
    for (int i = 0; i < 32; i += 8)
        t[ty + i][tx] = in[(size_t)(by + ty + i) * N + bx + tx];
    __syncthreads();
#pragma unroll
    for (int i = 0; i < 32; i += 8) {
        float v = t[tx][ty + i];
        bf16 h = __float2bfloat16_rn(v);
        bf16 l = __float2bfloat16_rn(v - __bfloat162float(h));
        size_t o = (size_t)(bx + ty + i) * M + by + tx;
        oh[o] = h;
        ol[o] = l;
    }
}

// V planes [tok=4096][1024] -> VT planes [bh=32][d=64][s=2048]
__global__ __launch_bounds__(256) void vt_transpose(
    const bf16* __restrict__ Vh, const bf16* __restrict__ Vl,
    bf16* __restrict__ Oh, bf16* __restrict__ Ol)
{
    __shared__ bf16 th[32][33], tl[32][33];
    int z = blockIdx.z;               // b*16 + h
    int b = z >> 4, h = z & 15;
    int d0 = blockIdx.x * 32, s0 = blockIdx.y * 32;
    int tx = threadIdx.x & 31, ty = threadIdx.x >> 5;
#pragma unroll
    for (int i = 0; i < 32; i += 8) {
        size_t off = (size_t)(b * 2048 + s0 + ty + i) * 1024 + h * 64 + d0 + tx;
        th[ty + i][tx] = Vh[off];
        tl[ty + i][tx] = Vl[off];
    }
    __syncthreads();
#pragma unroll
    for (int i = 0; i < 32; i += 8) {
        size_t off = ((size_t)z * 64 + d0 + ty + i) * 2048 + s0 + tx;
        Oh[off] = th[tx][ty + i];
        Ol[off] = tl[tx][ty + i];
    }
}

// ---------------- shared epilogue ----------------
__device__ __forceinline__ void epilogue_frag(
    float d0, float d1, size_t off, int col,
    const float* __restrict__ bias, float sg,
    float* __restrict__ Cf, bf16* __restrict__ Ph, bf16* __restrict__ Pl,
    int mode, float freq, float inv)
{
    if (mode == 0) {
        float2 o = { d0 + bias[col], d1 + bias[col + 1] };
        *(float2*)(Cf + off) = o;
    } else if (mode == 6) {
        float b0 = d0 + bias[col], b1 = d1 + bias[col + 1];
        float2 o = { b0, b1 };
        *(float2*)(Cf + off) = o;
        uint32_t ph, pl;
        cvt2(b0, b1, &ph, &pl);
        *(uint32_t*)(Ph + off) = ph;
        *(uint32_t*)(Pl + off) = pl;
    } else if (mode == 5) {
        float b0 = d0 + bias[col], b1 = d1 + bias[col + 1];
        uint32_t ph, pl;
        cvt2(b0, b1, &ph, &pl);
        *(uint32_t*)(Ph + off) = ph;
        *(uint32_t*)(Pl + off) = pl;
    } else if (mode == 2) {
        uint32_t ph, pl;
        cvt2(d0, d1, &ph, &pl);
        *(uint32_t*)(Ph + off) = ph;
        *(uint32_t*)(Pl + off) = pl;
    } else if (mode == 1) {
        float2 cv = *(float2*)(Cf + off);
        cv.x += sg * sinf(freq * d0) * d0 * inv;
        cv.y += sg * sinf(freq * d1) * d1 * inv;
        *(float2*)(Cf + off) = cv;
    } else {   // mode 4
        float2 cv = *(float2*)(Cf + off);
        float t0 = cv.x + sg * sinf(freq * d0) * d0 * inv;
        float t1 = cv.y + sg * sinf(freq * d1) * d1 * inv;
        uint32_t ph, pl;
        cvt2(t0, t1, &ph, &pl);
        *(uint32_t*)(Ph + off) = ph;
        *(uint32_t*)(Pl + off) = pl;
    }
}

// ===========================================================================
// gemm_low: 128x64 tile, 256 thr. Fused 4-way over z:
//   z: 0,1 -> A = Q planes; 2,3 -> A = K planes  (stride 8388608 per half)
//   B = TA slot z (stride 131072); out = LB slot z (stride 524288). mode 2.
// ===========================================================================
#define LDT 40
#define ST_AH 0
#define ST_AL 5120
#define ST_BH 10240
#define ST_BL 12800
#define ST_ELEMS 15360

__global__ __launch_bounds__(256) void gemm_low(
    const bf16* __restrict__ QBh, const bf16* __restrict__ TAh,
    bf16* __restrict__ LBh)
{
    extern __shared__ __align__(16) char smraw[];
    bf16* sm = (bf16*)smraw;
    uint32_t smb = smem_u32(smraw);

    const int K = 1024, N = 64;
    int z = blockIdx.z;
    const bf16* Ah = QBh + (size_t)(z >> 1) * 8388608u;
    const bf16* Al = Ah + 4194304u;
    const bf16* Bh = TAh + (size_t)z * 131072u;
    const bf16* Bl = Bh + 65536u;
    bf16* Ph = LBh + (size_t)z * 524288u;
    bf16* Pl = Ph + 262144u;

    int tid = threadIdx.x, wid = tid >> 5, lane = tid & 31;
    int bm = blockIdx.y * 128, bn = 0;
    int wm = (wid & 3) * 32, wn = (wid >> 2) * 32;

    float acc[2][4][4];
#pragma unroll
    for (int i = 0; i < 2; i++)
#pragma unroll
        for (int j = 0; j < 4; j++)
#pragma unroll
            for (int e = 0; e < 4; e++) acc[i][j][e] = 0.f;

    int ar = tid >> 1, ac0 = (tid & 1) * 16;
    int bnn = tid >> 2, bk0 = (tid & 3) * 8;

    uint4 Avh[2], Avl[2], Bvh, Bvl;
    int nchunks = K >> 5;

    {
        const bf16* Aph = Ah + (size_t)(bm + ar) * K + ac0;
        const bf16* Apl = Al + (size_t)(bm + ar) * K + ac0;
        Avh[0] = *(const uint4*)Aph; Avh[1] = *(const uint4*)(Aph + 8);
        Avl[0] = *(const uint4*)Apl; Avl[1] = *(const uint4*)(Apl + 8);
        Bvh = *(const uint4*)(Bh + (size_t)bnn * K + bk0);
        Bvl = *(const uint4*)(Bl + (size_t)bnn * K + bk0);
    }

    for (int c = 0; c < nchunks; c++) {
        int s = c & 1;
        bf16* st = sm + s * ST_ELEMS;

        *(uint4*)(st + ST_AH + ar * LDT + ac0)     = Avh[0];
        *(uint4*)(st + ST_AH + ar * LDT + ac0 + 8) = Avh[1];
        *(uint4*)(st + ST_AL + ar * LDT + ac0)     = Avl[0];
        *(uint4*)(st + ST_AL + ar * LDT + ac0 + 8) = Avl[1];
        *(uint4*)(st + ST_BH + bnn * LDT + bk0)    = Bvh;
        *(uint4*)(st + ST_BL + bnn * LDT + bk0)    = Bvl;
        __syncthreads();

        if (c + 1 < nchunks) {
            const bf16* Aph = Ah + (size_t)(bm + ar) * K + (c + 1) * 32 + ac0;
            const bf16* Apl = Al + (size_t)(bm + ar) * K + (c + 1) * 32 + ac0;
            Avh[0] = *(const uint4*)Aph; Avh[1] = *(const uint4*)(Aph + 8);
            Avl[0] = *(const uint4*)Apl; Avl[1] = *(const uint4*)(Apl + 8);
            Bvh = *(const uint4*)(Bh + (size_t)bnn * K + (c + 1) * 32 + bk0);
            Bvl = *(const uint4*)(Bl + (size_t)bnn * K + (c + 1) * 32 + bk0);
        }

        uint32_t stA  = smb + (uint32_t)(s * ST_ELEMS) * 2;
        uint32_t stAl = stA + ST_AL * 2;
        uint32_t stBh = stA + ST_BH * 2;
        uint32_t stBl = stA + ST_BL * 2;

#pragma unroll
        for (int kk = 0; kk < 32; kk += 16) {
            uint32_t ah[2][4], al[2][4], bh[4][2], bl[4][2];
#pragma unroll
            for (int i = 0; i < 2; i++) {
                uint32_t roff = (uint32_t)((wm + i * 16 + (lane & 15)) * LDT
                                           + kk + ((lane >> 4) << 3)) * 2;
                ldsm4(ah[i], stA + roff);
                ldsm4(al[i], stAl + roff);
            }
#pragma unroll
            for (int p = 0; p < 2; p++) {
                uint32_t noff = (uint32_t)((wn + p * 16 + (lane & 7) + ((lane >> 4) << 3)) * LDT
                                           + kk + (((lane >> 3) & 1) << 3)) * 2;
                uint32_t r[4];
                ldsm4(r, stBh + noff);
                bh[p * 2][0] = r[0]; bh[p * 2][1] = r[1];
                bh[p * 2 + 1][0] = r[2]; bh[p * 2 + 1][1] = r[3];
                ldsm4(r, stBl + noff);
                bl[p * 2][0] = r[0]; bl[p * 2][1] = r[1];
                bl[p * 2 + 1][0] = r[2]; bl[p * 2 + 1][1] = r[3];
            }
#pragma unroll
            for (int i = 0; i < 2; i++)
#pragma unroll
                for (int j = 0; j < 4; j++) {
                    mma16816(acc[i][j], ah[i], bh[j]);
                    mma16816(acc[i][j], ah[i], bl[j]);
                    mma16816(acc[i][j], al[i], bh[j]);
                }
        }
        __syncthreads();
    }

    int g = lane >> 2, q = lane & 3;
#pragma unroll
    for (int i = 0; i < 2; i++)
#pragma unroll
        for (int j = 0; j < 4; j++) {
            int row = bm + wm + i * 16 + g;
            int col = bn + wn + j * 8 + q * 2;
#pragma unroll
            for (int h = 0; h < 2; h++) {
                size_t off = (size_t)(row + h * 8) * N + col;
                epilogue_frag(acc[i][j][h * 2], acc[i][j][h * 2 + 1], off, col,
                              nullptr, 0.f, nullptr, Ph, Pl, 2, 0.f, 0.f);
            }
        }
}

// ===========================================================================
// gemm_bf2: 128x128 tile, 512 thr, z-fused.
// Per z: A += z*zsA (h and l), B += z*zsB, Cf += z*zsC (valid z<cfmax),
//        P += z*zsP; bias = {b0,b1,b2}[z]; mode 6 degrades to 5 for z>=cfmax.
// ===========================================================================
#define ST2_AH 0
#define ST2_AL 5120
#define ST2_BH 10240
#define ST2_BL 15360
#define ST2_ELEMS 20480

__global__ __launch_bounds__(512, 1) void gemm_bf2(
    const bf16* __restrict__ Ah0, const bf16* __restrict__ Al0, int zsA,
    const bf16* __restrict__ Bh0, const bf16* __restrict__ Bl0, int zsB,
    const float* __restrict__ b0, const float* __restrict__ b1, const float* __restrict__ b2,
    const float* __restrict__ coupling,
    float* __restrict__ Cf0, int zsC, int cfmax,
    bf16* __restrict__ Ph0, bf16* __restrict__ Pl0, int zsP,
    int K, int N, int mode, float freq, float inv)
{
    extern __shared__ __align__(16) char smraw[];
    bf16* sm = (bf16*)smraw;
    uint32_t smb = smem_u32(smraw);

    int z = blockIdx.z;
    const bf16* Ah = Ah0 + (size_t)z * zsA;
    const bf16* Al = Al0 + (size_t)z * zsA;
    const bf16* Bh = Bh0 + (size_t)z * zsB;
    const bf16* Bl = Bl0 + (size_t)z * zsB;
    float* Cf = (z < cfmax) ? (Cf0 + (size_t)z * zsC) : nullptr;
    bf16* Ph = Ph0 + (size_t)z * zsP;
    bf16* Pl = Pl0 + (size_t)z * zsP;
    const float* bias = (z == 0) ? b0 : (z == 1) ? b1 : b2;
    int lmode = (mode == 6 && z >= cfmax) ? 5 : mode;

    int tid = threadIdx.x, wid = tid >> 5, lane = tid & 31;
    int bm = blockIdx.y * 128, bn = blockIdx.x * 128;
    int wm = (wid & 3) * 32, wn = (wid >> 2) * 32;

    float acc[2][4][4];
#pragma unroll
    for (int i = 0; i < 2; i++)
#pragma unroll
        for (int j = 0; j < 4; j++)
#pragma unroll
            for (int e = 0; e < 4; e++) acc[i][j][e] = 0.f;

    int ar = tid >> 2, ac0 = (tid & 3) * 8;
    int bnn = tid >> 2, bk0 = (tid & 3) * 8;

    uint4 Avh, Avl, Bvh, Bvl;
    int nchunks = K >> 5;

    {
        Avh = *(const uint4*)(Ah + (size_t)(bm + ar) * K + ac0);
        Avl = *(const uint4*)(Al + (size_t)(bm + ar) * K + ac0);
        Bvh = *(const uint4*)(Bh + (size_t)(bn + bnn) * K + bk0);
        Bvl = *(const uint4*)(Bl + (size_t)(bn + bnn) * K + bk0);
    }

    for (int c = 0; c < nchunks; c++) {
        int s = c & 1;
        bf16* st = sm + s * ST2_ELEMS;

        *(uint4*)(st + ST2_AH + ar * LDT + ac0)  = Avh;
        *(uint4*)(st + ST2_AL + ar * LDT + ac0)  = Avl;
        *(uint4*)(st + ST2_BH + bnn * LDT + bk0) = Bvh;
        *(uint4*)(st + ST2_BL + bnn * LDT + bk0) = Bvl;
        __syncthreads();

        if (c + 1 < nchunks) {
            Avh = *(const uint4*)(Ah + (size_t)(bm + ar) * K + (c + 1) * 32 + ac0);
            Avl = *(const uint4*)(Al + (size_t)(bm + ar) * K + (c + 1) * 32 + ac0);
            Bvh = *(const uint4*)(Bh + (size_t)(bn + bnn) * K + (c + 1) * 32 + bk0);
            Bvl = *(const uint4*)(Bl + (size_t)(bn + bnn) * K + (c + 1) * 32 + bk0);
        }

        uint32_t stA  = smb + (uint32_t)(s * ST2_ELEMS) * 2;
        uint32_t stAl = stA + ST2_AL * 2;
        uint32_t stBh = stA + ST2_BH * 2;
        uint32_t stBl = stA + ST2_BL * 2;

#pragma unroll
        for (int kk = 0; kk < 32; kk += 16) {
            uint32_t ah[2][4], al[2][4], bh[4][2], bl[4][2];
#pragma unroll
            for (int i = 0; i < 2; i++) {
                uint32_t roff = (uint32_t)((wm + i * 16 + (lane & 15)) * LDT
                                           + kk + ((lane >> 4) << 3)) * 2;
                ldsm4(ah[i], stA + roff);
                ldsm4(al[i], stAl + roff);
            }
#pragma unroll
            for (int p = 0; p < 2; p++) {
                uint32_t noff = (uint32_t)((wn + p * 16 + (lane & 7) + ((lane >> 4) << 3)) * LDT
                                           + kk + (((lane >> 3) & 1) << 3)) * 2;
                uint32_t r[4];
                ldsm4(r, stBh + noff);
                bh[p * 2][0] = r[0]; bh[p * 2][1] = r[1];
                bh[p * 2 + 1][0] = r[2]; bh[p * 2 + 1][1] = r[3];
                ldsm4(r, stBl + noff);
                bl[p * 2][0] = r[0]; bl[p * 2][1] = r[1];
                bl[p * 2 + 1][0] = r[2]; bl[p * 2 + 1][1] = r[3];
            }
#pragma unroll
            for (int i = 0; i < 2; i++)
#pragma unroll
                for (int j = 0; j < 4; j++) {
                    mma16816(acc[i][j], ah[i], bh[j]);
                    mma16816(acc[i][j], ah[i], bl[j]);
                    mma16816(acc[i][j], al[i], bh[j]);
                }
        }
        __syncthreads();
    }

    int g = lane >> 2, q = lane & 3;
    float sg = 0.f;
    if (lmode == 1 || lmode == 4) sg = 1.f / (1.f + __expf(-(*coupling)));

#pragma unroll
    for (int i = 0; i < 2; i++)
#pragma unroll
        for (int j = 0; j < 4; j++) {
            int row = bm + wm + i * 16 + g;
            int col = bn + wn + j * 8 + q * 2;
#pragma unroll
            for (int h = 0; h < 2; h++) {
                size_t off = (size_t)(row + h * 8) * N + col;
                epilogue_frag(acc[i][j][h * 2], acc[i][j][h * 2 + 1], off, col,
                              bias, sg, Cf, Ph, Pl, lmode, freq, inv);
            }
        }
}

// ===========================================================================
// Flash attention: cp.async K/V staging (V from pre-transposed VT planes),
// occupancy 2 via __launch_bounds__(256, 2).
// ===========================================================================
#define FLT 72
#define FKH 0
#define FKL 4608
#define FVH 9216
#define FVL 13824
#define FSTAGE 18432

__device__ __forceinline__ uint32_t ldscale(const bf16* p) {
    __nv_bfloat162 v = *(const __nv_bfloat162*)p;
    __nv_bfloat162 s = __float2bfloat162_rn(0.125f);
    v = __hmul2(v, s);
    return *(uint32_t*)&v;
}

__device__ __forceinline__ void flash_issue(
    const bf16* __restrict__ Kh, const bf16* __restrict__ Kl,
    const bf16* __restrict__ VTh, const bf16* __restrict__ VTl,
    size_t hb, size_t vtb, int kt64, uint32_t sb, int tid)
{
#pragma unroll
    for (int r = 0; r < 2; r++) {
        int idx = tid + r * 256;
        int row = idx >> 3, c8 = (idx & 7) << 3;
        cp16(sb + (uint32_t)(FKH + row * FLT + c8) * 2,
             Kh + hb + (size_t)(kt64 + row) * HDIM + c8);
        cp16(sb + (uint32_t)(FKL + row * FLT + c8) * 2,
             Kl + hb + (size_t)(kt64 + row) * HDIM + c8);
        cp16(sb + (uint32_t)(FVH + row * FLT + c8) * 2,
             VTh + vtb + (size_t)row * SEQ + kt64 + c8);
        cp16(sb + (uint32_t)(FVL + row * FLT + c8) * 2,
             VTl + vtb + (size_t)row * SEQ + kt64 + c8);
    }
    asm volatile("cp.async.commit_group;");
}

__global__ __launch_bounds__(256, 2) void flash_bf(
    const bf16* __restrict__ Qh, const bf16* __restrict__ Ql,
    const bf16* __restrict__ Kh, const bf16* __restrict__ Kl,
    const bf16* __restrict__ VTh, const bf16* __restrict__ VTl,
    bf16* __restrict__ Oh, bf16* __restrict__ Ol)
{
    extern __shared__ __align__(16) char smraw[];
    uint32_t smb = smem_u32(smraw);

    int tid = threadIdx.x, wid = tid >> 5, lane = tid & 31;
    int g = lane >> 2, q = lane & 3;
    int q0 = blockIdx.x * 128, h = blockIdx.y, b = blockIdx.z;
    size_t hb = ((size_t)b * SEQ) * HDIM + (size_t)h * HD;
    size_t vtb = (size_t)(b * 16 + h) * 131072u;   // [bh][64][2048]

    uint32_t qh[4][4], ql[4][4];
    {
        int r0 = q0 + wid * 16 + g;
        const bf16* Qph = Qh + hb;
        const bf16* Qpl = Ql + hb;
#pragma unroll
        for (int t = 0; t < 4; t++) {
            qh[t][0] = ldscale(Qph + (size_t)r0 * HDIM + 16 * t + 2 * q);
            qh[t][1] = ldscale(Qph + (size_t)(r0 + 8) * HDIM + 16 * t + 2 * q);
            qh[t][2] = ldscale(Qph + (size_t)r0 * HDIM + 16 * t + 8 + 2 * q);
            qh[t][3] = ldscale(Qph + (size_t)(r0 + 8) * HDIM + 16 * t + 8 + 2 * q);
            ql[t][0] = ldscale(Qpl + (size_t)r0 * HDIM + 16 * t + 2 * q);
            ql[t][1] = ldscale(Qpl + (size_t)(r0 + 8) * HDIM + 16 * t + 2 * q);
            ql[t][2] = ldscale(Qpl + (size_t)r0 * HDIM + 16 * t + 8 + 2 * q);
            ql[t][3] = ldscale(Qpl + (size_t)(r0 + 8) * HDIM + 16 * t + 8 + 2 * q);
        }
    }

    float m[2] = { -1e30f, -1e30f }, l[2] = { 0.f, 0.f };
    float o[8][4];
#pragma unroll
    for (int j = 0; j < 8; j++)
#pragma unroll
        for (int e = 0; e < 4; e++) o[j][e] = 0.f;

    flash_issue(Kh, Kl, VTh, VTl, hb, vtb, 0, smb, tid);

    for (int kt = 0; kt < SEQ / 64; kt++) {
        int s = kt & 1;
        asm volatile("cp.async.wait_group 0;" ::: "memory");
        __syncthreads();
        if (kt + 1 < SEQ / 64)
            flash_issue(Kh, Kl, VTh, VTl, hb, vtb, (kt + 1) * 64,
                        smb + (uint32_t)((s ^ 1) * FSTAGE) * 2, tid);

        uint32_t kbase = smb + (uint32_t)(s * FSTAGE) * 2;

        float sf[8][4];
#pragma unroll
        for (int j = 0; j < 8; j++)
#pragma unroll
            for (int e = 0; e < 4; e++) sf[j][e] = 0.f;

#pragma unroll
        for (int t = 0; t < 4; t++) {
#pragma unroll
            for (int p = 0; p < 4; p++) {
                uint32_t off = (uint32_t)((p * 16 + (lane & 7) + ((lane >> 4) << 3)) * FLT
                                          + t * 16 + (((lane >> 3) & 1) << 3)) * 2;
                uint32_t kh[4], kl[4];
                ldsm4(kh, kbase + FKH * 2 + off);
                ldsm4(kl, kbase + FKL * 2 + off);
                mma16816(sf[2 * p],     qh[t], kh);
                mma16816(sf[2 * p],     qh[t], kl);
                mma16816(sf[2 * p],     ql[t], kh);
                mma16816(sf[2 * p + 1], qh[t], kh + 2);
                mma16816(sf[2 * p + 1], qh[t], kl + 2);
                mma16816(sf[2 * p + 1], ql[t], kh + 2);
            }
        }

#pragma unroll
        for (int r = 0; r < 2; r++) {
            float mx = -1e30f;
#pragma unroll
            for (int j = 0; j < 8; j++)
                mx = fmaxf(mx, fmaxf(sf[j][2 * r], sf[j][2 * r + 1]));
            mx = fmaxf(mx, __shfl_xor_sync(0xffffffffu, mx, 1));
            mx = fmaxf(mx, __shfl_xor_sync(0xffffffffu, mx, 2));
            float mn = fmaxf(m[r], mx);
            float cf = __expf(m[r] - mn);
            m[r] = mn;
            float ls = 0.f;
#pragma unroll
            for (int j = 0; j < 8; j++) {
                float p0 = __expf(sf[j][2 * r]     - mn);
                float p1 = __expf(sf[j][2 * r + 1] - mn);
                sf[j][2 * r] = p0; sf[j][2 * r + 1] = p1;
                ls += p0 + p1;
            }
            ls += __shfl_xor_sync(0xffffffffu, ls, 1);
            ls += __shfl_xor_sync(0xffffffffu, ls, 2);
            l[r] = l[r] * cf + ls;
#pragma unroll
            for (int j = 0; j < 8; j++) {
                o[j][2 * r] *= cf; o[j][2 * r + 1] *= cf;
            }
        }

#pragma unroll
        for (int t = 0; t < 4; t++) {
            uint32_t pa_h[4], pa_l[4];
            cvt2(sf[2 * t][0],     sf[2 * t][1],     &pa_h[0], &pa_l[0]);
            cvt2(sf[2 * t][2],     sf[2 * t][3],     &pa_h[1], &pa_l[1]);
            cvt2(sf[2 * t + 1][0], sf[2 * t + 1][1], &pa_h[2], &pa_l[2]);
            cvt2(sf[2 * t + 1][2], sf[2 * t + 1][3], &pa_h[3], &pa_l[3]);
#pragma unroll
            for (int p = 0; p < 4; p++) {
                uint32_t off = (uint32_t)((p * 16 + (lane & 7) + ((lane >> 4) << 3)) * FLT
                                          + t * 16 + (((lane >> 3) & 1) << 3)) * 2;
                uint32_t vh[4], vl[4];
                ldsm4(vh, kbase + FVH * 2 + off);
                ldsm4(vl, kbase + FVL * 2 + off);
                mma16816(o[2 * p],     pa_h, vh);
                mma16816(o[2 * p],     pa_h, vl);
                mma16816(o[2 * p],     pa_l, vh);
                mma16816(o[2 * p + 1], pa_h, vh + 2);
                mma16816(o[2 * p + 1], pa_h, vl + 2);
                mma16816(o[2 * p + 1], pa_l, vh + 2);
            }
        }
    }

    {
        int r0 = q0 + wid * 16 + g;
#pragma unroll
        for (int r = 0; r < 2; r++) {
            float invl = 1.f / l[r];
            int row = r0 + r * 8;
#pragma unroll
            for (int j = 0; j < 8; j++) {
                float v0 = o[j][2 * r] * invl;
                float v1 = o[j][2 * r + 1] * invl;
                uint32_t ph, pl;
                cvt2(v0, v1, &ph, &pl);
                size_t off = hb + (size_t)row * HDIM + j * 8 + 2 * q;
                *(uint32_t*)(Oh + off) = ph;
                *(uint32_t*)(Ol + off) = pl;
            }
        }
    }
}

// ===========================================================================
extern "C" void kernel_launch(void* const* d_in, const int* in_sizes, int n_in,
                              void* d_out, int out_size)
{
    const float* X   = (const float*)d_in[0];
    const float* Wq  = (const float*)d_in[1];
    const float* bq  = (const float*)d_in[2];
    const float* Wk  = (const float*)d_in[3];
    const float* bk  = (const float*)d_in[4];
    const float* Wv  = (const float*)d_in[5];
    const float* bv  = (const float*)d_in[6];
    const float* Wo  = (const float*)d_in[7];
    const float* bo  = (const float*)d_in[8];
    const float* qta = (const float*)d_in[9];
    const float* qtb = (const float*)d_in[10];
    const float* kta = (const float*)d_in[11];
    const float* ktb = (const float*)d_in[12];
    const float* cpl = (const float*)d_in[13];

    float* f32 = nullptr;
    bf16* bf = nullptr;
    cudaGetSymbolAddress((void**)&f32, g_f32);
    cudaGetSymbolAddress((void**)&bf, g_bf);

    const int GS  = 2 * ST_ELEMS * 2;    // 61440 B
    const int GS2 = 2 * ST2_ELEMS * 2;   // 81920 B
    const int FS  = 2 * FSTAGE * 2;      // 73728 B
    cudaFuncSetAttribute(gemm_low, cudaFuncAttributeMaxDynamicSharedMemorySize, GS);
    cudaFuncSetAttribute(gemm_bf2, cudaFuncAttributeMaxDynamicSharedMemorySize, GS2);
    cudaFuncSetAttribute(flash_bf, cudaFuncAttributeMaxDynamicSharedMemorySize, FS);

    const float PI2 = 6.28318530717958647692f;

    // ---- pre-convert (4 launches)
    split_f32<<<4096, 256>>>(X, bf + O_XH, bf + O_XL, 1048576);
    transpose_split4<<<dim3(32, 32, 4), 256>>>(Wq, Wk, Wv, Wo,
        bf + O_WT, bf + O_WT + 1048576u, 1024, 1024, 2097152);
    transpose_split4<<<dim3(2, 32, 4), 256>>>(qta, qta + 65536, kta, kta + 65536,
        bf + O_TA, bf + O_TA + 65536u, 1024, 64, 131072);
    transpose_split4<<<dim3(32, 2, 4), 256>>>(qtb, qtb + 65536, ktb, ktb + 65536,
        bf + O_TB, bf + O_TB + 65536u, 64, 1024, 131072);

    // ---- QKV fused (z = Q,K,V)
    gemm_bf2<<<dim3(8, 32, 3), 512, GS2>>>(
        bf + O_XH, bf + O_XL, 0,
        bf + O_WT, bf + O_WT + 1048576u, 2097152,
        bq, bk, bv, cpl,
        f32, 4194304, 2,
        bf + O_QBH, bf + O_QBH + 4194304u, 8388608,
        1024, 1024, 6, 0.f, 0.f);

    // ---- V transpose for flash cp.async
    vt_transpose<<<dim3(2, 64, 32), 256>>>(bf + O_VBH, bf + O_VBH + 4194304u,
                                           bf + O_VTH, bf + O_VTL);

    // ---- all 4 torsion low-rank GEMMs in one launch
    gemm_low<<<dim3(1, 32, 4), 256, GS>>>(bf + O_QBH, bf + O_TA, bf + O_LB);

    // ---- torsion update n=0 (Q and K fused)
    gemm_bf2<<<dim3(8, 32, 2), 512, GS2>>>(
        bf + O_LB, bf + O_LB + 262144u, 1048576,
        bf + O_TB, bf + O_TB + 65536u, 262144,
        nullptr, nullptr, nullptr, cpl,
        f32, 4194304, 2,
        bf + O_QBH, bf + O_QBH + 4194304u, 8388608,   // unused in mode 1
        64, 1024, 1, PI2, 1.0f);

    // ---- torsion update n=1 (Q and K fused; writes planes)
    gemm_bf2<<<dim3(8, 32, 2), 512, GS2>>>(
        bf + O_LB + 524288u, bf + O_LB + 786432u, 1048576,
        bf + O_TB + 131072u, bf + O_TB + 196608u, 262144,
        nullptr, nullptr, nullptr, cpl,
        f32, 4194304, 2,
        bf + O_QBH, bf + O_QBH + 4194304u, 8388608,
        64, 1024, 4, 2.f * PI2, 0.5f);

    // ---- flash attention (cp.async, occ 2)
    dim3 gAtt(SEQ / 128, NHEAD, BATCH);
    flash_bf<<<gAtt, 256, FS>>>(bf + O_QBH, bf + O_QBH + 4194304u,
                                bf + O_QBH + 8388608u, bf + O_QBH + 12582912u,
                                bf + O_VTH, bf + O_VTL,
                                bf + O_AOH, bf + O_AOL);

    // ---- output projection -> d_out
    gemm_bf2<<<dim3(8, 32, 1), 512, GS2>>>(
        bf + O_AOH, bf + O_AOL, 0,
        bf + O_WT + 6291456u, bf + O_WT + 7340032u, 0,
        bo, bo, bo, cpl,
        (float*)d_out, 0, 1,
        bf + O_AOH, bf + O_AOH, 0,   // unused in mode 0
        1024, 1024, 0, 0.f, 0.f);
}

// round 11
// speedup vs baseline: 2.9140x; 1.0571x over previous
#include <cuda_runtime.h>
#include <cuda_bf16.h>
#include <math.h>
#include <stdint.h>

#define MTOT 4096
#define HDIM 1024
#define NHEAD 16
#define HD 64
#define SEQ 2048
#define BATCH 2

typedef __nv_bfloat16 bf16;

// ---------------- scratch ----------------
__device__ float g_f32[2u * 4194304u];          // Qf, Kf
#define O_XH   0u
#define O_XL   4194304u
#define O_WT   8388608u
#define O_TA   16777216u
#define O_TB   17301504u
#define O_QBH  17825792u
#define O_VBH  34603008u
#define O_AOH  42991616u
#define O_AOL  47185920u
#define O_LB   51380224u
#define O_VTH  53477376u
#define O_VTL  57671680u
__device__ bf16 g_bf[61865984u];

// ---------------- helpers ----------------
__device__ __forceinline__ uint32_t smem_u32(const void* p) {
    uint32_t a;
    asm("{ .reg .u64 t; cvta.to.shared.u64 t, %1; cvt.u32.u64 %0, t; }"
        : "=r"(a) : "l"(p));
    return a;
}
__device__ __forceinline__ void ldsm4(uint32_t* r, uint32_t addr) {
    asm volatile("ldmatrix.sync.aligned.m8n8.x4.shared.b16 {%0,%1,%2,%3}, [%4];"
                 : "=r"(r[0]), "=r"(r[1]), "=r"(r[2]), "=r"(r[3]) : "r"(addr));
}
__device__ __forceinline__ void mma16816(float* c, const uint32_t* a, const uint32_t* b) {
    asm volatile(
        "mma.sync.aligned.m16n8k16.row.col.f32.bf16.bf16.f32 "
        "{%0,%1,%2,%3}, {%4,%5,%6,%7}, {%8,%9}, {%0,%1,%2,%3};"
        : "+f"(c[0]), "+f"(c[1]), "+f"(c[2]), "+f"(c[3])
        : "r"(a[0]), "r"(a[1]), "r"(a[2]), "r"(a[3]), "r"(b[0]), "r"(b[1]));
}
__device__ __forceinline__ void cvt2(float a, float b, uint32_t* hi, uint32_t* lo) {
    __nv_bfloat162 h = __floats2bfloat162_rn(a, b);
    float2 hf = __bfloat1622float2(h);
    __nv_bfloat162 l = __floats2bfloat162_rn(a - hf.x, b - hf.y);
    *hi = *(uint32_t*)&h;
    *lo = *(uint32_t*)&l;
}
__device__ __forceinline__ void cp16(uint32_t s, const void* g) {
    asm volatile("cp.async.cg.shared.global [%0], [%1], 16;" :: "r"(s), "l"(g));
}
#define CP_COMMIT()  asm volatile("cp.async.commit_group;")
#define CP_WAIT1()   asm volatile("cp.async.wait_group 1;" ::: "memory")
#define CP_WAIT0()   asm volatile("cp.async.wait_group 0;" ::: "memory")

// ---------------- pre-conversion kernels ----------------
__global__ __launch_bounds__(256) void split_f32(
    const float* __restrict__ in, bf16* __restrict__ oh, bf16* __restrict__ ol, int n4)
{
    int i = blockIdx.x * 256 + threadIdx.x;
    if (i < n4) {
        float4 f = ((const float4*)in)[i];
        uint2 h, l;
        cvt2(f.x, f.y, &h.x, &l.x);
        cvt2(f.z, f.w, &h.y, &l.y);
        ((uint2*)oh)[i] = h;
        ((uint2*)ol)[i] = l;
    }
}

__global__ __launch_bounds__(256) void transpose_split4(
    const float* __restrict__ i0, const float* __restrict__ i1,
    const float* __restrict__ i2, const float* __restrict__ i3,
    bf16* __restrict__ oh, bf16* __restrict__ ol,
    int M, int N, int zsO)
{
    __shared__ float t[32][33];
    int z = blockIdx.z;
    const float* in = (z == 0) ? i0 : (z == 1) ? i1 : (z == 2) ? i2 : i3;
    oh += (size_t)z * zsO; ol += (size_t)z * zsO;
    int bx = blockIdx.x * 32;
    int by = blockIdx.y * 32;
    int tx = threadIdx.x & 31, ty = threadIdx.x >> 5;
#pragma unroll
    for (int i = 0; i < 32; i += 8)
        t[ty + i][tx] = in[(size_t)(by + ty + i) * N + bx + tx];
    __syncthreads();
#pragma unroll
    for (int i = 0; i < 32; i += 8) {
        float v = t[tx][ty + i];
        bf16 h = __float2bfloat16_rn(v);
        bf16 l = __float2bfloat16_rn(v - __bfloat162float(h));
        size_t o = (size_t)(bx + ty + i) * M + by + tx;
        oh[o] = h;
        ol[o] = l;
    }
}

__global__ __launch_bounds__(256) void vt_transpose(
    const bf16* __restrict__ Vh, const bf16* __restrict__ Vl,
    bf16* __restrict__ Oh, bf16* __restrict__ Ol)
{
    __shared__ bf16 th[32][33], tl[32][33];
    int z = blockIdx.z;
    int b = z >> 4, h = z & 15;
    int d0 = blockIdx.x * 32, s0 = blockIdx.y * 32;
    int tx = threadIdx.x & 31, ty = threadIdx.x >> 5;
#pragma unroll
    for (int i = 0; i < 32; i += 8) {
        size_t off = (size_t)(b * 2048 + s0 + ty + i) * 1024 + h * 64 + d0 + tx;
        th[ty + i][tx] = Vh[off];
        tl[ty + i][tx] = Vl[off];
    }
    __syncthreads();
#pragma unroll
    for (int i = 0; i < 32; i += 8) {
        size_t off = ((size_t)z * 64 + d0 + ty + i) * 2048 + s0 + tx;
        Oh[off] = th[tx][ty + i];
        Ol[off] = tl[tx][ty + i];
    }
}

// ---------------- shared epilogue ----------------
__device__ __forceinline__ void epilogue_frag(
    float d0, float d1, size_t off, int col,
    const float* __restrict__ bias, float sg,
    float* __restrict__ Cf, bf16* __restrict__ Ph, bf16* __restrict__ Pl,
    int mode, float freq, float inv)
{
    if (mode == 0) {
        float2 o = { d0 + bias[col], d1 + bias[col + 1] };
        *(float2*)(Cf + off) = o;
    } else if (mode == 6) {
        float b0 = d0 + bias[col], b1 = d1 + bias[col + 1];
        float2 o = { b0, b1 };
        *(float2*)(Cf + off) = o;
        uint32_t ph, pl;
        cvt2(b0, b1, &ph, &pl);
        *(uint32_t*)(Ph + off) = ph;
        *(uint32_t*)(Pl + off) = pl;
    } else if (mode == 5) {
        float b0 = d0 + bias[col], b1 = d1 + bias[col + 1];
        uint32_t ph, pl;
        cvt2(b0, b1, &ph, &pl);
        *(uint32_t*)(Ph + off) = ph;
        *(uint32_t*)(Pl + off) = pl;
    } else if (mode == 2) {
        uint32_t ph, pl;
        cvt2(d0, d1, &ph, &pl);
        *(uint32_t*)(Ph + off) = ph;
        *(uint32_t*)(Pl + off) = pl;
    } else if (mode == 1) {
        float2 cv = *(float2*)(Cf + off);
        cv.x += sg * sinf(freq * d0) * d0 * inv;
        cv.y += sg * sinf(freq * d1) * d1 * inv;
        *(float2*)(Cf + off) = cv;
    } else {   // mode 4
        float2 cv = *(float2*)(Cf + off);
        float t0 = cv.x + sg * sinf(freq * d0) * d0 * inv;
        float t1 = cv.y + sg * sinf(freq * d1) * d1 * inv;
        uint32_t ph, pl;
        cvt2(t0, t1, &ph, &pl);
        *(uint32_t*)(Ph + off) = ph;
        *(uint32_t*)(Pl + off) = pl;
    }
}

// ===========================================================================
// gemm_low: 128x64 tile, 256 thr, 3-stage cp.async. 4-way z-fused (mode 2).
// ===========================================================================
#define LDT 40
#define ST_AH 0
#define ST_AL 5120
#define ST_BH 10240
#define ST_BL 12800
#define ST_ELEMS 15360
#define NSTG 3

__device__ __forceinline__ void low_issue(
    const bf16* __restrict__ Ah, const bf16* __restrict__ Al,
    const bf16* __restrict__ Bh, const bf16* __restrict__ Bl,
    int K, int bm, int c, uint32_t sb, int tid)
{
    // A: 128 rows x 32 k  (512 chunks, 2 per thread)
#pragma unroll
    for (int r = 0; r < 2; r++) {
        int idx = tid + r * 256;
        int row = idx >> 2, c8 = (idx & 3) * 8;
        uint32_t o = (uint32_t)(row * LDT + c8) * 2;
        cp16(sb + ST_AH * 2 + o, Ah + (size_t)(bm + row) * K + c * 32 + c8);
        cp16(sb + ST_AL * 2 + o, Al + (size_t)(bm + row) * K + c * 32 + c8);
    }
    // B: 64 rows x 32 k (256 chunks, 1 per thread)
    {
        int row = tid >> 2, c8 = (tid & 3) * 8;
        uint32_t o = (uint32_t)(row * LDT + c8) * 2;
        cp16(sb + ST_BH * 2 + o, Bh + (size_t)row * K + c * 32 + c8);
        cp16(sb + ST_BL * 2 + o, Bl + (size_t)row * K + c * 32 + c8);
    }
    CP_COMMIT();
}

__global__ __launch_bounds__(256) void gemm_low(
    const bf16* __restrict__ QBh, const bf16* __restrict__ TAh,
    bf16* __restrict__ LBh)
{
    extern __shared__ __align__(16) char smraw[];
    uint32_t smb = smem_u32(smraw);

    const int K = 1024, N = 64;
    int z = blockIdx.z;
    const bf16* Ah = QBh + (size_t)(z >> 1) * 8388608u;
    const bf16* Al = Ah + 4194304u;
    const bf16* Bh = TAh + (size_t)z * 131072u;
    const bf16* Bl = Bh + 65536u;
    bf16* Ph = LBh + (size_t)z * 524288u;
    bf16* Pl = Ph + 262144u;

    int tid = threadIdx.x, wid = tid >> 5, lane = tid & 31;
    int bm = blockIdx.y * 128;
    int wm = (wid & 3) * 32, wn = (wid >> 2) * 32;

    float acc[2][4][4];
#pragma unroll
    for (int i = 0; i < 2; i++)
#pragma unroll
        for (int j = 0; j < 4; j++)
#pragma unroll
            for (int e = 0; e < 4; e++) acc[i][j][e] = 0.f;

    int nch = K >> 5;
    low_issue(Ah, Al, Bh, Bl, K, bm, 0, smb, tid);
    low_issue(Ah, Al, Bh, Bl, K, bm, 1, smb + (uint32_t)ST_ELEMS * 2, tid);

    for (int c = 0; c < nch; c++) {
        if (c + 1 < nch) CP_WAIT1(); else CP_WAIT0();
        __syncthreads();
        if (c + 2 < nch)
            low_issue(Ah, Al, Bh, Bl, K, bm, c + 2,
                      smb + (uint32_t)(((c + 2) % NSTG) * ST_ELEMS) * 2, tid);

        uint32_t stA  = smb + (uint32_t)((c % NSTG) * ST_ELEMS) * 2;
        uint32_t stAl = stA + ST_AL * 2;
        uint32_t stBh = stA + ST_BH * 2;
        uint32_t stBl = stA + ST_BL * 2;

#pragma unroll
        for (int kk = 0; kk < 32; kk += 16) {
            uint32_t ah[2][4], al[2][4], bh[4][2], bl[4][2];
#pragma unroll
            for (int i = 0; i < 2; i++) {
                uint32_t roff = (uint32_t)((wm + i * 16 + (lane & 15)) * LDT
                                           + kk + ((lane >> 4) << 3)) * 2;
                ldsm4(ah[i], stA + roff);
                ldsm4(al[i], stAl + roff);
            }
#pragma unroll
            for (int p = 0; p < 2; p++) {
                uint32_t noff = (uint32_t)((wn + p * 16 + (lane & 7) + ((lane >> 4) << 3)) * LDT
                                           + kk + (((lane >> 3) & 1) << 3)) * 2;
                uint32_t r[4];
                ldsm4(r, stBh + noff);
                bh[p * 2][0] = r[0]; bh[p * 2][1] = r[1];
                bh[p * 2 + 1][0] = r[2]; bh[p * 2 + 1][1] = r[3];
                ldsm4(r, stBl + noff);
                bl[p * 2][0] = r[0]; bl[p * 2][1] = r[1];
                bl[p * 2 + 1][0] = r[2]; bl[p * 2 + 1][1] = r[3];
            }
#pragma unroll
            for (int i = 0; i < 2; i++)
#pragma unroll
                for (int j = 0; j < 4; j++) {
                    mma16816(acc[i][j], ah[i], bh[j]);
                    mma16816(acc[i][j], ah[i], bl[j]);
                    mma16816(acc[i][j], al[i], bh[j]);
                }
        }
        __syncthreads();
    }

    int g = lane >> 2, q = lane & 3;
#pragma unroll
    for (int i = 0; i < 2; i++)
#pragma unroll
        for (int j = 0; j < 4; j++) {
            int row = bm + wm + i * 16 + g;
            int col = wn + j * 8 + q * 2;
#pragma unroll
            for (int h = 0; h < 2; h++) {
                size_t off = (size_t)(row + h * 8) * N + col;
                epilogue_frag(acc[i][j][h * 2], acc[i][j][h * 2 + 1], off, col,
                              nullptr, 0.f, nullptr, Ph, Pl, 2, 0.f, 0.f);
            }
        }
}

// ===========================================================================
// gemm_bf2: 128x128 tile, 512 thr, 3-stage cp.async, z-fused.
// ===========================================================================
#define ST2_AH 0
#define ST2_AL 5120
#define ST2_BH 10240
#define ST2_BL 15360
#define ST2_ELEMS 20480

__device__ __forceinline__ void g2_issue(
    const bf16* __restrict__ Ah, const bf16* __restrict__ Al,
    const bf16* __restrict__ Bh, const bf16* __restrict__ Bl,
    int K, int bm, int bn, int c, uint32_t sb, int tid)
{
    int row = tid >> 2, c8 = (tid & 3) * 8;
    uint32_t o = (uint32_t)(row * LDT + c8) * 2;
    cp16(sb + ST2_AH * 2 + o, Ah + (size_t)(bm + row) * K + c * 32 + c8);
    cp16(sb + ST2_AL * 2 + o, Al + (size_t)(bm + row) * K + c * 32 + c8);
    cp16(sb + ST2_BH * 2 + o, Bh + (size_t)(bn + row) * K + c * 32 + c8);
    cp16(sb + ST2_BL * 2 + o, Bl + (size_t)(bn + row) * K + c * 32 + c8);
    CP_COMMIT();
}

__global__ __launch_bounds__(512, 1) void gemm_bf2(
    const bf16* __restrict__ Ah0, const bf16* __restrict__ Al0, int zsA,
    const bf16* __restrict__ Bh0, const bf16* __restrict__ Bl0, int zsB,
    const float* __restrict__ b0, const float* __restrict__ b1, const float* __restrict__ b2,
    const float* __restrict__ coupling,
    float* __restrict__ Cf0, int zsC, int cfmax,
    bf16* __restrict__ Ph0, bf16* __restrict__ Pl0, int zsP,
    int K, int N, int mode, float freq, float inv)
{
    extern __shared__ __align__(16) char smraw[];
    uint32_t smb = smem_u32(smraw);

    int z = blockIdx.z;
    const bf16* Ah = Ah0 + (size_t)z * zsA;
    const bf16* Al = Al0 + (size_t)z * zsA;
    const bf16* Bh = Bh0 + (size_t)z * zsB;
    const bf16* Bl = Bl0 + (size_t)z * zsB;
    float* Cf = (z < cfmax) ? (Cf0 + (size_t)z * zsC) : nullptr;
    bf16* Ph = Ph0 + (size_t)z * zsP;
    bf16* Pl = Pl0 + (size_t)z * zsP;
    const float* bias = (z == 0) ? b0 : (z == 1) ? b1 : b2;
    int lmode = (mode == 6 && z >= cfmax) ? 5 : mode;

    int tid = threadIdx.x, wid = tid >> 5, lane = tid & 31;
    int bm = blockIdx.y * 128, bn = blockIdx.x * 128;
    int wm = (wid & 3) * 32, wn = (wid >> 2) * 32;

    float acc[2][4][4];
#pragma unroll
    for (int i = 0; i < 2; i++)
#pragma unroll
        for (int j = 0; j < 4; j++)
#pragma unroll
            for (int e = 0; e < 4; e++) acc[i][j][e] = 0.f;

    int nch = K >> 5;
    g2_issue(Ah, Al, Bh, Bl, K, bm, bn, 0, smb, tid);
    g2_issue(Ah, Al, Bh, Bl, K, bm, bn, 1, smb + (uint32_t)ST2_ELEMS * 2, tid);

    for (int c = 0; c < nch; c++) {
        if (c + 1 < nch) CP_WAIT1(); else CP_WAIT0();
        __syncthreads();
        if (c + 2 < nch)
            g2_issue(Ah, Al, Bh, Bl, K, bm, bn, c + 2,
                     smb + (uint32_t)(((c + 2) % NSTG) * ST2_ELEMS) * 2, tid);

        uint32_t stA  = smb + (uint32_t)((c % NSTG) * ST2_ELEMS) * 2;
        uint32_t stAl = stA + ST2_AL * 2;
        uint32_t stBh = stA + ST2_BH * 2;
        uint32_t stBl = stA + ST2_BL * 2;

#pragma unroll
        for (int kk = 0; kk < 32; kk += 16) {
            uint32_t ah[2][4], al[2][4], bh[4][2], bl[4][2];
#pragma unroll
            for (int i = 0; i < 2; i++) {
                uint32_t roff = (uint32_t)((wm + i * 16 + (lane & 15)) * LDT
                                           + kk + ((lane >> 4) << 3)) * 2;
                ldsm4(ah[i], stA + roff);
                ldsm4(al[i], stAl + roff);
            }
#pragma unroll
            for (int p = 0; p < 2; p++) {
                uint32_t noff = (uint32_t)((wn + p * 16 + (lane & 7) + ((lane >> 4) << 3)) * LDT
                                           + kk + (((lane >> 3) & 1) << 3)) * 2;
                uint32_t r[4];
                ldsm4(r, stBh + noff);
                bh[p * 2][0] = r[0]; bh[p * 2][1] = r[1];
                bh[p * 2 + 1][0] = r[2]; bh[p * 2 + 1][1] = r[3];
                ldsm4(r, stBl + noff);
                bl[p * 2][0] = r[0]; bl[p * 2][1] = r[1];
                bl[p * 2 + 1][0] = r[2]; bl[p * 2 + 1][1] = r[3];
            }
#pragma unroll
            for (int i = 0; i < 2; i++)
#pragma unroll
                for (int j = 0; j < 4; j++) {
                    mma16816(acc[i][j], ah[i], bh[j]);
                    mma16816(acc[i][j], ah[i], bl[j]);
                    mma16816(acc[i][j], al[i], bh[j]);
                }
        }
        __syncthreads();
    }

    int g = lane >> 2, q = lane & 3;
    float sg = 0.f;
    if (lmode == 1 || lmode == 4) sg = 1.f / (1.f + __expf(-(*coupling)));

#pragma unroll
    for (int i = 0; i < 2; i++)
#pragma unroll
        for (int j = 0; j < 4; j++) {
            int row = bm + wm + i * 16 + g;
            int col = bn + wn + j * 8 + q * 2;
#pragma unroll
            for (int h = 0; h < 2; h++) {
                size_t off = (size_t)(row + h * 8) * N + col;
                epilogue_frag(acc[i][j][h * 2], acc[i][j][h * 2 + 1], off, col,
                              bias, sg, Cf, Ph, Pl, lmode, freq, inv);
            }
        }
}

// ===========================================================================
// Flash attention (unchanged from R10 — proven): cp.async, occ 2.
// ===========================================================================
#define FLT 72
#define FKH 0
#define FKL 4608
#define FVH 9216
#define FVL 13824
#define FSTAGE 18432

__device__ __forceinline__ uint32_t ldscale(const bf16* p) {
    __nv_bfloat162 v = *(const __nv_bfloat162*)p;
    __nv_bfloat162 s = __float2bfloat162_rn(0.125f);
    v = __hmul2(v, s);
    return *(uint32_t*)&v;
}

__device__ __forceinline__ void flash_issue(
    const bf16* __restrict__ Kh, const bf16* __restrict__ Kl,
    const bf16* __restrict__ VTh, const bf16* __restrict__ VTl,
    size_t hb, size_t vtb, int kt64, uint32_t sb, int tid)
{
#pragma unroll
    for (int r = 0; r < 2; r++) {
        int idx = tid + r * 256;
        int row = idx >> 3, c8 = (idx & 7) << 3;
        cp16(sb + (uint32_t)(FKH + row * FLT + c8) * 2,
             Kh + hb + (size_t)(kt64 + row) * HDIM + c8);
        cp16(sb + (uint32_t)(FKL + row * FLT + c8) * 2,
             Kl + hb + (size_t)(kt64 + row) * HDIM + c8);
        cp16(sb + (uint32_t)(FVH + row * FLT + c8) * 2,
             VTh + vtb + (size_t)row * SEQ + kt64 + c8);
        cp16(sb + (uint32_t)(FVL + row * FLT + c8) * 2,
             VTl + vtb + (size_t)row * SEQ + kt64 + c8);
    }
    CP_COMMIT();
}

__global__ __launch_bounds__(256, 2) void flash_bf(
    const bf16* __restrict__ Qh, const bf16* __restrict__ Ql,
    const bf16* __restrict__ Kh, const bf16* __restrict__ Kl,
    const bf16* __restrict__ VTh, const bf16* __restrict__ VTl,
    bf16* __restrict__ Oh, bf16* __restrict__ Ol)
{
    extern __shared__ __align__(16) char smraw[];
    uint32_t smb = smem_u32(smraw);

    int tid = threadIdx.x, wid = tid >> 5, lane = tid & 31;
    int g = lane >> 2, q = lane & 3;
    int q0 = blockIdx.x * 128, h = blockIdx.y, b = blockIdx.z;
    size_t hb = ((size_t)b * SEQ) * HDIM + (size_t)h * HD;
    size_t vtb = (size_t)(b * 16 + h) * 131072u;

    uint32_t qh[4][4], ql[4][4];
    {
        int r0 = q0 + wid * 16 + g;
        const bf16* Qph = Qh + hb;
        const bf16* Qpl = Ql + hb;
#pragma unroll
        for (int t = 0; t < 4; t++) {
            qh[t][0] = ldscale(Qph + (size_t)r0 * HDIM + 16 * t + 2 * q);
            qh[t][1] = ldscale(Qph + (size_t)(r0 + 8) * HDIM + 16 * t + 2 * q);
            qh[t][2] = ldscale(Qph + (size_t)r0 * HDIM + 16 * t + 8 + 2 * q);
            qh[t][3] = ldscale(Qph + (size_t)(r0 + 8) * HDIM + 16 * t + 8 + 2 * q);
            ql[t][0] = ldscale(Qpl + (size_t)r0 * HDIM + 16 * t + 2 * q);
            ql[t][1] = ldscale(Qpl + (size_t)(r0 + 8) * HDIM + 16 * t + 2 * q);
            ql[t][2] = ldscale(Qpl + (size_t)r0 * HDIM + 16 * t + 8 + 2 * q);
            ql[t][3] = ldscale(Qpl + (size_t)(r0 + 8) * HDIM + 16 * t + 8 + 2 * q);
        }
    }

    float m[2] = { -1e30f, -1e30f }, l[2] = { 0.f, 0.f };
    float o[8][4];
#pragma unroll
    for (int j = 0; j < 8; j++)
#pragma unroll
        for (int e = 0; e < 4; e++) o[j][e] = 0.f;

    flash_issue(Kh, Kl, VTh, VTl, hb, vtb, 0, smb, tid);

    for (int kt = 0; kt < SEQ / 64; kt++) {
        int s = kt & 1;
        CP_WAIT0();
        __syncthreads();
        if (kt + 1 < SEQ / 64)
            flash_issue(Kh, Kl, VTh, VTl, hb, vtb, (kt + 1) * 64,
                        smb + (uint32_t)((s ^ 1) * FSTAGE) * 2, tid);

        uint32_t kbase = smb + (uint32_t)(s * FSTAGE) * 2;

        float sf[8][4];
#pragma unroll
        for (int j = 0; j < 8; j++)
#pragma unroll
            for (int e = 0; e < 4; e++) sf[j][e] = 0.f;

#pragma unroll
        for (int t = 0; t < 4; t++) {
#pragma unroll
            for (int p = 0; p < 4; p++) {
                uint32_t off = (uint32_t)((p * 16 + (lane & 7) + ((lane >> 4) << 3)) * FLT
                                          + t * 16 + (((lane >> 3) & 1) << 3)) * 2;
                uint32_t kh[4], kl[4];
                ldsm4(kh, kbase + FKH * 2 + off);
                ldsm4(kl, kbase + FKL * 2 + off);
                mma16816(sf[2 * p],     qh[t], kh);
                mma16816(sf[2 * p],     qh[t], kl);
                mma16816(sf[2 * p],     ql[t], kh);
                mma16816(sf[2 * p + 1], qh[t], kh + 2);
                mma16816(sf[2 * p + 1], qh[t], kl + 2);
                mma16816(sf[2 * p + 1], ql[t], kh + 2);
            }
        }

#pragma unroll
        for (int r = 0; r < 2; r++) {
            float mx = -1e30f;
#pragma unroll
            for (int j = 0; j < 8; j++)
                mx = fmaxf(mx, fmaxf(sf[j][2 * r], sf[j][2 * r + 1]));
            mx = fmaxf(mx, __shfl_xor_sync(0xffffffffu, mx, 1));
            mx = fmaxf(mx, __shfl_xor_sync(0xffffffffu, mx, 2));
            float mn = fmaxf(m[r], mx);
            float cf = __expf(m[r] - mn);
            m[r] = mn;
            float ls = 0.f;
#pragma unroll
            for (int j = 0; j < 8; j++) {
                float p0 = __expf(sf[j][2 * r]     - mn);
                float p1 = __expf(sf[j][2 * r + 1] - mn);
                sf[j][2 * r] = p0; sf[j][2 * r + 1] = p1;
                ls += p0 + p1;
            }
            ls += __shfl_xor_sync(0xffffffffu, ls, 1);
            ls += __shfl_xor_sync(0xffffffffu, ls, 2);
            l[r] = l[r] * cf + ls;
#pragma unroll
            for (int j = 0; j < 8; j++) {
                o[j][2 * r] *= cf; o[j][2 * r + 1] *= cf;
            }
        }

#pragma unroll
        for (int t = 0; t < 4; t++) {
            uint32_t pa_h[4], pa_l[4];
            cvt2(sf[2 * t][0],     sf[2 * t][1],     &pa_h[0], &pa_l[0]);
            cvt2(sf[2 * t][2],     sf[2 * t][3],     &pa_h[1], &pa_l[1]);
            cvt2(sf[2 * t + 1][0], sf[2 * t + 1][1], &pa_h[2], &pa_l[2]);
            cvt2(sf[2 * t + 1][2], sf[2 * t + 1][3], &pa_h[3], &pa_l[3]);
#pragma unroll
            for (int p = 0; p < 4; p++) {
                uint32_t off = (uint32_t)((p * 16 + (lane & 7) + ((lane >> 4) << 3)) * FLT
                                          + t * 16 + (((lane >> 3) & 1) << 3)) * 2;
                uint32_t vh[4], vl[4];
                ldsm4(vh, kbase + FVH * 2 + off);
                ldsm4(vl, kbase + FVL * 2 + off);
                mma16816(o[2 * p],     pa_h, vh);
                mma16816(o[2 * p],     pa_h, vl);
                mma16816(o[2 * p],     pa_l, vh);
                mma16816(o[2 * p + 1], pa_h, vh + 2);
                mma16816(o[2 * p + 1], pa_h, vl + 2);
                mma16816(o[2 * p + 1], pa_l, vh + 2);
            }
        }
    }

    {
        int r0 = q0 + wid * 16 + g;
#pragma unroll
        for (int r = 0; r < 2; r++) {
            float invl = 1.f / l[r];
            int row = r0 + r * 8;
#pragma unroll
            for (int j = 0; j < 8; j++) {
                float v0 = o[j][2 * r] * invl;
                float v1 = o[j][2 * r + 1] * invl;
                uint32_t ph, pl;
                cvt2(v0, v1, &ph, &pl);
                size_t off = hb + (size_t)row * HDIM + j * 8 + 2 * q;
                *(uint32_t*)(Oh + off) = ph;
                *(uint32_t*)(Ol + off) = pl;
            }
        }
    }
}

// ===========================================================================
extern "C" void kernel_launch(void* const* d_in, const int* in_sizes, int n_in,
                              void* d_out, int out_size)
{
    const float* X   = (const float*)d_in[0];
    const float* Wq  = (const float*)d_in[1];
    const float* bq  = (const float*)d_in[2];
    const float* Wk  = (const float*)d_in[3];
    const float* bk  = (const float*)d_in[4];
    const float* Wv  = (const float*)d_in[5];
    const float* bv  = (const float*)d_in[6];
    const float* Wo  = (const float*)d_in[7];
    const float* bo  = (const float*)d_in[8];
    const float* qta = (const float*)d_in[9];
    const float* qtb = (const float*)d_in[10];
    const float* kta = (const float*)d_in[11];
    const float* ktb = (const float*)d_in[12];
    const float* cpl = (const float*)d_in[13];

    float* f32 = nullptr;
    bf16* bf = nullptr;
    cudaGetSymbolAddress((void**)&f32, g_f32);
    cudaGetSymbolAddress((void**)&bf, g_bf);

    const int GS  = NSTG * ST_ELEMS * 2;    // 92160 B
    const int GS2 = NSTG * ST2_ELEMS * 2;   // 122880 B
    const int FS  = 2 * FSTAGE * 2;         // 73728 B
    cudaFuncSetAttribute(gemm_low, cudaFuncAttributeMaxDynamicSharedMemorySize, GS);
    cudaFuncSetAttribute(gemm_bf2, cudaFuncAttributeMaxDynamicSharedMemorySize, GS2);
    cudaFuncSetAttribute(flash_bf, cudaFuncAttributeMaxDynamicSharedMemorySize, FS);

    const float PI2 = 6.28318530717958647692f;

    // ---- pre-convert (4 launches)
    split_f32<<<4096, 256>>>(X, bf + O_XH, bf + O_XL, 1048576);
    transpose_split4<<<dim3(32, 32, 4), 256>>>(Wq, Wk, Wv, Wo,
        bf + O_WT, bf + O_WT + 1048576u, 1024, 1024, 2097152);
    transpose_split4<<<dim3(2, 32, 4), 256>>>(qta, qta + 65536, kta, kta + 65536,
        bf + O_TA, bf + O_TA + 65536u, 1024, 64, 131072);
    transpose_split4<<<dim3(32, 2, 4), 256>>>(qtb, qtb + 65536, ktb, ktb + 65536,
        bf + O_TB, bf + O_TB + 65536u, 64, 1024, 131072);

    // ---- QKV fused (z = Q,K,V)
    gemm_bf2<<<dim3(8, 32, 3), 512, GS2>>>(
        bf + O_XH, bf + O_XL, 0,
        bf + O_WT, bf + O_WT + 1048576u, 2097152,
        bq, bk, bv, cpl,
        f32, 4194304, 2,
        bf + O_QBH, bf + O_QBH + 4194304u, 8388608,
        1024, 1024, 6, 0.f, 0.f);

    // ---- V transpose for flash cp.async
    vt_transpose<<<dim3(2, 64, 32), 256>>>(bf + O_VBH, bf + O_VBH + 4194304u,
                                           bf + O_VTH, bf + O_VTL);

    // ---- all 4 torsion low-rank GEMMs in one launch
    gemm_low<<<dim3(1, 32, 4), 256, GS>>>(bf + O_QBH, bf + O_TA, bf + O_LB);

    // ---- torsion update n=0 (Q and K fused)
    gemm_bf2<<<dim3(8, 32, 2), 512, GS2>>>(
        bf + O_LB, bf + O_LB + 262144u, 1048576,
        bf + O_TB, bf + O_TB + 65536u, 262144,
        nullptr, nullptr, nullptr, cpl,
        f32, 4194304, 2,
        bf + O_QBH, bf + O_QBH + 4194304u, 8388608,
        64, 1024, 1, PI2, 1.0f);

    // ---- torsion update n=1 (Q and K fused; writes planes)
    gemm_bf2<<<dim3(8, 32, 2), 512, GS2>>>(
        bf + O_LB + 524288u, bf + O_LB + 786432u, 1048576,
        bf + O_TB + 131072u, bf + O_TB + 196608u, 262144,
        nullptr, nullptr, nullptr, cpl,
        f32, 4194304, 2,
        bf + O_QBH, bf + O_QBH + 4194304u, 8388608,
        64, 1024, 4, 2.f * PI2, 0.5f);

    // ---- flash attention (cp.async, occ 2)
    dim3 gAtt(SEQ / 128, NHEAD, BATCH);
    flash_bf<<<gAtt, 256, FS>>>(bf + O_QBH, bf + O_QBH + 4194304u,
                                bf + O_QBH + 8388608u, bf + O_QBH + 12582912u,
                                bf + O_VTH, bf + O_VTL,
                                bf + O_AOH, bf + O_AOL);

    // ---- output projection -> d_out
    gemm_bf2<<<dim3(8, 32, 1), 512, GS2>>>(
        bf + O_AOH, bf + O_AOL, 0,
        bf + O_WT + 6291456u, bf + O_WT + 7340032u, 0,
        bo, bo, bo, cpl,
        (float*)d_out, 0, 1,
        bf + O_AOH, bf + O_AOH, 0,
        1024, 1024, 0, 0.f, 0.f);
}

// round 14
// speedup vs baseline: 3.1251x; 1.0724x over previous
#include <cuda_runtime.h>
#include <cuda_bf16.h>
#include <math.h>
#include <stdint.h>

#define MTOT 4096
#define HDIM 1024
#define NHEAD 16
#define HD 64
#define SEQ 2048
#define BATCH 2

typedef __nv_bfloat16 bf16;

// ---------------- scratch (bf16 planes only; no fp32 scratch needed) -------
#define O_XH   0u
#define O_XL   4194304u
#define O_WT   8388608u      // W slots: h@O_WT+z*2097152, l=h+1048576 (q,k,v,o)
#define O_TA   16777216u     // 4 slots: h@z*131072, l=h+65536 (qta0,qta1,kta0,kta1)
#define O_TB   17301504u     // 4 slots: h@z*131072, l=h+65536 (qtb0,qtb1,ktb0,ktb1)
#define O_QBH  17825792u     // Q/K/V planes: h@O_QBH+z*8388608, l=h+4194304
#define O_AOH  42991616u
#define O_AOL  47185920u
#define O_LB   51380224u     // 4 hi-only slots: z*262144 (q_n0,q_n1,k_n0,k_n1)
#define O_VTH  53477376u
#define O_VTL  57671680u
__device__ bf16 g_bf[61865984u];

// ---------------- helpers ----------------
__device__ __forceinline__ uint32_t smem_u32(const void* p) {
    uint32_t a;
    asm("{ .reg .u64 t; cvta.to.shared.u64 t, %1; cvt.u32.u64 %0, t; }"
        : "=r"(a) : "l"(p));
    return a;
}
__device__ __forceinline__ void ldsm4(uint32_t* r, uint32_t addr) {
    asm volatile("ldmatrix.sync.aligned.m8n8.x4.shared.b16 {%0,%1,%2,%3}, [%4];"
                 : "=r"(r[0]), "=r"(r[1]), "=r"(r[2]), "=r"(r[3]) : "r"(addr));
}
__device__ __forceinline__ void mma16816(float* c, const uint32_t* a, const uint32_t* b) {
    asm volatile(
        "mma.sync.aligned.m16n8k16.row.col.f32.bf16.bf16.f32 "
        "{%0,%1,%2,%3}, {%4,%5,%6,%7}, {%8,%9}, {%0,%1,%2,%3};"
        : "+f"(c[0]), "+f"(c[1]), "+f"(c[2]), "+f"(c[3])
        : "r"(a[0]), "r"(a[1]), "r"(a[2]), "r"(a[3]), "r"(b[0]), "r"(b[1]));
}
__device__ __forceinline__ void cvt2(float a, float b, uint32_t* hi, uint32_t* lo) {
    __nv_bfloat162 h = __floats2bfloat162_rn(a, b);
    float2 hf = __bfloat1622float2(h);
    __nv_bfloat162 l = __floats2bfloat162_rn(a - hf.x, b - hf.y);
    *hi = *(uint32_t*)&h;
    *lo = *(uint32_t*)&l;
}
__device__ __forceinline__ void cp16(uint32_t s, const void* g) {
    asm volatile("cp.async.cg.shared.global [%0], [%1], 16;" :: "r"(s), "l"(g));
}
#define CP_COMMIT()  asm volatile("cp.async.commit_group;")
#define CP_WAIT1()   asm volatile("cp.async.wait_group 1;" ::: "memory")
#define CP_WAIT0()   asm volatile("cp.async.wait_group 0;" ::: "memory")

// ---------------- pre-conversion kernels ----------------
__global__ __launch_bounds__(256) void split_f32(
    const float* __restrict__ in, bf16* __restrict__ oh, bf16* __restrict__ ol, int n4)
{
    int i = blockIdx.x * 256 + threadIdx.x;
    if (i < n4) {
        float4 f = ((const float4*)in)[i];
        uint2 h, l;
        cvt2(f.x, f.y, &h.x, &l.x);
        cvt2(f.z, f.w, &h.y, &l.y);
        ((uint2*)oh)[i] = h;
        ((uint2*)ol)[i] = l;
    }
}

__global__ __launch_bounds__(256) void transpose_split4(
    const float* __restrict__ i0, const float* __restrict__ i1,
    const float* __restrict__ i2, const float* __restrict__ i3,
    bf16* __restrict__ oh, bf16* __restrict__ ol,
    int M, int N, int zsO)
{
    __shared__ float t[32][33];
    int z = blockIdx.z;
    const float* in = (z == 0) ? i0 : (z == 1) ? i1 : (z == 2) ? i2 : i3;
    oh += (size_t)z * zsO; ol += (size_t)z * zsO;
    int bx = blockIdx.x * 32;
    int by = blockIdx.y * 32;
    int tx = threadIdx.x & 31, ty = threadIdx.x >> 5;
#pragma unroll
    for (int i = 0; i < 32; i += 8)
        t[ty + i][tx] = in[(size_t)(by + ty + i) * N + bx + tx];
    __syncthreads();
#pragma unroll
    for (int i = 0; i < 32; i += 8) {
        float v = t[tx][ty + i];
        bf16 h = __float2bfloat16_rn(v);
        bf16 l = __float2bfloat16_rn(v - __bfloat162float(h));
        size_t o = (size_t)(bx + ty + i) * M + by + tx;
        oh[o] = h;
        ol[o] = l;
    }
}

__global__ __launch_bounds__(256) void vt_transpose(
    const bf16* __restrict__ Vh, const bf16* __restrict__ Vl,
    bf16* __restrict__ Oh, bf16* __restrict__ Ol)
{
    __shared__ bf16 th[32][33], tl[32][33];
    int z = blockIdx.z;
    int b = z >> 4, h = z & 15;
    int d0 = blockIdx.x * 32, s0 = blockIdx.y * 32;
    int tx = threadIdx.x & 31, ty = threadIdx.x >> 5;
#pragma unroll
    for (int i = 0; i < 32; i += 8) {
        size_t off = (size_t)(b * 2048 + s0 + ty + i) * 1024 + h * 64 + d0 + tx;
        th[ty + i][tx] = Vh[off];
        tl[ty + i][tx] = Vl[off];
    }
    __syncthreads();
#pragma unroll
    for (int i = 0; i < 32; i += 8) {
        size_t off = ((size_t)z * 64 + d0 + ty + i) * 2048 + s0 + tx;
        Oh[off] = th[tx][ty + i];
        Ol[off] = tl[tx][ty + i];
    }
}

// ---------------- shared epilogue (modes 0 / 5 only now) ----------------
__device__ __forceinline__ void epilogue_frag(
    float d0, float d1, size_t off, int col,
    const float* __restrict__ bias,
    float* __restrict__ Cf, bf16* __restrict__ Ph, bf16* __restrict__ Pl,
    int mode)
{
    float b0 = d0 + bias[col], b1 = d1 + bias[col + 1];
    if (mode == 0) {
        float2 o = { b0, b1 };
        *(float2*)(Cf + off) = o;
    } else {   // 5: planes only
        uint32_t ph, pl;
        cvt2(b0, b1, &ph, &pl);
        *(uint32_t*)(Ph + off) = ph;
        *(uint32_t*)(Pl + off) = pl;
    }
}

#define LDT 40
#define NSTG 3

// ===========================================================================
// gemm_low1: SINGLE-TERM bf16. C[4096,64] = Ahi[4096,1024] @ Bhi[64,1024]^T.
// 128x64 tile, 256 thr, 3-stage cp.async, 4-way z-fused. Writes hi plane only.
// ===========================================================================
#define SL_A 0
#define SL_B 5120
#define SL_ELEMS 7680

__device__ __forceinline__ void low_issue(
    const bf16* __restrict__ Ah, const bf16* __restrict__ Bh,
    int bm, int c, uint32_t sb, int tid)
{
#pragma unroll
    for (int r = 0; r < 2; r++) {
        int idx = tid + r * 256;
        int row = idx >> 2, c8 = (idx & 3) * 8;
        cp16(sb + SL_A * 2 + (uint32_t)(row * LDT + c8) * 2,
             Ah + (size_t)(bm + row) * 1024 + c * 32 + c8);
    }
    {
        int row = tid >> 2, c8 = (tid & 3) * 8;
        cp16(sb + SL_B * 2 + (uint32_t)(row * LDT + c8) * 2,
             Bh + (size_t)row * 1024 + c * 32 + c8);
    }
    CP_COMMIT();
}

__global__ __launch_bounds__(256) void gemm_low1(
    const bf16* __restrict__ QBh, const bf16* __restrict__ TAh,
    bf16* __restrict__ LBh)
{
    extern __shared__ __align__(16) char smraw[];
    uint32_t smb = smem_u32(smraw);

    int z = blockIdx.z;
    const bf16* Ah = QBh + (size_t)(z >> 1) * 8388608u;          // Q or K hi plane
    const bf16* Bh = TAh + (size_t)z * 131072u;                  // ta hi
    bf16* Ph = LBh + (size_t)z * 262144u;

    int tid = threadIdx.x, wid = tid >> 5, lane = tid & 31;
    int bm = blockIdx.y * 128;
    int wm = (wid & 3) * 32, wn = (wid >> 2) * 32;

    float acc[2][4][4];
#pragma unroll
    for (int i = 0; i < 2; i++)
#pragma unroll
        for (int j = 0; j < 4; j++)
#pragma unroll
            for (int e = 0; e < 4; e++) acc[i][j][e] = 0.f;

    const int nch = 32;
    low_issue(Ah, Bh, bm, 0, smb, tid);
    low_issue(Ah, Bh, bm, 1, smb + (uint32_t)SL_ELEMS * 2, tid);

    for (int c = 0; c < nch; c++) {
        if (c + 1 < nch) CP_WAIT1(); else CP_WAIT0();
        __syncthreads();
        if (c + 2 < nch)
            low_issue(Ah, Bh, bm, c + 2,
                      smb + (uint32_t)(((c + 2) % NSTG) * SL_ELEMS) * 2, tid);

        uint32_t stA = smb + (uint32_t)((c % NSTG) * SL_ELEMS) * 2;
        uint32_t stB = stA + SL_B * 2;

#pragma unroll
        for (int kk = 0; kk < 32; kk += 16) {
            uint32_t ah[2][4], bh[4][2];
#pragma unroll
            for (int i = 0; i < 2; i++) {
                uint32_t roff = (uint32_t)((wm + i * 16 + (lane & 15)) * LDT
                                           + kk + ((lane >> 4) << 3)) * 2;
                ldsm4(ah[i], stA + roff);
            }
#pragma unroll
            for (int p = 0; p < 2; p++) {
                uint32_t noff = (uint32_t)((wn + p * 16 + (lane & 7) + ((lane >> 4) << 3)) * LDT
                                           + kk + (((lane >> 3) & 1) << 3)) * 2;
                uint32_t r[4];
                ldsm4(r, stB + noff);
                bh[p * 2][0] = r[0]; bh[p * 2][1] = r[1];
                bh[p * 2 + 1][0] = r[2]; bh[p * 2 + 1][1] = r[3];
            }
#pragma unroll
            for (int i = 0; i < 2; i++)
#pragma unroll
                for (int j = 0; j < 4; j++)
                    mma16816(acc[i][j], ah[i], bh[j]);
        }
        __syncthreads();
    }

    int g = lane >> 2, q = lane & 3;
#pragma unroll
    for (int i = 0; i < 2; i++)
#pragma unroll
        for (int j = 0; j < 4; j++) {
            int row = bm + wm + i * 16 + g;
            int col = wn + j * 8 + q * 2;
#pragma unroll
            for (int h = 0; h < 2; h++) {
                size_t off = (size_t)(row + h * 8) * 64 + col;
                __nv_bfloat162 hv = __floats2bfloat162_rn(acc[i][j][h * 2],
                                                          acc[i][j][h * 2 + 1]);
                *(uint32_t*)(Ph + off) = *(uint32_t*)&hv;
            }
        }
}

// ===========================================================================
// torsion_upd: fused n=0 + n=1 update, single-term bf16 GEMMs (K=64).
// D_n[4096,1024] = L_n[4096,64] @ tb_n[1024,64]^T for n=0,1, then
// plane(out) = recon(planes) + sig*(sin(2pi d0)*d0 + sin(4pi d1)*d1*0.5).
// z: 0 -> Q planes, 1 -> K planes (in-place plane update).
// ===========================================================================
#define SU_A 0
#define SU_B 5120
#define SU_ELEMS 10240

__device__ __forceinline__ void upd_issue(
    const bf16* __restrict__ L0, const bf16* __restrict__ B0,
    int bm, int bn, int idx, uint32_t sb, int tid)
{
    int n = idx >> 1, c = idx & 1;
    const bf16* A = L0 + (size_t)n * 262144u;
    const bf16* B = B0 + (size_t)n * 131072u;
    int row = tid >> 2, c8 = (tid & 3) * 8;
    uint32_t o = (uint32_t)(row * LDT + c8) * 2;
    cp16(sb + SU_A * 2 + o, A + (size_t)(bm + row) * 64 + c * 32 + c8);
    cp16(sb + SU_B * 2 + o, B + (size_t)(bn + row) * 64 + c * 32 + c8);
    CP_COMMIT();
}

__global__ __launch_bounds__(512, 1) void torsion_upd(
    const bf16* __restrict__ LB, const bf16* __restrict__ TB,
    bf16* __restrict__ QB, const float* __restrict__ coupling)
{
    extern __shared__ __align__(16) char smraw[];
    uint32_t smb = smem_u32(smraw);

    int z = blockIdx.z;
    const bf16* L0 = LB + (size_t)z * 524288u;       // slots z*2, z*2+1
    const bf16* B0 = TB + (size_t)z * 262144u;       // tb hi slots z*2, z*2+1
    bf16* Ph = QB + (size_t)z * 8388608u;
    bf16* Pl = Ph + 4194304u;

    int tid = threadIdx.x, wid = tid >> 5, lane = tid & 31;
    int bm = blockIdx.y * 128, bn = blockIdx.x * 128;
    int wm = (wid & 3) * 32, wn = (wid >> 2) * 32;

    float acc[2][2][4][4];
#pragma unroll
    for (int n = 0; n < 2; n++)
#pragma unroll
        for (int i = 0; i < 2; i++)
#pragma unroll
            for (int j = 0; j < 4; j++)
#pragma unroll
                for (int e = 0; e < 4; e++) acc[n][i][j][e] = 0.f;

    upd_issue(L0, B0, bm, bn, 0, smb, tid);
    upd_issue(L0, B0, bm, bn, 1, smb + (uint32_t)SU_ELEMS * 2, tid);

    for (int idx = 0; idx < 4; idx++) {
        if (idx + 1 < 4) CP_WAIT1(); else CP_WAIT0();
        __syncthreads();
        if (idx + 2 < 4)
            upd_issue(L0, B0, bm, bn, idx + 2,
                      smb + (uint32_t)(((idx + 2) % NSTG) * SU_ELEMS) * 2, tid);

        int n = idx >> 1;
        uint32_t stA = smb + (uint32_t)((idx % NSTG) * SU_ELEMS) * 2;
        uint32_t stB = stA + SU_B * 2;

#pragma unroll
        for (int kk = 0; kk < 32; kk += 16) {
            uint32_t ah[2][4], bh[4][2];
#pragma unroll
            for (int i = 0; i < 2; i++) {
                uint32_t roff = (uint32_t)((wm + i * 16 + (lane & 15)) * LDT
                                           + kk + ((lane >> 4) << 3)) * 2;
                ldsm4(ah[i], stA + roff);
            }
#pragma unroll
            for (int p = 0; p < 2; p++) {
                uint32_t noff = (uint32_t)((wn + p * 16 + (lane & 7) + ((lane >> 4) << 3)) * LDT
                                           + kk + (((lane >> 3) & 1) << 3)) * 2;
                uint32_t r[4];
                ldsm4(r, stB + noff);
                bh[p * 2][0] = r[0]; bh[p * 2][1] = r[1];
                bh[p * 2 + 1][0] = r[2]; bh[p * 2 + 1][1] = r[3];
            }
#pragma unroll
            for (int i = 0; i < 2; i++)
#pragma unroll
                for (int j = 0; j < 4; j++)
                    mma16816(acc[n][i][j], ah[i], bh[j]);
        }
        __syncthreads();
    }

    const float PI2 = 6.28318530717958647692f;
    const float PI4 = 12.5663706143591729539f;
    float sg = 1.f / (1.f + __expf(-(*coupling)));

    int g = lane >> 2, q = lane & 3;
#pragma unroll
    for (int i = 0; i < 2; i++)
#pragma unroll
        for (int j = 0; j < 4; j++) {
            int row = bm + wm + i * 16 + g;
            int col = bn + wn + j * 8 + q * 2;
#pragma unroll
            for (int h = 0; h < 2; h++) {
                size_t off = (size_t)(row + h * 8) * 1024 + col;
                uint32_t hv = *(uint32_t*)(Ph + off);
                uint32_t lv = *(uint32_t*)(Pl + off);
                float2 rh = __bfloat1622float2(*(__nv_bfloat162*)&hv);
                float2 rl = __bfloat1622float2(*(__nv_bfloat162*)&lv);
                float d0a = acc[0][i][j][h * 2],     d1a = acc[1][i][j][h * 2];
                float d0b = acc[0][i][j][h * 2 + 1], d1b = acc[1][i][j][h * 2 + 1];
                float t0 = rh.x + rl.x + sg * (sinf(PI2 * d0a) * d0a
                                               + sinf(PI4 * d1a) * d1a * 0.5f);
                float t1 = rh.y + rl.y + sg * (sinf(PI2 * d0b) * d0b
                                               + sinf(PI4 * d1b) * d1b * 0.5f);
                uint32_t ph, pl;
                cvt2(t0, t1, &ph, &pl);
                *(uint32_t*)(Ph + off) = ph;
                *(uint32_t*)(Pl + off) = pl;
            }
        }
}

// ===========================================================================
// gemm_bf2: 128x128 tile, 512 thr, 3-stage cp.async, z-fused (3-term split).
// ===========================================================================
#define ST2_AH 0
#define ST2_AL 5120
#define ST2_BH 10240
#define ST2_BL 15360
#define ST2_ELEMS 20480

__device__ __forceinline__ void g2_issue(
    const bf16* __restrict__ Ah, const bf16* __restrict__ Al,
    const bf16* __restrict__ Bh, const bf16* __restrict__ Bl,
    int K, int bm, int bn, int c, uint32_t sb, int tid)
{
    int row = tid >> 2, c8 = (tid & 3) * 8;
    uint32_t o = (uint32_t)(row * LDT + c8) * 2;
    cp16(sb + ST2_AH * 2 + o, Ah + (size_t)(bm + row) * K + c * 32 + c8);
    cp16(sb + ST2_AL * 2 + o, Al + (size_t)(bm + row) * K + c * 32 + c8);
    cp16(sb + ST2_BH * 2 + o, Bh + (size_t)(bn + row) * K + c * 32 + c8);
    cp16(sb + ST2_BL * 2 + o, Bl + (size_t)(bn + row) * K + c * 32 + c8);
    CP_COMMIT();
}

__global__ __launch_bounds__(512, 1) void gemm_bf2(
    const bf16* __restrict__ Ah0, const bf16* __restrict__ Al0, int zsA,
    const bf16* __restrict__ Bh0, const bf16* __restrict__ Bl0, int zsB,
    const float* __restrict__ b0, const float* __restrict__ b1, const float* __restrict__ b2,
    float* __restrict__ Cf,
    bf16* __restrict__ Ph0, bf16* __restrict__ Pl0, int zsP,
    int K, int N, int mode)
{
    extern __shared__ __align__(16) char smraw[];
    uint32_t smb = smem_u32(smraw);

    int z = blockIdx.z;
    const bf16* Ah = Ah0 + (size_t)z * zsA;
    const bf16* Al = Al0 + (size_t)z * zsA;
    const bf16* Bh = Bh0 + (size_t)z * zsB;
    const bf16* Bl = Bl0 + (size_t)z * zsB;
    bf16* Ph = Ph0 + (size_t)z * zsP;
    bf16* Pl = Pl0 + (size_t)z * zsP;
    const float* bias = (z == 0) ? b0 : (z == 1) ? b1 : b2;

    int tid = threadIdx.x, wid = tid >> 5, lane = tid & 31;
    int bm = blockIdx.y * 128, bn = blockIdx.x * 128;
    int wm = (wid & 3) * 32, wn = (wid >> 2) * 32;

    float acc[2][4][4];
#pragma unroll
    for (int i = 0; i < 2; i++)
#pragma unroll
        for (int j = 0; j < 4; j++)
#pragma unroll
            for (int e = 0; e < 4; e++) acc[i][j][e] = 0.f;

    int nch = K >> 5;
    g2_issue(Ah, Al, Bh, Bl, K, bm, bn, 0, smb, tid);
    g2_issue(Ah, Al, Bh, Bl, K, bm, bn, 1, smb + (uint32_t)ST2_ELEMS * 2, tid);

    for (int c = 0; c < nch; c++) {
        if (c + 1 < nch) CP_WAIT1(); else CP_WAIT0();
        __syncthreads();
        if (c + 2 < nch)
            g2_issue(Ah, Al, Bh, Bl, K, bm, bn, c + 2,
                     smb + (uint32_t)(((c + 2) % NSTG) * ST2_ELEMS) * 2, tid);

        uint32_t stA  = smb + (uint32_t)((c % NSTG) * ST2_ELEMS) * 2;
        uint32_t stAl = stA + ST2_AL * 2;
        uint32_t stBh = stA + ST2_BH * 2;
        uint32_t stBl = stA + ST2_BL * 2;

#pragma unroll
        for (int kk = 0; kk < 32; kk += 16) {
            uint32_t ah[2][4], al[2][4], bh[4][2], bl[4][2];
#pragma unroll
            for (int i = 0; i < 2; i++) {
                uint32_t roff = (uint32_t)((wm + i * 16 + (lane & 15)) * LDT
                                           + kk + ((lane >> 4) << 3)) * 2;
                ldsm4(ah[i], stA + roff);
                ldsm4(al[i], stAl + roff);
            }
#pragma unroll
            for (int p = 0; p < 2; p++) {
                uint32_t noff = (uint32_t)((wn + p * 16 + (lane & 7) + ((lane >> 4) << 3)) * LDT
                                           + kk + (((lane >> 3) & 1) << 3)) * 2;
                uint32_t r[4];
                ldsm4(r, stBh + noff);
                bh[p * 2][0] = r[0]; bh[p * 2][1] = r[1];
                bh[p * 2 + 1][0] = r[2]; bh[p * 2 + 1][1] = r[3];
                ldsm4(r, stBl + noff);
                bl[p * 2][0] = r[0]; bl[p * 2][1] = r[1];
                bl[p * 2 + 1][0] = r[2]; bl[p * 2 + 1][1] = r[3];
            }
#pragma unroll
            for (int i = 0; i < 2; i++)
#pragma unroll
                for (int j = 0; j < 4; j++) {
                    mma16816(acc[i][j], ah[i], bh[j]);
                    mma16816(acc[i][j], ah[i], bl[j]);
                    mma16816(acc[i][j], al[i], bh[j]);
                }
        }
        __syncthreads();
    }

    int g = lane >> 2, q = lane & 3;
#pragma unroll
    for (int i = 0; i < 2; i++)
#pragma unroll
        for (int j = 0; j < 4; j++) {
            int row = bm + wm + i * 16 + g;
            int col = bn + wn + j * 8 + q * 2;
#pragma unroll
            for (int h = 0; h < 2; h++) {
                size_t off = (size_t)(row + h * 8) * N + col;
                epilogue_frag(acc[i][j][h * 2], acc[i][j][h * 2 + 1], off, col,
                              bias, Cf, Ph, Pl, mode);
            }
        }
}

// ===========================================================================
// Flash attention (unchanged — proven): cp.async, occ 2.
// ===========================================================================
#define FLT 72
#define FKH 0
#define FKL 4608
#define FVH 9216
#define FVL 13824
#define FSTAGE 18432

__device__ __forceinline__ uint32_t ldscale(const bf16* p) {
    __nv_bfloat162 v = *(const __nv_bfloat162*)p;
    __nv_bfloat162 s = __float2bfloat162_rn(0.125f);
    v = __hmul2(v, s);
    return *(uint32_t*)&v;
}

__device__ __forceinline__ void flash_issue(
    const bf16* __restrict__ Kh, const bf16* __restrict__ Kl,
    const bf16* __restrict__ VTh, const bf16* __restrict__ VTl,
    size_t hb, size_t vtb, int kt64, uint32_t sb, int tid)
{
#pragma unroll
    for (int r = 0; r < 2; r++) {
        int idx = tid + r * 256;
        int row = idx >> 3, c8 = (idx & 7) << 3;
        cp16(sb + (uint32_t)(FKH + row * FLT + c8) * 2,
             Kh + hb + (size_t)(kt64 + row) * HDIM + c8);
        cp16(sb + (uint32_t)(FKL + row * FLT + c8) * 2,
             Kl + hb + (size_t)(kt64 + row) * HDIM + c8);
        cp16(sb + (uint32_t)(FVH + row * FLT + c8) * 2,
             VTh + vtb + (size_t)row * SEQ + kt64 + c8);
        cp16(sb + (uint32_t)(FVL + row * FLT + c8) * 2,
             VTl + vtb + (size_t)row * SEQ + kt64 + c8);
    }
    CP_COMMIT();
}

__global__ __launch_bounds__(256, 2) void flash_bf(
    const bf16* __restrict__ Qh, const bf16* __restrict__ Ql,
    const bf16* __restrict__ Kh, const bf16* __restrict__ Kl,
    const bf16* __restrict__ VTh, const bf16* __restrict__ VTl,
    bf16* __restrict__ Oh, bf16* __restrict__ Ol)
{
    extern __shared__ __align__(16) char smraw[];
    uint32_t smb = smem_u32(smraw);

    int tid = threadIdx.x, wid = tid >> 5, lane = tid & 31;
    int g = lane >> 2, q = lane & 3;
    int q0 = blockIdx.x * 128, h = blockIdx.y, b = blockIdx.z;
    size_t hb = ((size_t)b * SEQ) * HDIM + (size_t)h * HD;
    size_t vtb = (size_t)(b * 16 + h) * 131072u;

    uint32_t qh[4][4], ql[4][4];
    {
        int r0 = q0 + wid * 16 + g;
        const bf16* Qph = Qh + hb;
        const bf16* Qpl = Ql + hb;
#pragma unroll
        for (int t = 0; t < 4; t++) {
            qh[t][0] = ldscale(Qph + (size_t)r0 * HDIM + 16 * t + 2 * q);
            qh[t][1] = ldscale(Qph + (size_t)(r0 + 8) * HDIM + 16 * t + 2 * q);
            qh[t][2] = ldscale(Qph + (size_t)r0 * HDIM + 16 * t + 8 + 2 * q);
            qh[t][3] = ldscale(Qph + (size_t)(r0 + 8) * HDIM + 16 * t + 8 + 2 * q);
            ql[t][0] = ldscale(Qpl + (size_t)r0 * HDIM + 16 * t + 2 * q);
            ql[t][1] = ldscale(Qpl + (size_t)(r0 + 8) * HDIM + 16 * t + 2 * q);
            ql[t][2] = ldscale(Qpl + (size_t)r0 * HDIM + 16 * t + 8 + 2 * q);
            ql[t][3] = ldscale(Qpl + (size_t)(r0 + 8) * HDIM + 16 * t + 8 + 2 * q);
        }
    }

    float m[2] = { -1e30f, -1e30f }, l[2] = { 0.f, 0.f };
    float o[8][4];
#pragma unroll
    for (int j = 0; j < 8; j++)
#pragma unroll
        for (int e = 0; e < 4; e++) o[j][e] = 0.f;

    flash_issue(Kh, Kl, VTh, VTl, hb, vtb, 0, smb, tid);

    for (int kt = 0; kt < SEQ / 64; kt++) {
        int s = kt & 1;
        CP_WAIT0();
        __syncthreads();
        if (kt + 1 < SEQ / 64)
            flash_issue(Kh, Kl, VTh, VTl, hb, vtb, (kt + 1) * 64,
                        smb + (uint32_t)((s ^ 1) * FSTAGE) * 2, tid);

        uint32_t kbase = smb + (uint32_t)(s * FSTAGE) * 2;

        float sf[8][4];
#pragma unroll
        for (int j = 0; j < 8; j++)
#pragma unroll
            for (int e = 0; e < 4; e++) sf[j][e] = 0.f;

#pragma unroll
        for (int t = 0; t < 4; t++) {
#pragma unroll
            for (int p = 0; p < 4; p++) {
                uint32_t off = (uint32_t)((p * 16 + (lane & 7) + ((lane >> 4) << 3)) * FLT
                                          + t * 16 + (((lane >> 3) & 1) << 3)) * 2;
                uint32_t kh[4], kl[4];
                ldsm4(kh, kbase + FKH * 2 + off);
                ldsm4(kl, kbase + FKL * 2 + off);
                mma16816(sf[2 * p],     qh[t], kh);
                mma16816(sf[2 * p],     qh[t], kl);
                mma16816(sf[2 * p],     ql[t], kh);
                mma16816(sf[2 * p + 1], qh[t], kh + 2);
                mma16816(sf[2 * p + 1], qh[t], kl + 2);
                mma16816(sf[2 * p + 1], ql[t], kh + 2);
            }
        }

#pragma unroll
        for (int r = 0; r < 2; r++) {
            float mx = -1e30f;
#pragma unroll
            for (int j = 0; j < 8; j++)
                mx = fmaxf(mx, fmaxf(sf[j][2 * r], sf[j][2 * r + 1]));
            mx = fmaxf(mx, __shfl_xor_sync(0xffffffffu, mx, 1));
            mx = fmaxf(mx, __shfl_xor_sync(0xffffffffu, mx, 2));
            float mn = fmaxf(m[r], mx);
            float cf = __expf(m[r] - mn);
            m[r] = mn;
            float ls = 0.f;
#pragma unroll
            for (int j = 0; j < 8; j++) {
                float p0 = __expf(sf[j][2 * r]     - mn);
                float p1 = __expf(sf[j][2 * r + 1] - mn);
                sf[j][2 * r] = p0; sf[j][2 * r + 1] = p1;
                ls += p0 + p1;
            }
            ls += __shfl_xor_sync(0xffffffffu, ls, 1);
            ls += __shfl_xor_sync(0xffffffffu, ls, 2);
            l[r] = l[r] * cf + ls;
#pragma unroll
            for (int j = 0; j < 8; j++) {
                o[j][2 * r] *= cf; o[j][2 * r + 1] *= cf;
            }
        }

#pragma unroll
        for (int t = 0; t < 4; t++) {
            uint32_t pa_h[4], pa_l[4];
            cvt2(sf[2 * t][0],     sf[2 * t][1],     &pa_h[0], &pa_l[0]);
            cvt2(sf[2 * t][2],     sf[2 * t][3],     &pa_h[1], &pa_l[1]);
            cvt2(sf[2 * t + 1][0], sf[2 * t + 1][1], &pa_h[2], &pa_l[2]);
            cvt2(sf[2 * t + 1][2], sf[2 * t + 1][3], &pa_h[3], &pa_l[3]);
#pragma unroll
            for (int p = 0; p < 4; p++) {
                uint32_t off = (uint32_t)((p * 16 + (lane & 7) + ((lane >> 4) << 3)) * FLT
                                          + t * 16 + (((lane >> 3) & 1) << 3)) * 2;
                uint32_t vh[4], vl[4];
                ldsm4(vh, kbase + FVH * 2 + off);
                ldsm4(vl, kbase + FVL * 2 + off);
                mma16816(o[2 * p],     pa_h, vh);
                mma16816(o[2 * p],     pa_h, vl);
                mma16816(o[2 * p],     pa_l, vh);
                mma16816(o[2 * p + 1], pa_h, vh + 2);
                mma16816(o[2 * p + 1], pa_h, vl + 2);
                mma16816(o[2 * p + 1], pa_l, vh + 2);
            }
        }
    }

    {
        int r0 = q0 + wid * 16 + g;
#pragma unroll
        for (int r = 0; r < 2; r++) {
            float invl = 1.f / l[r];
            int row = r0 + r * 8;
#pragma unroll
            for (int j = 0; j < 8; j++) {
                float v0 = o[j][2 * r] * invl;
                float v1 = o[j][2 * r + 1] * invl;
                uint32_t ph, pl;
                cvt2(v0, v1, &ph, &pl);
                size_t off = hb + (size_t)row * HDIM + j * 8 + 2 * q;
                *(uint32_t*)(Oh + off) = ph;
                *(uint32_t*)(Ol + off) = pl;
            }
        }
    }
}

// ===========================================================================
extern "C" void kernel_launch(void* const* d_in, const int* in_sizes, int n_in,
                              void* d_out, int out_size)
{
    const float* X   = (const float*)d_in[0];
    const float* Wq  = (const float*)d_in[1];
    const float* bq  = (const float*)d_in[2];
    const float* Wk  = (const float*)d_in[3];
    const float* bk  = (const float*)d_in[4];
    const float* Wv  = (const float*)d_in[5];
    const float* bv  = (const float*)d_in[6];
    const float* Wo  = (const float*)d_in[7];
    const float* bo  = (const float*)d_in[8];
    const float* qta = (const float*)d_in[9];
    const float* qtb = (const float*)d_in[10];
    const float* kta = (const float*)d_in[11];
    const float* ktb = (const float*)d_in[12];
    const float* cpl = (const float*)d_in[13];

    bf16* bf = nullptr;
    cudaGetSymbolAddress((void**)&bf, g_bf);

    const int GSL = NSTG * SL_ELEMS * 2;    // 46080 B
    const int GSU = NSTG * SU_ELEMS * 2;    // 61440 B
    const int GS2 = NSTG * ST2_ELEMS * 2;   // 122880 B
    const int FS  = 2 * FSTAGE * 2;         // 73728 B
    cudaFuncSetAttribute(gemm_low1,   cudaFuncAttributeMaxDynamicSharedMemorySize, GSL);
    cudaFuncSetAttribute(torsion_upd, cudaFuncAttributeMaxDynamicSharedMemorySize, GSU);
    cudaFuncSetAttribute(gemm_bf2,    cudaFuncAttributeMaxDynamicSharedMemorySize, GS2);
    cudaFuncSetAttribute(flash_bf,    cudaFuncAttributeMaxDynamicSharedMemorySize, FS);

    // ---- pre-convert (4 launches)
    split_f32<<<4096, 256>>>(X, bf + O_XH, bf + O_XL, 1048576);
    transpose_split4<<<dim3(32, 32, 4), 256>>>(Wq, Wk, Wv, Wo,
        bf + O_WT, bf + O_WT + 1048576u, 1024, 1024, 2097152);
    transpose_split4<<<dim3(2, 32, 4), 256>>>(qta, qta + 65536, kta, kta + 65536,
        bf + O_TA, bf + O_TA + 65536u, 1024, 64, 131072);
    transpose_split4<<<dim3(32, 2, 4), 256>>>(qtb, qtb + 65536, ktb, ktb + 65536,
        bf + O_TB, bf + O_TB + 65536u, 64, 1024, 131072);

    // ---- QKV fused (planes only, mode 5)
    gemm_bf2<<<dim3(8, 32, 3), 512, GS2>>>(
        bf + O_XH, bf + O_XL, 0,
        bf + O_WT, bf + O_WT + 1048576u, 2097152,
        bq, bk, bv,
        nullptr,
        bf + O_QBH, bf + O_QBH + 4194304u, 8388608,
        1024, 1024, 5);

    // ---- V transpose for flash cp.async
    vt_transpose<<<dim3(2, 64, 32), 256>>>(bf + O_QBH + 16777216u, bf + O_QBH + 20971520u,
                                           bf + O_VTH, bf + O_VTL);

    // ---- all 4 torsion low-rank GEMMs, single-term
    gemm_low1<<<dim3(1, 32, 4), 256, GSL>>>(bf + O_QBH, bf + O_TA, bf + O_LB);

    // ---- fused torsion update (n=0 + n=1, Q and K in one launch)
    torsion_upd<<<dim3(8, 32, 2), 512, GSU>>>(bf + O_LB, bf + O_TB, bf + O_QBH, cpl);

    // ---- flash attention (cp.async, occ 2)
    dim3 gAtt(SEQ / 128, NHEAD, BATCH);
    flash_bf<<<gAtt, 256, FS>>>(bf + O_QBH, bf + O_QBH + 4194304u,
                                bf + O_QBH + 8388608u, bf + O_QBH + 12582912u,
                                bf + O_VTH, bf + O_VTL,
                                bf + O_AOH, bf + O_AOL);

    // ---- output projection -> d_out (mode 0)
    gemm_bf2<<<dim3(8, 32, 1), 512, GS2>>>(
        bf + O_AOH, bf + O_AOL, 0,
        bf + O_WT + 6291456u, bf + O_WT + 7340032u, 0,
        bo, bo, bo,
        (float*)d_out,
        bf + O_AOH, bf + O_AOH, 0,
        1024, 1024, 0);
}